// round 3
// baseline (speedup 1.0000x reference)
#include <cuda_runtime.h>
#include <math.h>

#define BATCH   8
#define SEQ     4000
#define DIM     256
#define BCH     5
#define NCHUNK  800   // SEQ / BCH
#define CG      16    // chunks per group
#define NG      50    // NCHUNK / CG
#define TOKG    (CG*BCH)  // 80 tokens per group

// log2(0.9865), double-precision derived
#define GLOG2 (-0.0196090426f)

__device__ __forceinline__ float gpow(float k) { return exp2f(k * GLOG2); }

// scratch (static device arrays; no allocation)
__device__ float g_Q[BATCH * SEQ * DIM];
__device__ float g_K[BATCH * SEQ * DIM];
__device__ float g_V[BATCH * SEQ * DIM];
__device__ float g_S[(size_t)BATCH * NG * DIM * DIM];
__device__ float g_P[(size_t)BATCH * NG * DIM * DIM];

// ---------------------------------------------------------------------------
// K1: QKV projections. C[M,256] = A[M,256] @ W[256,256], M = BATCH*SEQ = 32000
// 128x128 block tile, BK=8, 256 threads, 8x8 per thread.
// grid = (2, 250, 3)   z selects Q/K/V
// ---------------------------------------------------------------------------
__global__ __launch_bounds__(256) void proj_kernel(
    const float* __restrict__ xq, const float* __restrict__ xk, const float* __restrict__ xv,
    const float* __restrict__ Wq, const float* __restrict__ Wk, const float* __restrict__ Wv)
{
    const int which = blockIdx.z;
    const float* A = (which == 0) ? xq : (which == 1) ? xk : xv;
    const float* B = (which == 0) ? Wq : (which == 1) ? Wk : Wv;
    float* C = (which == 0) ? g_Q : (which == 1) ? g_K : g_V;

    const int N = 256, K = 256;
    __shared__ float As[8][128];   // As[k][m]
    __shared__ float Bs[8][128];   // Bs[k][n]

    int tid = threadIdx.x;
    int tx = tid & 15, ty = tid >> 4;
    int row0 = blockIdx.y * 128;
    int col0 = blockIdx.x * 128;

    int arow = tid >> 1;          // 0..127
    int acol = (tid & 1) * 4;     // 0 or 4
    int brow = tid >> 5;          // 0..7
    int bcol = (tid & 31) * 4;    // 0..124

    const float* Aptr = A + (size_t)(row0 + arow) * K + acol;
    const float* Bptr = B + (size_t)brow * N + col0 + bcol;

    float acc[8][8];
#pragma unroll
    for (int i = 0; i < 8; i++)
#pragma unroll
        for (int j = 0; j < 8; j++) acc[i][j] = 0.f;

    for (int k0 = 0; k0 < K; k0 += 8) {
        float4 av = *(const float4*)(Aptr + k0);
        float4 bv = *(const float4*)(Bptr + (size_t)k0 * N);
        As[acol + 0][arow] = av.x;
        As[acol + 1][arow] = av.y;
        As[acol + 2][arow] = av.z;
        As[acol + 3][arow] = av.w;
        *(float4*)&Bs[brow][bcol] = bv;
        __syncthreads();
#pragma unroll
        for (int kk = 0; kk < 8; kk++) {
            float a[8], b[8];
            *(float4*)&a[0] = *(const float4*)&As[kk][ty * 4];
            *(float4*)&a[4] = *(const float4*)&As[kk][64 + ty * 4];
            *(float4*)&b[0] = *(const float4*)&Bs[kk][tx * 4];
            *(float4*)&b[4] = *(const float4*)&Bs[kk][64 + tx * 4];
#pragma unroll
            for (int i = 0; i < 8; i++)
#pragma unroll
                for (int j = 0; j < 8; j++) acc[i][j] += a[i] * b[j];
        }
        __syncthreads();
    }

#pragma unroll
    for (int ih = 0; ih < 2; ih++)
#pragma unroll
        for (int i = 0; i < 4; i++) {
            int r = row0 + ih * 64 + ty * 4 + i;
            float* Crow = C + (size_t)r * N + col0;
            int ai = ih * 4 + i;
            *(float4*)(Crow + tx * 4)      = make_float4(acc[ai][0], acc[ai][1], acc[ai][2], acc[ai][3]);
            *(float4*)(Crow + 64 + tx * 4) = make_float4(acc[ai][4], acc[ai][5], acc[ai][6], acc[ai][7]);
        }
}

// ---------------------------------------------------------------------------
// K2: group states. S_g[d][e] = sum_{t in group} w_t * K[t][d] * V[t][e],
// w_t = gamma^{6*(CG-1 - chunkInGroup(t))}.
// grid = (2, 2, BATCH*NG), 256 threads, 128x128 tile, BK=8 over 80 tokens.
// ---------------------------------------------------------------------------
__global__ __launch_bounds__(256) void groupstate_kernel()
{
    int bz = blockIdx.z;             // b*NG + g
    int b = bz / NG, g = bz % NG;
    int d0 = blockIdx.y * 128;
    int e0 = blockIdx.x * 128;

    const float* Kbase = g_K + (size_t)(b * SEQ + g * TOKG) * DIM;
    const float* Vbase = g_V + (size_t)(b * SEQ + g * TOKG) * DIM;

    __shared__ float As[8][128];   // [t][d]  (weighted K)
    __shared__ float Bs[8][128];   // [t][e]  (V)

    int tid = threadIdx.x;
    int tx = tid & 15, ty = tid >> 4;
    int trow = tid >> 5;           // token in 8-slab
    int tcol = (tid & 31) * 4;

    float acc[8][8];
#pragma unroll
    for (int i = 0; i < 8; i++)
#pragma unroll
        for (int j = 0; j < 8; j++) acc[i][j] = 0.f;

    for (int k0 = 0; k0 < TOKG; k0 += 8) {
        int t = k0 + trow;
        float w = gpow((float)(6 * (CG - 1 - t / BCH)));
        float4 kv = *(const float4*)(Kbase + (size_t)t * DIM + d0 + tcol);
        float4 vv = *(const float4*)(Vbase + (size_t)t * DIM + e0 + tcol);
        kv.x *= w; kv.y *= w; kv.z *= w; kv.w *= w;
        *(float4*)&As[trow][tcol] = kv;
        *(float4*)&Bs[trow][tcol] = vv;
        __syncthreads();
#pragma unroll
        for (int kk = 0; kk < 8; kk++) {
            float a[8], bb[8];
            *(float4*)&a[0]  = *(const float4*)&As[kk][ty * 4];
            *(float4*)&a[4]  = *(const float4*)&As[kk][64 + ty * 4];
            *(float4*)&bb[0] = *(const float4*)&Bs[kk][tx * 4];
            *(float4*)&bb[4] = *(const float4*)&Bs[kk][64 + tx * 4];
#pragma unroll
            for (int i = 0; i < 8; i++)
#pragma unroll
                for (int j = 0; j < 8; j++) acc[i][j] += a[i] * bb[j];
        }
        __syncthreads();
    }

#pragma unroll
    for (int ih = 0; ih < 2; ih++)
#pragma unroll
        for (int i = 0; i < 4; i++) {
            int dr = d0 + ih * 64 + ty * 4 + i;
            float* Sp = g_S + ((size_t)bz * DIM + dr) * DIM + e0;
            int ai = ih * 4 + i;
            *(float4*)(Sp + tx * 4)      = make_float4(acc[ai][0], acc[ai][1], acc[ai][2], acc[ai][3]);
            *(float4*)(Sp + 64 + tx * 4) = make_float4(acc[ai][4], acc[ai][5], acc[ai][6], acc[ai][7]);
        }
}

// ---------------------------------------------------------------------------
// K3: exclusive group prefix:  P_0 = 0;  P_g = gamma^6 * S_{g-1} + gamma^{6*CG} * P_{g-1}
// One thread per (b, d, e).
// ---------------------------------------------------------------------------
__global__ __launch_bounds__(256) void prefix_kernel()
{
    int idx = blockIdx.x * blockDim.x + threadIdx.x;
    if (idx >= BATCH * DIM * DIM) return;
    int b = idx / (DIM * DIM);
    int de = idx - b * (DIM * DIM);
    size_t base = (size_t)b * NG * DIM * DIM + de;
    const float g6 = gpow(6.f);
    const float g6C = gpow(6.f * CG);
    float p = 0.f;
    g_P[base] = 0.f;
    for (int g = 1; g < NG; g++) {
        p = g6 * g_S[base + (size_t)(g - 1) * DIM * DIM] + g6C * p;
        g_P[base + (size_t)g * DIM * DIM] = p;
    }
}

// ---------------------------------------------------------------------------
// K5: intra-chunk term + within-group cross. One block per (m, b). Writes out.
// out[m][o] = sum_{p<=o} gamma^{p-o} (Q_m[o].K_m[p]) V_m[p]
//           + [m not last in group] sum_{j=gC..m} gamma^{6(m+1-j)} (Q_{m+1}[o].K_j[p]) V_j[p]
// ---------------------------------------------------------------------------
__global__ __launch_bounds__(256) void local_kernel(float* __restrict__ out)
{
    int m = blockIdx.x, b = blockIdx.y;
    int g = m / CG, gC = g * CG;
    int tid = threadIdx.x;
    int e = tid;
    int w = tid >> 5, lane = tid & 31;

    __shared__ float sQ[5][256];
    __shared__ float sK[5][256];
    __shared__ float sS[5][8];

    float acc[5] = {0.f, 0.f, 0.f, 0.f, 0.f};
    const size_t qkvBase = (size_t)b * SEQ * DIM;
    bool doCross = (m != gC + CG - 1);   // last chunk of group: cross handled fully by K4

    if (doCross) {
        const float* Qp = g_Q + qkvBase + (size_t)(m + 1) * BCH * DIM;
#pragma unroll
        for (int i = 0; i < 5; i++) sQ[i][tid] = Qp[i * DIM + tid];
        __syncthreads();

        for (int j = gC; j <= m; j++) {
            const float* Kp = g_K + qkvBase + (size_t)j * BCH * DIM;
#pragma unroll
            for (int i = 0; i < 5; i++) sK[i][tid] = Kp[i * DIM + tid];
            __syncthreads();

            float wgt = gpow((float)(6 * (m + 1 - j)));
            for (int pr = w; pr < 25; pr += 8) {
                int o = pr / 5, p = pr % 5;
                float s = 0.f;
#pragma unroll
                for (int dd = 0; dd < 8; dd++) s += sQ[o][lane + dd * 32] * sK[p][lane + dd * 32];
#pragma unroll
                for (int off = 16; off; off >>= 1) s += __shfl_xor_sync(0xffffffffu, s, off);
                if (lane == 0) sS[o][p] = s * wgt;
            }
            __syncthreads();

            const float* Vp = g_V + qkvBase + (size_t)j * BCH * DIM;
            float v[5];
#pragma unroll
            for (int p = 0; p < 5; p++) v[p] = Vp[p * DIM + e];
#pragma unroll
            for (int o = 0; o < 5; o++) {
                float t = acc[o];
#pragma unroll
                for (int p = 0; p < 5; p++) t += sS[o][p] * v[p];
                acc[o] = t;
            }
            __syncthreads();
        }
    }

    // intra-chunk
    {
        const float* Qp = g_Q + qkvBase + (size_t)m * BCH * DIM;
        const float* Kp = g_K + qkvBase + (size_t)m * BCH * DIM;
#pragma unroll
        for (int i = 0; i < 5; i++) { sQ[i][tid] = Qp[i * DIM + tid]; sK[i][tid] = Kp[i * DIM + tid]; }
        __syncthreads();

        for (int pr = w; pr < 25; pr += 8) {
            int o = pr / 5, p = pr % 5;
            float s = 0.f;
#pragma unroll
            for (int dd = 0; dd < 8; dd++) s += sQ[o][lane + dd * 32] * sK[p][lane + dd * 32];
#pragma unroll
            for (int off = 16; off; off >>= 1) s += __shfl_xor_sync(0xffffffffu, s, off);
            if (lane == 0) sS[o][p] = (p <= o) ? s * gpow((float)(p - o)) : 0.f;
        }
        __syncthreads();

        const float* Vp = g_V + qkvBase + (size_t)m * BCH * DIM;
        float v[5];
#pragma unroll
        for (int p = 0; p < 5; p++) v[p] = Vp[p * DIM + e];
#pragma unroll
        for (int o = 0; o < 5; o++) {
            float t = acc[o];
#pragma unroll
            for (int p = 0; p < 5; p++) t += sS[o][p] * v[p];
            acc[o] = t;
        }
    }

    float* Op = out + qkvBase + (size_t)m * BCH * DIM;
#pragma unroll
    for (int o = 0; o < 5; o++) Op[o * DIM + e] = acc[o];
}

// ---------------------------------------------------------------------------
// K4: global cross. For each (b,g): Cg[80][256] = Q_group @ P_g, then
// out[token q*5+o-5] += gamma^{6*(q-gC)} * Cg[r][e].   (skip r<5 at g=0)
// grid = (2, BATCH*NG), 256 threads (16x16), thread tile 5x8, BK=16.
// ---------------------------------------------------------------------------
__global__ __launch_bounds__(256) void crossglobal_kernel(float* __restrict__ out)
{
    int bz = blockIdx.y;             // b*NG + g
    int b = bz / NG, g = bz % NG;
    int e0 = blockIdx.x * 128;
    int tid = threadIdx.x;
    int tx = tid & 15, ty = tid >> 4;

    __shared__ float As[16][84];     // [kk][r]   (Q tile transposed)
    __shared__ float Bs[16][128];    // [kk][e]   (P tile)

    const float* Qbase = g_Q + (size_t)(b * SEQ + g * TOKG) * DIM;
    const float* Pbase = g_P + (size_t)bz * DIM * DIM;

    float acc[5][8];
#pragma unroll
    for (int i = 0; i < 5; i++)
#pragma unroll
        for (int j = 0; j < 8; j++) acc[i][j] = 0.f;

    for (int k0 = 0; k0 < DIM; k0 += 16) {
        for (int i = tid; i < 80 * 16; i += 256) {
            int r = i >> 4, kk = i & 15;
            As[kk][r] = Qbase[(size_t)r * DIM + k0 + kk];
        }
#pragma unroll
        for (int pass = 0; pass < 2; pass++) {
            int f = tid + pass * 256;
            int row = f >> 5, c4 = (f & 31) * 4;
            *(float4*)&Bs[row][c4] = *(const float4*)(Pbase + (size_t)(k0 + row) * DIM + e0 + c4);
        }
        __syncthreads();
#pragma unroll
        for (int kk = 0; kk < 16; kk++) {
            float a[5], bq[8];
#pragma unroll
            for (int i = 0; i < 5; i++) a[i] = As[kk][ty * 5 + i];
            *(float4*)&bq[0] = *(const float4*)&Bs[kk][tx * 8];
            *(float4*)&bq[4] = *(const float4*)&Bs[kk][tx * 8 + 4];
#pragma unroll
            for (int i = 0; i < 5; i++)
#pragma unroll
                for (int j = 0; j < 8; j++) acc[i][j] += a[i] * bq[j];
        }
        __syncthreads();
    }

    float scale = gpow((float)(6 * ty));  // gamma^{6*(q - gC)}, q-gC == ty
    int gtok0 = g * TOKG;
#pragma unroll
    for (int i = 0; i < 5; i++) {
        int r = ty * 5 + i;
        int tok = gtok0 + r - 5;
        if (tok < 0) continue;           // only g==0, r<5
        float* Op = out + ((size_t)b * SEQ + tok) * DIM + e0 + tx * 8;
#pragma unroll
        for (int j = 0; j < 8; j++) Op[j] += scale * acc[i][j];
    }
}

// ---------------------------------------------------------------------------
extern "C" void kernel_launch(void* const* d_in, const int* in_sizes, int n_in,
                              void* d_out, int out_size)
{
    const float* xq = (const float*)d_in[0];
    const float* xk = (const float*)d_in[1];
    const float* xv = (const float*)d_in[2];
    const float* Wq = (const float*)d_in[3];
    const float* Wk = (const float*)d_in[4];
    const float* Wv = (const float*)d_in[5];
    float* out = (float*)d_out;

    dim3 blk(256);
    proj_kernel<<<dim3(2, 250, 3), blk>>>(xq, xk, xv, Wq, Wk, Wv);
    groupstate_kernel<<<dim3(2, 2, BATCH * NG), blk>>>();
    prefix_kernel<<<dim3((BATCH * DIM * DIM + 255) / 256), blk>>>();
    local_kernel<<<dim3(NCHUNK, BATCH), blk>>>(out);
    crossglobal_kernel<<<dim3(2, BATCH * NG), blk>>>(out);
}

// round 5
// speedup vs baseline: 1.5918x; 1.5918x over previous
#include <cuda_runtime.h>
#include <cuda_bf16.h>
#include <stdint.h>
#include <math.h>

#define BATCH   8
#define SEQ     4000
#define DIM     256
#define BCH     5
#define NCHUNK  800
#define CG      16
#define NG      50
#define TOKG    (CG*BCH)

#define GLOG2 (-0.0196090426f)
__device__ __forceinline__ float gpow(float k) { return exp2f(k * GLOG2); }

// scratch
__device__ float g_Q[BATCH * SEQ * DIM];
__device__ float g_K[BATCH * SEQ * DIM];
__device__ float g_V[BATCH * SEQ * DIM];
__device__ float g_S[(size_t)BATCH * NG * DIM * DIM];
__device__ float g_P[(size_t)BATCH * NG * DIM * DIM];

// ---------------------------------------------------------------------------
// mma / ldmatrix helpers (bf16 split-precision path)
// ---------------------------------------------------------------------------
__device__ __forceinline__ unsigned su32(const void* p) {
    return (unsigned)__cvta_generic_to_shared(p);
}

__device__ __forceinline__ void ldm4(uint32_t* r, unsigned addr) {
    asm volatile("ldmatrix.sync.aligned.m8n8.x4.shared.b16 {%0,%1,%2,%3}, [%4];"
        : "=r"(r[0]), "=r"(r[1]), "=r"(r[2]), "=r"(r[3]) : "r"(addr));
}
__device__ __forceinline__ void ldm4t(uint32_t* r, unsigned addr) {
    asm volatile("ldmatrix.sync.aligned.m8n8.x4.trans.shared.b16 {%0,%1,%2,%3}, [%4];"
        : "=r"(r[0]), "=r"(r[1]), "=r"(r[2]), "=r"(r[3]) : "r"(addr));
}
__device__ __forceinline__ void mma16816(float* c, const uint32_t* a, const uint32_t* b) {
    asm volatile(
        "mma.sync.aligned.m16n8k16.row.col.f32.bf16.bf16.f32 "
        "{%0,%1,%2,%3},{%4,%5,%6,%7},{%8,%9},{%0,%1,%2,%3};"
        : "+f"(c[0]), "+f"(c[1]), "+f"(c[2]), "+f"(c[3])
        : "r"(a[0]), "r"(a[1]), "r"(a[2]), "r"(a[3]), "r"(b[0]), "r"(b[1]));
}

// split x,y into (hi,lo) bf16x2 packed words; halves ordered [x, y] low->high
__device__ __forceinline__ void split2(float x, float y, uint32_t& h, uint32_t& l) {
    __nv_bfloat162 hb = __floats2bfloat162_rn(x, y);
    float rx = x - __bfloat162float(hb.x);
    float ry = y - __bfloat162float(hb.y);
    __nv_bfloat162 lb = __floats2bfloat162_rn(rx, ry);
    h = *reinterpret_cast<uint32_t*>(&hb);
    l = *reinterpret_cast<uint32_t*>(&lb);
}

// smem pads (in bf16 halves): A-style [m][k] uses 40, B-style [k][n] uses 136
#define KP 40
#define NP 136

// ---------------------------------------------------------------------------
// K1: QKV projections via bf16-split mma. C[M=32000,256] = A @ W.
// block 128x128, BK=32, 8 warps as 2(m) x 4(n), warp tile 64x32.
// grid = (2, 250, 3)
// ---------------------------------------------------------------------------
__global__ __launch_bounds__(256) void proj_mma(
    const float* __restrict__ xq, const float* __restrict__ xk, const float* __restrict__ xv,
    const float* __restrict__ Wq, const float* __restrict__ Wk, const float* __restrict__ Wv)
{
    const int which = blockIdx.z;
    const float* A = (which == 0) ? xq : (which == 1) ? xk : xv;
    const float* B = (which == 0) ? Wq : (which == 1) ? Wk : Wv;
    float* C = (which == 0) ? g_Q : (which == 1) ? g_K : g_V;

    __shared__ uint32_t sAh[128 * (KP / 2)], sAl[128 * (KP / 2)];
    __shared__ uint32_t sBh[32 * (NP / 2)], sBl[32 * (NP / 2)];

    int tid = threadIdx.x, lane = tid & 31, wid = tid >> 5;
    int lr = lane & 7, lg = lane >> 3;
    int warp_m = (wid & 1) * 64, warp_n = (wid >> 1) * 32;
    int row0 = blockIdx.y * 128, col0 = blockIdx.x * 128;

    float acc[4][4][4];
#pragma unroll
    for (int i = 0; i < 4; i++)
#pragma unroll
        for (int j = 0; j < 4; j++)
#pragma unroll
            for (int q = 0; q < 4; q++) acc[i][j][q] = 0.f;

    unsigned aOff = ((unsigned)(warp_m + lr + (lg & 1) * 8) * KP + (lg >> 1) * 8) * 2;
    unsigned aBh = su32(sAh) + aOff, aBl = su32(sAl) + aOff;
    unsigned bOff = ((unsigned)(lr + (lg & 1) * 8) * NP + warp_n + (lg >> 1) * 8) * 2;
    unsigned bBh = su32(sBh) + bOff, bBl = su32(sBl) + bOff;

    for (int k0 = 0; k0 < 256; k0 += 32) {
#pragma unroll
        for (int j = 0; j < 4; j++) {            // A slab 128x32
            int i = tid + j * 256;
            int r = i >> 3, kq = (i & 7) * 4;
            float4 v = *(const float4*)(A + (size_t)(row0 + r) * 256 + k0 + kq);
            uint32_t h0, l0, h1, l1;
            split2(v.x, v.y, h0, l0); split2(v.z, v.w, h1, l1);
            int idx = r * (KP / 2) + (kq >> 1);
            sAh[idx] = h0; sAh[idx + 1] = h1; sAl[idx] = l0; sAl[idx + 1] = l1;
        }
#pragma unroll
        for (int j = 0; j < 4; j++) {            // B slab 32x128
            int i = tid + j * 256;
            int r = i >> 5, nq = (i & 31) * 4;
            float4 v = *(const float4*)(B + (size_t)(k0 + r) * 256 + col0 + nq);
            uint32_t h0, l0, h1, l1;
            split2(v.x, v.y, h0, l0); split2(v.z, v.w, h1, l1);
            int idx = r * (NP / 2) + (nq >> 1);
            sBh[idx] = h0; sBh[idx + 1] = h1; sBl[idx] = l0; sBl[idx + 1] = l1;
        }
        __syncthreads();
#pragma unroll
        for (int ks = 0; ks < 32; ks += 16) {
            uint32_t ah[4][4], al[4][4], bh[2][4], bl[2][4];
#pragma unroll
            for (int mt = 0; mt < 4; mt++) {
                unsigned o = ((unsigned)(mt * 16) * KP + ks) * 2;
                ldm4(ah[mt], aBh + o); ldm4(al[mt], aBl + o);
            }
#pragma unroll
            for (int np = 0; np < 2; np++) {
                unsigned o = ((unsigned)ks * NP + np * 16) * 2;
                ldm4t(bh[np], bBh + o); ldm4t(bl[np], bBl + o);
            }
#pragma unroll
            for (int mt = 0; mt < 4; mt++)
#pragma unroll
                for (int nt = 0; nt < 4; nt++) {
                    const uint32_t* bhp = &bh[nt >> 1][(nt & 1) * 2];
                    const uint32_t* blp = &bl[nt >> 1][(nt & 1) * 2];
                    mma16816(acc[mt][nt], ah[mt], bhp);
                    mma16816(acc[mt][nt], ah[mt], blp);
                    mma16816(acc[mt][nt], al[mt], bhp);
                }
        }
        __syncthreads();
    }

    int g4 = lane >> 2, t4 = (lane & 3) * 2;
#pragma unroll
    for (int mt = 0; mt < 4; mt++)
#pragma unroll
        for (int nt = 0; nt < 4; nt++) {
            int r = row0 + warp_m + mt * 16 + g4;
            int c = col0 + warp_n + nt * 8 + t4;
            *(float2*)&C[(size_t)r * 256 + c] = make_float2(acc[mt][nt][0], acc[mt][nt][1]);
            *(float2*)&C[(size_t)(r + 8) * 256 + c] = make_float2(acc[mt][nt][2], acc[mt][nt][3]);
        }
}

// ---------------------------------------------------------------------------
// K2: group states via mma. S_g = (wK)^T V, K-dim = 80 tokens, BK=16.
// K stored [t][d] -> A frags via ldmatrix.trans. grid (2,2,400).
// ---------------------------------------------------------------------------
__global__ __launch_bounds__(256) void groupstate_mma()
{
    int bz = blockIdx.z;
    int b = bz / NG, g = bz % NG;
    int d0 = blockIdx.y * 128, e0 = blockIdx.x * 128;

    __shared__ uint32_t sKh[16 * (NP / 2)], sKl[16 * (NP / 2)];
    __shared__ uint32_t sVh[16 * (NP / 2)], sVl[16 * (NP / 2)];

    int tid = threadIdx.x, lane = tid & 31, wid = tid >> 5;
    int lr = lane & 7, lg = lane >> 3;
    int warp_m = (wid & 1) * 64, warp_n = (wid >> 1) * 32;

    const float* Kb = g_K + (size_t)(b * SEQ + g * TOKG) * 256;
    const float* Vb = g_V + (size_t)(b * SEQ + g * TOKG) * 256;

    float acc[4][4][4];
#pragma unroll
    for (int i = 0; i < 4; i++)
#pragma unroll
        for (int j = 0; j < 4; j++)
#pragma unroll
            for (int q = 0; q < 4; q++) acc[i][j][q] = 0.f;

    // A via trans: stored [k][m] -> row = lr + (lg>>1)*8, col = m + (lg&1)*8
    unsigned aOff = ((unsigned)(lr + (lg >> 1) * 8) * NP + warp_m + (lg & 1) * 8) * 2;
    unsigned aBh = su32(sKh) + aOff, aBl = su32(sKl) + aOff;
    unsigned bOff = ((unsigned)(lr + (lg & 1) * 8) * NP + warp_n + (lg >> 1) * 8) * 2;
    unsigned bBh = su32(sVh) + bOff, bBl = su32(sVl) + bOff;

    for (int t0 = 0; t0 < TOKG; t0 += 16) {
#pragma unroll
        for (int j = 0; j < 2; j++) {
            int i = tid + j * 256;
            int tr = i >> 5, dq = (i & 31) * 4;
            int tg = t0 + tr;
            float w = gpow((float)(6 * (CG - 1 - tg / BCH)));
            float4 kv = *(const float4*)(Kb + (size_t)tg * 256 + d0 + dq);
            kv.x *= w; kv.y *= w; kv.z *= w; kv.w *= w;
            uint32_t h0, l0, h1, l1;
            split2(kv.x, kv.y, h0, l0); split2(kv.z, kv.w, h1, l1);
            int idx = tr * (NP / 2) + (dq >> 1);
            sKh[idx] = h0; sKh[idx + 1] = h1; sKl[idx] = l0; sKl[idx + 1] = l1;
            float4 vv = *(const float4*)(Vb + (size_t)tg * 256 + e0 + dq);
            split2(vv.x, vv.y, h0, l0); split2(vv.z, vv.w, h1, l1);
            sVh[idx] = h0; sVh[idx + 1] = h1; sVl[idx] = l0; sVl[idx + 1] = l1;
        }
        __syncthreads();
        {
            uint32_t ah[4][4], al[4][4], bh[2][4], bl[2][4];
#pragma unroll
            for (int mt = 0; mt < 4; mt++) {
                unsigned o = (unsigned)(mt * 16) * 2;           // column shift
                ldm4t(ah[mt], aBh + o); ldm4t(al[mt], aBl + o);
            }
#pragma unroll
            for (int np = 0; np < 2; np++) {
                unsigned o = (unsigned)(np * 16) * 2;
                ldm4t(bh[np], bBh + o); ldm4t(bl[np], bBl + o);
            }
#pragma unroll
            for (int mt = 0; mt < 4; mt++)
#pragma unroll
                for (int nt = 0; nt < 4; nt++) {
                    const uint32_t* bhp = &bh[nt >> 1][(nt & 1) * 2];
                    const uint32_t* blp = &bl[nt >> 1][(nt & 1) * 2];
                    mma16816(acc[mt][nt], ah[mt], bhp);
                    mma16816(acc[mt][nt], ah[mt], blp);
                    mma16816(acc[mt][nt], al[mt], bhp);
                }
        }
        __syncthreads();
    }

    int g4 = lane >> 2, t4 = (lane & 3) * 2;
    float* S = g_S + (size_t)bz * DIM * DIM;
#pragma unroll
    for (int mt = 0; mt < 4; mt++)
#pragma unroll
        for (int nt = 0; nt < 4; nt++) {
            int r = d0 + warp_m + mt * 16 + g4;
            int c = e0 + warp_n + nt * 8 + t4;
            *(float2*)&S[(size_t)r * 256 + c] = make_float2(acc[mt][nt][0], acc[mt][nt][1]);
            *(float2*)&S[(size_t)(r + 8) * 256 + c] = make_float2(acc[mt][nt][2], acc[mt][nt][3]);
        }
}

// ---------------------------------------------------------------------------
// K3: exclusive group prefix (unchanged)
// ---------------------------------------------------------------------------
__global__ __launch_bounds__(256) void prefix_kernel()
{
    int idx = blockIdx.x * blockDim.x + threadIdx.x;
    if (idx >= BATCH * DIM * DIM) return;
    int b = idx / (DIM * DIM);
    int de = idx - b * (DIM * DIM);
    size_t base = (size_t)b * NG * DIM * DIM + de;
    const float g6 = gpow(6.f);
    const float g6C = gpow(6.f * CG);
    float p = 0.f;
    g_P[base] = 0.f;
    for (int g = 1; g < NG; g++) {
        p = g6 * g_S[base + (size_t)(g - 1) * DIM * DIM] + g6C * p;
        g_P[base + (size_t)g * DIM * DIM] = p;
    }
}

// ---------------------------------------------------------------------------
// K5: intra-chunk + within-group cross (unchanged)
// ---------------------------------------------------------------------------
__global__ __launch_bounds__(256) void local_kernel(float* __restrict__ out)
{
    int m = blockIdx.x, b = blockIdx.y;
    int g = m / CG, gC = g * CG;
    int tid = threadIdx.x;
    int e = tid;
    int w = tid >> 5, lane = tid & 31;

    __shared__ float sQ[5][256];
    __shared__ float sK[5][256];
    __shared__ float sS[5][8];

    float acc[5] = {0.f, 0.f, 0.f, 0.f, 0.f};
    const size_t qkvBase = (size_t)b * SEQ * DIM;
    bool doCross = (m != gC + CG - 1);

    if (doCross) {
        const float* Qp = g_Q + qkvBase + (size_t)(m + 1) * BCH * DIM;
#pragma unroll
        for (int i = 0; i < 5; i++) sQ[i][tid] = Qp[i * DIM + tid];
        __syncthreads();

        for (int j = gC; j <= m; j++) {
            const float* Kp = g_K + qkvBase + (size_t)j * BCH * DIM;
#pragma unroll
            for (int i = 0; i < 5; i++) sK[i][tid] = Kp[i * DIM + tid];
            __syncthreads();

            float wgt = gpow((float)(6 * (m + 1 - j)));
            for (int pr = w; pr < 25; pr += 8) {
                int o = pr / 5, p = pr % 5;
                float s = 0.f;
#pragma unroll
                for (int dd = 0; dd < 8; dd++) s += sQ[o][lane + dd * 32] * sK[p][lane + dd * 32];
#pragma unroll
                for (int off = 16; off; off >>= 1) s += __shfl_xor_sync(0xffffffffu, s, off);
                if (lane == 0) sS[o][p] = s * wgt;
            }
            __syncthreads();

            const float* Vp = g_V + qkvBase + (size_t)j * BCH * DIM;
            float v[5];
#pragma unroll
            for (int p = 0; p < 5; p++) v[p] = Vp[p * DIM + e];
#pragma unroll
            for (int o = 0; o < 5; o++) {
                float t = acc[o];
#pragma unroll
                for (int p = 0; p < 5; p++) t += sS[o][p] * v[p];
                acc[o] = t;
            }
            __syncthreads();
        }
    }

    {
        const float* Qp = g_Q + qkvBase + (size_t)m * BCH * DIM;
        const float* Kp = g_K + qkvBase + (size_t)m * BCH * DIM;
#pragma unroll
        for (int i = 0; i < 5; i++) { sQ[i][tid] = Qp[i * DIM + tid]; sK[i][tid] = Kp[i * DIM + tid]; }
        __syncthreads();

        for (int pr = w; pr < 25; pr += 8) {
            int o = pr / 5, p = pr % 5;
            float s = 0.f;
#pragma unroll
            for (int dd = 0; dd < 8; dd++) s += sQ[o][lane + dd * 32] * sK[p][lane + dd * 32];
#pragma unroll
            for (int off = 16; off; off >>= 1) s += __shfl_xor_sync(0xffffffffu, s, off);
            if (lane == 0) sS[o][p] = (p <= o) ? s * gpow((float)(p - o)) : 0.f;
        }
        __syncthreads();

        const float* Vp = g_V + qkvBase + (size_t)m * BCH * DIM;
        float v[5];
#pragma unroll
        for (int p = 0; p < 5; p++) v[p] = Vp[p * DIM + e];
#pragma unroll
        for (int o = 0; o < 5; o++) {
            float t = acc[o];
#pragma unroll
            for (int p = 0; p < 5; p++) t += sS[o][p] * v[p];
            acc[o] = t;
        }
    }

    float* Op = out + qkvBase + (size_t)m * BCH * DIM;
#pragma unroll
    for (int o = 0; o < 5; o++) Op[o * DIM + e] = acc[o];
}

// ---------------------------------------------------------------------------
// K4: global cross via mma. C[80,128] = Q_group @ P_g, scaled += into out.
// 8 warps as 1(m) x 8(n): warp tile 80x16 (5 m-tiles, 2 n-tiles). BK=32.
// grid (2, 400)
// ---------------------------------------------------------------------------
__global__ __launch_bounds__(256) void crossglobal_mma(float* __restrict__ out)
{
    int bz = blockIdx.y;
    int b = bz / NG, g = bz % NG;
    int e0 = blockIdx.x * 128;

    __shared__ uint32_t sQh[80 * (KP / 2)], sQl[80 * (KP / 2)];
    __shared__ uint32_t sPh[32 * (NP / 2)], sPl[32 * (NP / 2)];

    int tid = threadIdx.x, lane = tid & 31, wid = tid >> 5;
    int lr = lane & 7, lg = lane >> 3;
    int warp_n = wid * 16;

    const float* Qb = g_Q + (size_t)(b * SEQ + g * TOKG) * 256;
    const float* Pb = g_P + (size_t)bz * DIM * DIM;

    float acc[5][2][4];
#pragma unroll
    for (int i = 0; i < 5; i++)
#pragma unroll
        for (int j = 0; j < 2; j++)
#pragma unroll
            for (int q = 0; q < 4; q++) acc[i][j][q] = 0.f;

    unsigned aOff = ((unsigned)(lr + (lg & 1) * 8) * KP + (lg >> 1) * 8) * 2;
    unsigned aBh = su32(sQh) + aOff, aBl = su32(sQl) + aOff;
    unsigned bOff = ((unsigned)(lr + (lg & 1) * 8) * NP + warp_n + (lg >> 1) * 8) * 2;
    unsigned bBh = su32(sPh) + bOff, bBl = su32(sPl) + bOff;

    for (int k0 = 0; k0 < 256; k0 += 32) {
#pragma unroll
        for (int j = 0; j < 3; j++) {            // Q slab 80x32 = 640 float4
            int i = tid + j * 256;
            if (i < 640) {
                int r = i >> 3, kq = (i & 7) * 4;
                float4 v = *(const float4*)(Qb + (size_t)r * 256 + k0 + kq);
                uint32_t h0, l0, h1, l1;
                split2(v.x, v.y, h0, l0); split2(v.z, v.w, h1, l1);
                int idx = r * (KP / 2) + (kq >> 1);
                sQh[idx] = h0; sQh[idx + 1] = h1; sQl[idx] = l0; sQl[idx + 1] = l1;
            }
        }
#pragma unroll
        for (int j = 0; j < 4; j++) {            // P slab 32x128
            int i = tid + j * 256;
            int r = i >> 5, nq = (i & 31) * 4;
            float4 v = *(const float4*)(Pb + (size_t)(k0 + r) * 256 + e0 + nq);
            uint32_t h0, l0, h1, l1;
            split2(v.x, v.y, h0, l0); split2(v.z, v.w, h1, l1);
            int idx = r * (NP / 2) + (nq >> 1);
            sPh[idx] = h0; sPh[idx + 1] = h1; sPl[idx] = l0; sPl[idx + 1] = l1;
        }
        __syncthreads();
#pragma unroll
        for (int ks = 0; ks < 32; ks += 16) {
            uint32_t ah[5][4], al[5][4], bh[4], bl[4];
#pragma unroll
            for (int mt = 0; mt < 5; mt++) {
                unsigned o = ((unsigned)(mt * 16) * KP + ks) * 2;
                ldm4(ah[mt], aBh + o); ldm4(al[mt], aBl + o);
            }
            {
                unsigned o = ((unsigned)ks * NP) * 2;
                ldm4t(bh, bBh + o); ldm4t(bl, bBl + o);
            }
#pragma unroll
            for (int mt = 0; mt < 5; mt++)
#pragma unroll
                for (int nt = 0; nt < 2; nt++) {
                    const uint32_t* bhp = &bh[nt * 2];
                    const uint32_t* blp = &bl[nt * 2];
                    mma16816(acc[mt][nt], ah[mt], bhp);
                    mma16816(acc[mt][nt], ah[mt], blp);
                    mma16816(acc[mt][nt], al[mt], bhp);
                }
        }
        __syncthreads();
    }

    int g4 = lane >> 2, t4 = (lane & 3) * 2;
#pragma unroll
    for (int mt = 0; mt < 5; mt++)
#pragma unroll
        for (int nt = 0; nt < 2; nt++) {
            int c = e0 + warp_n + nt * 8 + t4;
            int r1 = mt * 16 + g4;
            int tok1 = g * TOKG + r1 - 5;
            if (tok1 >= 0) {
                float s = gpow((float)(6 * (r1 / 5)));
                float2* p = (float2*)&out[((size_t)b * SEQ + tok1) * 256 + c];
                float2 o = *p;
                o.x += s * acc[mt][nt][0]; o.y += s * acc[mt][nt][1];
                *p = o;
            }
            int r2 = r1 + 8;
            int tok2 = g * TOKG + r2 - 5;
            if (tok2 >= 0) {
                float s = gpow((float)(6 * (r2 / 5)));
                float2* p = (float2*)&out[((size_t)b * SEQ + tok2) * 256 + c];
                float2 o = *p;
                o.x += s * acc[mt][nt][2]; o.y += s * acc[mt][nt][3];
                *p = o;
            }
        }
}

// ---------------------------------------------------------------------------
extern "C" void kernel_launch(void* const* d_in, const int* in_sizes, int n_in,
                              void* d_out, int out_size)
{
    const float* xq = (const float*)d_in[0];
    const float* xk = (const float*)d_in[1];
    const float* xv = (const float*)d_in[2];
    const float* Wq = (const float*)d_in[3];
    const float* Wk = (const float*)d_in[4];
    const float* Wv = (const float*)d_in[5];
    float* out = (float*)d_out;

    dim3 blk(256);
    proj_mma<<<dim3(2, 250, 3), blk>>>(xq, xk, xv, Wq, Wk, Wv);
    groupstate_mma<<<dim3(2, 2, BATCH * NG), blk>>>();
    prefix_kernel<<<dim3((BATCH * DIM * DIM + 255) / 256), blk>>>();
    local_kernel<<<dim3(NCHUNK, BATCH), blk>>>(out);
    crossglobal_mma<<<dim3(2, BATCH * NG), blk>>>(out);
}

// round 6
// speedup vs baseline: 2.0665x; 1.2982x over previous
#include <cuda_runtime.h>
#include <cuda_bf16.h>
#include <stdint.h>
#include <math.h>

#define BATCH   8
#define SEQ     4000
#define DIM     256
#define BCH     5
#define NCHUNK  800
#define CG      16
#define NG      50
#define TOKG    (CG*BCH)

#define GLOG2 (-0.0196090426f)
__device__ __forceinline__ float gpow(float k) { return exp2f(k * GLOG2); }

// scratch
__device__ float g_Q[BATCH * SEQ * DIM];
__device__ float g_K[BATCH * SEQ * DIM];
__device__ float g_V[BATCH * SEQ * DIM];
__device__ float g_S[(size_t)BATCH * NG * DIM * DIM];
__device__ float g_P[(size_t)BATCH * NG * DIM * DIM];

// ---------------------------------------------------------------------------
// mma / ldmatrix helpers (bf16 split-precision path)
// ---------------------------------------------------------------------------
__device__ __forceinline__ unsigned su32(const void* p) {
    return (unsigned)__cvta_generic_to_shared(p);
}

__device__ __forceinline__ void ldm4(uint32_t* r, unsigned addr) {
    asm volatile("ldmatrix.sync.aligned.m8n8.x4.shared.b16 {%0,%1,%2,%3}, [%4];"
        : "=r"(r[0]), "=r"(r[1]), "=r"(r[2]), "=r"(r[3]) : "r"(addr));
}
__device__ __forceinline__ void ldm4t(uint32_t* r, unsigned addr) {
    asm volatile("ldmatrix.sync.aligned.m8n8.x4.trans.shared.b16 {%0,%1,%2,%3}, [%4];"
        : "=r"(r[0]), "=r"(r[1]), "=r"(r[2]), "=r"(r[3]) : "r"(addr));
}
__device__ __forceinline__ void mma16816(float* c, const uint32_t* a, const uint32_t* b) {
    asm volatile(
        "mma.sync.aligned.m16n8k16.row.col.f32.bf16.bf16.f32 "
        "{%0,%1,%2,%3},{%4,%5,%6,%7},{%8,%9},{%0,%1,%2,%3};"
        : "+f"(c[0]), "+f"(c[1]), "+f"(c[2]), "+f"(c[3])
        : "r"(a[0]), "r"(a[1]), "r"(a[2]), "r"(a[3]), "r"(b[0]), "r"(b[1]));
}

__device__ __forceinline__ void split2(float x, float y, uint32_t& h, uint32_t& l) {
    __nv_bfloat162 hb = __floats2bfloat162_rn(x, y);
    float rx = x - __bfloat162float(hb.x);
    float ry = y - __bfloat162float(hb.y);
    __nv_bfloat162 lb = __floats2bfloat162_rn(rx, ry);
    h = *reinterpret_cast<uint32_t*>(&hb);
    l = *reinterpret_cast<uint32_t*>(&lb);
}

#define KP 40
#define NP 136

// ---------------------------------------------------------------------------
// K1: QKV projections via bf16-split mma. grid = (2, 250, 3)
// ---------------------------------------------------------------------------
__global__ __launch_bounds__(256) void proj_mma(
    const float* __restrict__ xq, const float* __restrict__ xk, const float* __restrict__ xv,
    const float* __restrict__ Wq, const float* __restrict__ Wk, const float* __restrict__ Wv)
{
    const int which = blockIdx.z;
    const float* A = (which == 0) ? xq : (which == 1) ? xk : xv;
    const float* B = (which == 0) ? Wq : (which == 1) ? Wk : Wv;
    float* C = (which == 0) ? g_Q : (which == 1) ? g_K : g_V;

    __shared__ uint32_t sAh[128 * (KP / 2)], sAl[128 * (KP / 2)];
    __shared__ uint32_t sBh[32 * (NP / 2)], sBl[32 * (NP / 2)];

    int tid = threadIdx.x, lane = tid & 31, wid = tid >> 5;
    int lr = lane & 7, lg = lane >> 3;
    int warp_m = (wid & 1) * 64, warp_n = (wid >> 1) * 32;
    int row0 = blockIdx.y * 128, col0 = blockIdx.x * 128;

    float acc[4][4][4];
#pragma unroll
    for (int i = 0; i < 4; i++)
#pragma unroll
        for (int j = 0; j < 4; j++)
#pragma unroll
            for (int q = 0; q < 4; q++) acc[i][j][q] = 0.f;

    unsigned aOff = ((unsigned)(warp_m + lr + (lg & 1) * 8) * KP + (lg >> 1) * 8) * 2;
    unsigned aBh = su32(sAh) + aOff, aBl = su32(sAl) + aOff;
    unsigned bOff = ((unsigned)(lr + (lg & 1) * 8) * NP + warp_n + (lg >> 1) * 8) * 2;
    unsigned bBh = su32(sBh) + bOff, bBl = su32(sBl) + bOff;

    for (int k0 = 0; k0 < 256; k0 += 32) {
#pragma unroll
        for (int j = 0; j < 4; j++) {
            int i = tid + j * 256;
            int r = i >> 3, kq = (i & 7) * 4;
            float4 v = *(const float4*)(A + (size_t)(row0 + r) * 256 + k0 + kq);
            uint32_t h0, l0, h1, l1;
            split2(v.x, v.y, h0, l0); split2(v.z, v.w, h1, l1);
            int idx = r * (KP / 2) + (kq >> 1);
            sAh[idx] = h0; sAh[idx + 1] = h1; sAl[idx] = l0; sAl[idx + 1] = l1;
        }
#pragma unroll
        for (int j = 0; j < 4; j++) {
            int i = tid + j * 256;
            int r = i >> 5, nq = (i & 31) * 4;
            float4 v = *(const float4*)(B + (size_t)(k0 + r) * 256 + col0 + nq);
            uint32_t h0, l0, h1, l1;
            split2(v.x, v.y, h0, l0); split2(v.z, v.w, h1, l1);
            int idx = r * (NP / 2) + (nq >> 1);
            sBh[idx] = h0; sBh[idx + 1] = h1; sBl[idx] = l0; sBl[idx + 1] = l1;
        }
        __syncthreads();
#pragma unroll
        for (int ks = 0; ks < 32; ks += 16) {
            uint32_t ah[4][4], al[4][4], bh[2][4], bl[2][4];
#pragma unroll
            for (int mt = 0; mt < 4; mt++) {
                unsigned o = ((unsigned)(mt * 16) * KP + ks) * 2;
                ldm4(ah[mt], aBh + o); ldm4(al[mt], aBl + o);
            }
#pragma unroll
            for (int np = 0; np < 2; np++) {
                unsigned o = ((unsigned)ks * NP + np * 16) * 2;
                ldm4t(bh[np], bBh + o); ldm4t(bl[np], bBl + o);
            }
#pragma unroll
            for (int mt = 0; mt < 4; mt++)
#pragma unroll
                for (int nt = 0; nt < 4; nt++) {
                    const uint32_t* bhp = &bh[nt >> 1][(nt & 1) * 2];
                    const uint32_t* blp = &bl[nt >> 1][(nt & 1) * 2];
                    mma16816(acc[mt][nt], ah[mt], bhp);
                    mma16816(acc[mt][nt], ah[mt], blp);
                    mma16816(acc[mt][nt], al[mt], bhp);
                }
        }
        __syncthreads();
    }

    int g4 = lane >> 2, t4 = (lane & 3) * 2;
#pragma unroll
    for (int mt = 0; mt < 4; mt++)
#pragma unroll
        for (int nt = 0; nt < 4; nt++) {
            int r = row0 + warp_m + mt * 16 + g4;
            int c = col0 + warp_n + nt * 8 + t4;
            *(float2*)&C[(size_t)r * 256 + c] = make_float2(acc[mt][nt][0], acc[mt][nt][1]);
            *(float2*)&C[(size_t)(r + 8) * 256 + c] = make_float2(acc[mt][nt][2], acc[mt][nt][3]);
        }
}

// ---------------------------------------------------------------------------
// K2: group states via mma. grid (2,2,400).
// ---------------------------------------------------------------------------
__global__ __launch_bounds__(256) void groupstate_mma()
{
    int bz = blockIdx.z;
    int b = bz / NG, g = bz % NG;
    int d0 = blockIdx.y * 128, e0 = blockIdx.x * 128;

    __shared__ uint32_t sKh[16 * (NP / 2)], sKl[16 * (NP / 2)];
    __shared__ uint32_t sVh[16 * (NP / 2)], sVl[16 * (NP / 2)];

    int tid = threadIdx.x, lane = tid & 31, wid = tid >> 5;
    int lr = lane & 7, lg = lane >> 3;
    int warp_m = (wid & 1) * 64, warp_n = (wid >> 1) * 32;

    const float* Kb = g_K + (size_t)(b * SEQ + g * TOKG) * 256;
    const float* Vb = g_V + (size_t)(b * SEQ + g * TOKG) * 256;

    float acc[4][4][4];
#pragma unroll
    for (int i = 0; i < 4; i++)
#pragma unroll
        for (int j = 0; j < 4; j++)
#pragma unroll
            for (int q = 0; q < 4; q++) acc[i][j][q] = 0.f;

    unsigned aOff = ((unsigned)(lr + (lg >> 1) * 8) * NP + warp_m + (lg & 1) * 8) * 2;
    unsigned aBh = su32(sKh) + aOff, aBl = su32(sKl) + aOff;
    unsigned bOff = ((unsigned)(lr + (lg & 1) * 8) * NP + warp_n + (lg >> 1) * 8) * 2;
    unsigned bBh = su32(sVh) + bOff, bBl = su32(sVl) + bOff;

    for (int t0 = 0; t0 < TOKG; t0 += 16) {
#pragma unroll
        for (int j = 0; j < 2; j++) {
            int i = tid + j * 256;
            int tr = i >> 5, dq = (i & 31) * 4;
            int tg = t0 + tr;
            float w = gpow((float)(6 * (CG - 1 - tg / BCH)));
            float4 kv = *(const float4*)(Kb + (size_t)tg * 256 + d0 + dq);
            kv.x *= w; kv.y *= w; kv.z *= w; kv.w *= w;
            uint32_t h0, l0, h1, l1;
            split2(kv.x, kv.y, h0, l0); split2(kv.z, kv.w, h1, l1);
            int idx = tr * (NP / 2) + (dq >> 1);
            sKh[idx] = h0; sKh[idx + 1] = h1; sKl[idx] = l0; sKl[idx + 1] = l1;
            float4 vv = *(const float4*)(Vb + (size_t)tg * 256 + e0 + dq);
            split2(vv.x, vv.y, h0, l0); split2(vv.z, vv.w, h1, l1);
            sVh[idx] = h0; sVh[idx + 1] = h1; sVl[idx] = l0; sVl[idx + 1] = l1;
        }
        __syncthreads();
        {
            uint32_t ah[4][4], al[4][4], bh[2][4], bl[2][4];
#pragma unroll
            for (int mt = 0; mt < 4; mt++) {
                unsigned o = (unsigned)(mt * 16) * 2;
                ldm4t(ah[mt], aBh + o); ldm4t(al[mt], aBl + o);
            }
#pragma unroll
            for (int np = 0; np < 2; np++) {
                unsigned o = (unsigned)(np * 16) * 2;
                ldm4t(bh[np], bBh + o); ldm4t(bl[np], bBl + o);
            }
#pragma unroll
            for (int mt = 0; mt < 4; mt++)
#pragma unroll
                for (int nt = 0; nt < 4; nt++) {
                    const uint32_t* bhp = &bh[nt >> 1][(nt & 1) * 2];
                    const uint32_t* blp = &bl[nt >> 1][(nt & 1) * 2];
                    mma16816(acc[mt][nt], ah[mt], bhp);
                    mma16816(acc[mt][nt], ah[mt], blp);
                    mma16816(acc[mt][nt], al[mt], bhp);
                }
        }
        __syncthreads();
    }

    int g4 = lane >> 2, t4 = (lane & 3) * 2;
    float* S = g_S + (size_t)bz * DIM * DIM;
#pragma unroll
    for (int mt = 0; mt < 4; mt++)
#pragma unroll
        for (int nt = 0; nt < 4; nt++) {
            int r = d0 + warp_m + mt * 16 + g4;
            int c = e0 + warp_n + nt * 8 + t4;
            *(float2*)&S[(size_t)r * 256 + c] = make_float2(acc[mt][nt][0], acc[mt][nt][1]);
            *(float2*)&S[(size_t)(r + 8) * 256 + c] = make_float2(acc[mt][nt][2], acc[mt][nt][3]);
        }
}

// ---------------------------------------------------------------------------
// K3: exclusive group prefix
// ---------------------------------------------------------------------------
__global__ __launch_bounds__(256) void prefix_kernel()
{
    int idx = blockIdx.x * blockDim.x + threadIdx.x;
    if (idx >= BATCH * DIM * DIM) return;
    int b = idx / (DIM * DIM);
    int de = idx - b * (DIM * DIM);
    size_t base = (size_t)b * NG * DIM * DIM + de;
    const float g6 = gpow(6.f);
    const float g6C = gpow(6.f * CG);
    float p = 0.f;
    g_P[base] = 0.f;
    for (int g = 1; g < NG; g++) {
        p = g6 * g_S[base + (size_t)(g - 1) * DIM * DIM] + g6C * p;
        g_P[base + (size_t)g * DIM * DIM] = p;
    }
}

// ---------------------------------------------------------------------------
// K5 (NEW): per-group local term via two MMAs.
// S80 = Q_g @ K_g^T  ->  M[t][s] = w_intra*S[t][s] + w_cross*S[t+5][s]
// out_group = M @ V_g  (written, not accumulated; K4 does += after)
// grid (NG, BATCH), 256 threads, dynamic smem.
// ---------------------------------------------------------------------------
#define L2_S_OFF   0                 // fp32 S[80][84]            26,880 B
#define L2_QK_OFF  26880             // 4 x u32[80][20]           25,600 B (phase1)
#define L2_M_OFF   26880             // 2 x u32[80][44]           28,160 B (phase2)
#define L2_V_OFF   55040             // 2 x u32[80][68]           43,520 B (phase2)
#define L2_SMEM    98560

__global__ __launch_bounds__(256) void local2_kernel(float* __restrict__ out)
{
    extern __shared__ char sm[];
    float*    sS  = (float*)(sm + L2_S_OFF);            // [80][84]
    uint32_t* sQh = (uint32_t*)(sm + L2_QK_OFF);        // [80][20]
    uint32_t* sQl = sQh + 80 * 20;
    uint32_t* sKh = sQl + 80 * 20;
    uint32_t* sKl = sKh + 80 * 20;
    uint32_t* sMh = (uint32_t*)(sm + L2_M_OFF);         // [80][44]
    uint32_t* sMl = sMh + 80 * 44;
    uint32_t* sVh = (uint32_t*)(sm + L2_V_OFF);         // [80][68]
    uint32_t* sVl = sVh + 80 * 68;

    int g = blockIdx.x, b = blockIdx.y;
    int tid = threadIdx.x, lane = tid & 31, wid = tid >> 5;
    int lr = lane & 7, lg = lane >> 3;
    int g4 = lane >> 2, t4 = (lane & 3) * 2;

    const size_t tokBase = (size_t)b * SEQ + (size_t)g * TOKG;
    const float* Qb = g_Q + tokBase * 256;
    const float* Kb = g_K + tokBase * 256;
    const float* Vb = g_V + tokBase * 256;

    // lane-row components for ldmatrix addressing
    unsigned rowsel = lr + (lg & 1) * 8;
    unsigned colsel = (lg >> 1) * 8;

    // ---------------- Phase 1: S = Q @ K^T  (K-dim 256, slabs of 32) --------
    float acc1[4][2][4];
#pragma unroll
    for (int i = 0; i < 4; i++)
#pragma unroll
        for (int j = 0; j < 2; j++)
#pragma unroll
            for (int q = 0; q < 4; q++) acc1[i][j][q] = 0.f;

    unsigned qH = su32(sQh) + (rowsel * 40 + colsel) * 2;
    unsigned qL = su32(sQl) + (rowsel * 40 + colsel) * 2;
    unsigned kH = su32(sKh) + (rowsel * 40 + colsel) * 2;
    unsigned kL = su32(sKl) + (rowsel * 40 + colsel) * 2;

    for (int k0 = 0; k0 < 256; k0 += 32) {
#pragma unroll
        for (int j = 0; j < 3; j++) {                 // 640 float4 per matrix
            int i = tid + j * 256;
            if (i < 640) {
                int r = i >> 3, kq = (i & 7) * 4;
                float4 v = *(const float4*)(Qb + (size_t)r * 256 + k0 + kq);
                uint32_t h0, l0, h1, l1;
                split2(v.x, v.y, h0, l0); split2(v.z, v.w, h1, l1);
                int idx = r * 20 + (kq >> 1);
                sQh[idx] = h0; sQh[idx + 1] = h1; sQl[idx] = l0; sQl[idx + 1] = l1;
                v = *(const float4*)(Kb + (size_t)r * 256 + k0 + kq);
                split2(v.x, v.y, h0, l0); split2(v.z, v.w, h1, l1);
                sKh[idx] = h0; sKh[idx + 1] = h1; sKl[idx] = l0; sKl[idx + 1] = l1;
            }
        }
        __syncthreads();
#pragma unroll
        for (int ks = 0; ks < 32; ks += 16) {
            int li = 0;
            for (int tile = wid; tile < 25; tile += 8, li++) {
                int mt = tile / 5, nt = tile - mt * 5;
                unsigned ao = ((unsigned)(mt * 16) * 40 + ks) * 2;
                unsigned bo = ((unsigned)(nt * 16) * 40 + ks) * 2;
                uint32_t ah[4], al[4], rh[4], rl[4];
                ldm4(ah, qH + ao); ldm4(al, qL + ao);
                ldm4(rh, kH + bo); ldm4(rl, kL + bo);
                uint32_t bh0[2] = {rh[0], rh[2]}, bh1[2] = {rh[1], rh[3]};
                uint32_t bl0[2] = {rl[0], rl[2]}, bl1[2] = {rl[1], rl[3]};
                mma16816(acc1[li][0], ah, bh0);
                mma16816(acc1[li][0], ah, bl0);
                mma16816(acc1[li][0], al, bh0);
                mma16816(acc1[li][1], ah, bh1);
                mma16816(acc1[li][1], ah, bl1);
                mma16816(acc1[li][1], al, bh1);
            }
        }
        __syncthreads();
    }

    // write S tiles (sS region disjoint from Q/K slabs)
    {
        int li = 0;
        for (int tile = wid; tile < 25; tile += 8, li++) {
            int mt = tile / 5, nt = tile - mt * 5;
#pragma unroll
            for (int sub = 0; sub < 2; sub++) {
                int c = nt * 16 + sub * 8 + t4;
                int r = mt * 16 + g4;
                sS[r * 84 + c]     = acc1[li][sub][0];
                sS[r * 84 + c + 1] = acc1[li][sub][1];
                sS[(r + 8) * 84 + c]     = acc1[li][sub][2];
                sS[(r + 8) * 84 + c + 1] = acc1[li][sub][3];
            }
        }
    }
    __syncthreads();

    // ---------------- Phase 2a: build M (masked/weighted/shifted S) --------
    for (int pz = tid; pz < 3200; pz += 256) {
        int t = pz / 40, sp = pz - t * 40;
        int i = t / 5, o = t - i * 5;
        float mv[2];
#pragma unroll
        for (int u = 0; u < 2; u++) {
            int s = sp * 2 + u;
            int j = s / 5, p = s - j * 5;
            float v = 0.f;
            if (j == i && p <= o) v += gpow((float)(p - o)) * sS[t * 84 + s];
            if (i < 15 && j <= i) v += gpow((float)(6 * (i + 1 - j))) * sS[(t + 5) * 84 + s];
            mv[u] = v;
        }
        uint32_t h, l;
        split2(mv[0], mv[1], h, l);
        sMh[t * 44 + sp] = h;
        sMl[t * 44 + sp] = l;
    }

    // ---------------- Phase 2b: out = M @ V  (two 128-wide n-slabs) --------
    unsigned mH = su32(sMh) + (rowsel * 88 + colsel) * 2;
    unsigned mL = su32(sMl) + (rowsel * 88 + colsel) * 2;
    unsigned vH = su32(sVh) + (rowsel * 136 + (unsigned)wid * 16 + colsel) * 2;
    unsigned vL = su32(sVl) + (rowsel * 136 + (unsigned)wid * 16 + colsel) * 2;

    for (int e0 = 0; e0 < 256; e0 += 128) {
#pragma unroll
        for (int j = 0; j < 10; j++) {                // 2560 float4
            int i = tid + j * 256;
            int r = i >> 5, eq = (i & 31) * 4;
            float4 v = *(const float4*)(Vb + (size_t)r * 256 + e0 + eq);
            uint32_t h0, l0, h1, l1;
            split2(v.x, v.y, h0, l0); split2(v.z, v.w, h1, l1);
            int idx = r * 68 + (eq >> 1);
            sVh[idx] = h0; sVh[idx + 1] = h1; sVl[idx] = l0; sVl[idx + 1] = l1;
        }
        __syncthreads();

        float acc2[5][2][4];
#pragma unroll
        for (int i = 0; i < 5; i++)
#pragma unroll
            for (int j = 0; j < 2; j++)
#pragma unroll
                for (int q = 0; q < 4; q++) acc2[i][j][q] = 0.f;

#pragma unroll
        for (int ks = 0; ks < 80; ks += 16) {
            uint32_t bh[4], bl[4];
            unsigned vo = ((unsigned)ks * 136) * 2;
            ldm4t(bh, vH + vo); ldm4t(bl, vL + vo);
#pragma unroll
            for (int mt = 0; mt < 5; mt++) {
                unsigned ao = ((unsigned)(mt * 16) * 88 + ks) * 2;
                uint32_t ah[4], al[4];
                ldm4(ah, mH + ao); ldm4(al, mL + ao);
                mma16816(acc2[mt][0], ah, &bh[0]);
                mma16816(acc2[mt][0], ah, &bl[0]);
                mma16816(acc2[mt][0], al, &bh[0]);
                mma16816(acc2[mt][1], ah, &bh[2]);
                mma16816(acc2[mt][1], ah, &bl[2]);
                mma16816(acc2[mt][1], al, &bh[2]);
            }
        }

#pragma unroll
        for (int mt = 0; mt < 5; mt++)
#pragma unroll
            for (int nt = 0; nt < 2; nt++) {
                int r = mt * 16 + g4;
                int c = e0 + wid * 16 + nt * 8 + t4;
                float* O0 = out + (tokBase + r) * 256 + c;
                float* O1 = out + (tokBase + r + 8) * 256 + c;
                *(float2*)O0 = make_float2(acc2[mt][nt][0], acc2[mt][nt][1]);
                *(float2*)O1 = make_float2(acc2[mt][nt][2], acc2[mt][nt][3]);
            }
        __syncthreads();
    }
}

// ---------------------------------------------------------------------------
// K4: global cross via mma. grid (2, 400)
// ---------------------------------------------------------------------------
__global__ __launch_bounds__(256) void crossglobal_mma(float* __restrict__ out)
{
    int bz = blockIdx.y;
    int b = bz / NG, g = bz % NG;
    int e0 = blockIdx.x * 128;

    __shared__ uint32_t sQh[80 * (KP / 2)], sQl[80 * (KP / 2)];
    __shared__ uint32_t sPh[32 * (NP / 2)], sPl[32 * (NP / 2)];

    int tid = threadIdx.x, lane = tid & 31, wid = tid >> 5;
    int lr = lane & 7, lg = lane >> 3;
    int warp_n = wid * 16;

    const float* Qb = g_Q + (size_t)(b * SEQ + g * TOKG) * 256;
    const float* Pb = g_P + (size_t)bz * DIM * DIM;

    float acc[5][2][4];
#pragma unroll
    for (int i = 0; i < 5; i++)
#pragma unroll
        for (int j = 0; j < 2; j++)
#pragma unroll
            for (int q = 0; q < 4; q++) acc[i][j][q] = 0.f;

    unsigned aOff = ((unsigned)(lr + (lg & 1) * 8) * KP + (lg >> 1) * 8) * 2;
    unsigned aBh = su32(sQh) + aOff, aBl = su32(sQl) + aOff;
    unsigned bOff = ((unsigned)(lr + (lg & 1) * 8) * NP + warp_n + (lg >> 1) * 8) * 2;
    unsigned bBh = su32(sPh) + bOff, bBl = su32(sPl) + bOff;

    for (int k0 = 0; k0 < 256; k0 += 32) {
#pragma unroll
        for (int j = 0; j < 3; j++) {
            int i = tid + j * 256;
            if (i < 640) {
                int r = i >> 3, kq = (i & 7) * 4;
                float4 v = *(const float4*)(Qb + (size_t)r * 256 + k0 + kq);
                uint32_t h0, l0, h1, l1;
                split2(v.x, v.y, h0, l0); split2(v.z, v.w, h1, l1);
                int idx = r * (KP / 2) + (kq >> 1);
                sQh[idx] = h0; sQh[idx + 1] = h1; sQl[idx] = l0; sQl[idx + 1] = l1;
            }
        }
#pragma unroll
        for (int j = 0; j < 4; j++) {
            int i = tid + j * 256;
            int r = i >> 5, nq = (i & 31) * 4;
            float4 v = *(const float4*)(Pb + (size_t)(k0 + r) * 256 + e0 + nq);
            uint32_t h0, l0, h1, l1;
            split2(v.x, v.y, h0, l0); split2(v.z, v.w, h1, l1);
            int idx = r * (NP / 2) + (nq >> 1);
            sPh[idx] = h0; sPh[idx + 1] = h1; sPl[idx] = l0; sPl[idx + 1] = l1;
        }
        __syncthreads();
#pragma unroll
        for (int ks = 0; ks < 32; ks += 16) {
            uint32_t ah[5][4], al[5][4], bh[4], bl[4];
#pragma unroll
            for (int mt = 0; mt < 5; mt++) {
                unsigned o = ((unsigned)(mt * 16) * KP + ks) * 2;
                ldm4(ah[mt], aBh + o); ldm4(al[mt], aBl + o);
            }
            {
                unsigned o = ((unsigned)ks * NP) * 2;
                ldm4t(bh, bBh + o); ldm4t(bl, bBl + o);
            }
#pragma unroll
            for (int mt = 0; mt < 5; mt++)
#pragma unroll
                for (int nt = 0; nt < 2; nt++) {
                    const uint32_t* bhp = &bh[nt * 2];
                    const uint32_t* blp = &bl[nt * 2];
                    mma16816(acc[mt][nt], ah[mt], bhp);
                    mma16816(acc[mt][nt], ah[mt], blp);
                    mma16816(acc[mt][nt], al[mt], bhp);
                }
        }
        __syncthreads();
    }

    int g4 = lane >> 2, t4 = (lane & 3) * 2;
#pragma unroll
    for (int mt = 0; mt < 5; mt++)
#pragma unroll
        for (int nt = 0; nt < 2; nt++) {
            int c = e0 + warp_n + nt * 8 + t4;
            int r1 = mt * 16 + g4;
            int tok1 = g * TOKG + r1 - 5;
            if (tok1 >= 0) {
                float s = gpow((float)(6 * (r1 / 5)));
                float2* p = (float2*)&out[((size_t)b * SEQ + tok1) * 256 + c];
                float2 o = *p;
                o.x += s * acc[mt][nt][0]; o.y += s * acc[mt][nt][1];
                *p = o;
            }
            int r2 = r1 + 8;
            int tok2 = g * TOKG + r2 - 5;
            if (tok2 >= 0) {
                float s = gpow((float)(6 * (r2 / 5)));
                float2* p = (float2*)&out[((size_t)b * SEQ + tok2) * 256 + c];
                float2 o = *p;
                o.x += s * acc[mt][nt][2]; o.y += s * acc[mt][nt][3];
                *p = o;
            }
        }
}

// ---------------------------------------------------------------------------
extern "C" void kernel_launch(void* const* d_in, const int* in_sizes, int n_in,
                              void* d_out, int out_size)
{
    const float* xq = (const float*)d_in[0];
    const float* xk = (const float*)d_in[1];
    const float* xv = (const float*)d_in[2];
    const float* Wq = (const float*)d_in[3];
    const float* Wk = (const float*)d_in[4];
    const float* Wv = (const float*)d_in[5];
    float* out = (float*)d_out;

    cudaFuncSetAttribute(local2_kernel, cudaFuncAttributeMaxDynamicSharedMemorySize, L2_SMEM);

    dim3 blk(256);
    proj_mma<<<dim3(2, 250, 3), blk>>>(xq, xk, xv, Wq, Wk, Wv);
    groupstate_mma<<<dim3(2, 2, BATCH * NG), blk>>>();
    prefix_kernel<<<dim3((BATCH * DIM * DIM + 255) / 256), blk>>>();
    local2_kernel<<<dim3(NG, BATCH), blk, L2_SMEM>>>(out);
    crossglobal_mma<<<dim3(2, BATCH * NG), blk>>>(out);
}

// round 7
// speedup vs baseline: 2.3461x; 1.1353x over previous
#include <cuda_runtime.h>
#include <cuda_bf16.h>
#include <stdint.h>
#include <math.h>

#define BATCH   8
#define SEQ     4000
#define DIM     256
#define BCH     5
#define NCHUNK  800
#define CG      16
#define NG      50
#define TOKG    (CG*BCH)

#define NEL     (BATCH*SEQ*DIM)      // 8,192,000
#define NEL2    (NEL/2)              // 4,096,000 u32

#define GLOG2 (-0.0196090426f)
__device__ __forceinline__ float gpow(float k) { return exp2f(k * GLOG2); }

// ------------------------- global scratch (no alloc) ------------------------
__device__ uint32_t g_Xh[3 * NEL2], g_Xl[3 * NEL2];     // split inputs
__device__ uint32_t g_Wsh[3 * 32768], g_Wsl[3 * 32768]; // split weights
__device__ uint32_t g_Qh[NEL2], g_Ql[NEL2];
__device__ uint32_t g_Kh[NEL2], g_Kl[NEL2];
__device__ uint32_t g_Vh[NEL2], g_Vl[NEL2];
__device__ uint32_t g_Kwh[NEL2], g_Kwl[NEL2];           // pre-weighted K
__device__ float    g_S[(size_t)BATCH * NG * DIM * DIM];
__device__ uint32_t g_Ph[(size_t)BATCH * NG * 32768], g_Pl[(size_t)BATCH * NG * 32768];

// ------------------------------ helpers -------------------------------------
__device__ __forceinline__ unsigned su32(const void* p) {
    return (unsigned)__cvta_generic_to_shared(p);
}
__device__ __forceinline__ void cpa16(unsigned s, const void* g) {
    asm volatile("cp.async.cg.shared.global [%0], [%1], 16;" :: "r"(s), "l"(g));
}
__device__ __forceinline__ void cp_commit() { asm volatile("cp.async.commit_group;"); }
template<int N> __device__ __forceinline__ void cp_wait() {
    asm volatile("cp.async.wait_group %0;" :: "n"(N));
}
__device__ __forceinline__ void ldm4(uint32_t* r, unsigned addr) {
    asm volatile("ldmatrix.sync.aligned.m8n8.x4.shared.b16 {%0,%1,%2,%3}, [%4];"
        : "=r"(r[0]), "=r"(r[1]), "=r"(r[2]), "=r"(r[3]) : "r"(addr));
}
__device__ __forceinline__ void ldm4t(uint32_t* r, unsigned addr) {
    asm volatile("ldmatrix.sync.aligned.m8n8.x4.trans.shared.b16 {%0,%1,%2,%3}, [%4];"
        : "=r"(r[0]), "=r"(r[1]), "=r"(r[2]), "=r"(r[3]) : "r"(addr));
}
__device__ __forceinline__ void mma16816(float* c, const uint32_t* a, const uint32_t* b) {
    asm volatile(
        "mma.sync.aligned.m16n8k16.row.col.f32.bf16.bf16.f32 "
        "{%0,%1,%2,%3},{%4,%5,%6,%7},{%8,%9},{%0,%1,%2,%3};"
        : "+f"(c[0]), "+f"(c[1]), "+f"(c[2]), "+f"(c[3])
        : "r"(a[0]), "r"(a[1]), "r"(a[2]), "r"(a[3]), "r"(b[0]), "r"(b[1]));
}
__device__ __forceinline__ void split2(float x, float y, uint32_t& h, uint32_t& l) {
    __nv_bfloat162 hb = __floats2bfloat162_rn(x, y);
    float rx = x - __bfloat162float(hb.x);
    float ry = y - __bfloat162float(hb.y);
    __nv_bfloat162 lb = __floats2bfloat162_rn(rx, ry);
    h = *reinterpret_cast<uint32_t*>(&hb);
    l = *reinterpret_cast<uint32_t*>(&lb);
}

// ---------------------------------------------------------------------------
// K0: presplit inputs + weights into bf16 hi/lo. grid (8064,1,3)
// ---------------------------------------------------------------------------
__global__ __launch_bounds__(256) void presplit_kernel(
    const float* __restrict__ xq, const float* __restrict__ xk, const float* __restrict__ xv,
    const float* __restrict__ Wq, const float* __restrict__ Wk, const float* __restrict__ Wv)
{
    int which = blockIdx.z;
    int bid = blockIdx.x, tid = threadIdx.x;
    const float4* src; uint2* dh; uint2* dl; int idx;
    if (bid < 8000) {
        const float* s = which == 0 ? xq : (which == 1 ? xk : xv);
        src = (const float4*)s;
        dh = (uint2*)(g_Xh + (size_t)which * NEL2);
        dl = (uint2*)(g_Xl + (size_t)which * NEL2);
        idx = bid * 256 + tid;
    } else {
        const float* s = which == 0 ? Wq : (which == 1 ? Wk : Wv);
        src = (const float4*)s;
        dh = (uint2*)(g_Wsh + which * 32768);
        dl = (uint2*)(g_Wsl + which * 32768);
        idx = (bid - 8000) * 256 + tid;
    }
    float4 v = src[idx];
    uint32_t h0, l0, h1, l1;
    split2(v.x, v.y, h0, l0); split2(v.z, v.w, h1, l1);
    dh[idx] = make_uint2(h0, h1);
    dl[idx] = make_uint2(l0, l1);
}

// ---------------------------------------------------------------------------
// K1: QKV projections, cp.async pipelined, pre-split operands. grid (2,250,3)
// smem per stage: A hi/lo [128][40h] (10240B each) + B hi/lo [32][136h] (8704B each)
// ---------------------------------------------------------------------------
#define PJ_STAGE 37888

__device__ __forceinline__ void pj_copy(unsigned sb, int tid, int row0, int col0, int k0,
    const char* Agh, const char* Agl, const char* Bgh, const char* Bgl)
{
#pragma unroll
    for (int j = 0; j < 8; j++) {
        int c = tid + j * 256;
        int seg = c >> 9, cc = c & 511;
        if (seg < 2) {
            int r = cc >> 2, ch = cc & 3;
            const char* gp = (seg ? Agl : Agh) + ((size_t)(row0 + r) * 256 + k0) * 2 + ch * 16;
            cpa16(sb + seg * 10240u + r * 80u + ch * 16u, gp);
        } else {
            int r = cc >> 4, ch = cc & 15;
            const char* gp = (seg == 3 ? Bgl : Bgh) + ((size_t)(k0 + r) * 256 + col0) * 2 + ch * 16;
            cpa16(sb + 20480u + (seg - 2) * 8704u + r * 272u + ch * 16u, gp);
        }
    }
}

__global__ __launch_bounds__(256) void proj_mma()
{
    extern __shared__ char sm[];
    int which = blockIdx.z;
    const char* Agh = (const char*)(g_Xh + (size_t)which * NEL2);
    const char* Agl = (const char*)(g_Xl + (size_t)which * NEL2);
    const char* Bgh = (const char*)(g_Wsh + which * 32768);
    const char* Bgl = (const char*)(g_Wsl + which * 32768);
    uint32_t* Ch = which == 0 ? g_Qh : (which == 1 ? g_Kh : g_Vh);
    uint32_t* Cl = which == 0 ? g_Ql : (which == 1 ? g_Kl : g_Vl);

    int tid = threadIdx.x, lane = tid & 31, wid = tid >> 5;
    int lr = lane & 7, lg = lane >> 3;
    int warp_m = (wid & 1) * 64, warp_n = (wid >> 1) * 32;
    int row0 = blockIdx.y * 128, col0 = blockIdx.x * 128;
    unsigned smB = su32(sm);
    unsigned rowsel = lr + (lg & 1) * 8, colsel = (lg >> 1) * 8;
    unsigned aoff = (unsigned)(warp_m + rowsel) * 80 + colsel * 2;
    unsigned boff = (unsigned)rowsel * 272 + (warp_n + colsel) * 2;

    float acc[4][4][4];
#pragma unroll
    for (int i = 0; i < 4; i++)
#pragma unroll
        for (int j = 0; j < 4; j++)
#pragma unroll
            for (int q = 0; q < 4; q++) acc[i][j][q] = 0.f;

    pj_copy(smB, tid, row0, col0, 0, Agh, Agl, Bgh, Bgl);
    cp_commit();

    for (int it = 0; it < 8; it++) {
        int cur = it & 1;
        if (it < 7) {
            pj_copy(smB + (1 - cur) * PJ_STAGE, tid, row0, col0, (it + 1) * 32, Agh, Agl, Bgh, Bgl);
            cp_commit();
            cp_wait<1>();
        } else cp_wait<0>();
        __syncthreads();

        unsigned sb = smB + cur * PJ_STAGE;
        unsigned aH = sb + aoff, aL = aH + 10240;
        unsigned bH = sb + 20480 + boff, bL = bH + 8704;
#pragma unroll
        for (int ks = 0; ks < 32; ks += 16) {
            uint32_t ah[4][4], al[4][4], bh[2][4], bl[2][4];
#pragma unroll
            for (int mt = 0; mt < 4; mt++) {
                unsigned o = (unsigned)(mt * 16) * 80 + ks * 2;
                ldm4(ah[mt], aH + o); ldm4(al[mt], aL + o);
            }
#pragma unroll
            for (int np = 0; np < 2; np++) {
                unsigned o = (unsigned)ks * 272 + np * 32;
                ldm4t(bh[np], bH + o); ldm4t(bl[np], bL + o);
            }
#pragma unroll
            for (int mt = 0; mt < 4; mt++)
#pragma unroll
                for (int nt = 0; nt < 4; nt++) {
                    const uint32_t* bhp = &bh[nt >> 1][(nt & 1) * 2];
                    const uint32_t* blp = &bl[nt >> 1][(nt & 1) * 2];
                    mma16816(acc[mt][nt], ah[mt], bhp);
                    mma16816(acc[mt][nt], ah[mt], blp);
                    mma16816(acc[mt][nt], al[mt], bhp);
                }
        }
        __syncthreads();
    }

    int g4 = lane >> 2, t4 = (lane & 3) * 2;
    bool isK = (which == 1);
#pragma unroll
    for (int mt = 0; mt < 4; mt++)
#pragma unroll
        for (int nt = 0; nt < 4; nt++) {
            int r = row0 + warp_m + mt * 16 + g4;
            int c = col0 + warp_n + nt * 8 + t4;
#pragma unroll
            for (int h2 = 0; h2 < 2; h2++) {
                int rr = r + h2 * 8;
                float a0 = acc[mt][nt][h2 * 2], a1 = acc[mt][nt][h2 * 2 + 1];
                uint32_t hh, ll;
                split2(a0, a1, hh, ll);
                size_t o = ((size_t)rr * 256 + c) >> 1;
                Ch[o] = hh; Cl[o] = ll;
                if (isK) {
                    int tok = rr % SEQ;
                    float w = gpow(6.f * (float)(15 - ((tok / 5) & 15)));
                    split2(w * a0, w * a1, hh, ll);
                    g_Kwh[o] = hh; g_Kwl[o] = ll;
                }
            }
        }
}

// ---------------------------------------------------------------------------
// K2: group states S_g = Kw^T V, pure-copy cp.async pipelined. grid (2,2,400)
// stage: Kwh[16][136] @0, Kwl @4352, Vh @8704, Vl @13056; stride 17408
// ---------------------------------------------------------------------------
__device__ __forceinline__ void gs_copy(unsigned sb, int tid, size_t bTok, int t0, int d0, int e0)
{
#pragma unroll
    for (int j = 0; j < 4; j++) {
        int c = tid + j * 256;
        int seg = c >> 8, cc = c & 255;
        int r = cc >> 4, ch = cc & 15;
        const char* base = seg == 0 ? (const char*)g_Kwh : seg == 1 ? (const char*)g_Kwl
                         : seg == 2 ? (const char*)g_Vh : (const char*)g_Vl;
        size_t gidx = ((bTok + t0 + r) * 256 + ((seg < 2) ? d0 : e0)) * 2 + ch * 16;
        cpa16(sb + seg * 4352u + r * 272u + ch * 16u, base + gidx);
    }
}

__global__ __launch_bounds__(256) void groupstate_mma()
{
    __shared__ __align__(16) char gsm[2 * 17408];
    int bz = blockIdx.z;
    int b = bz / NG, g = bz % NG;
    int d0 = blockIdx.y * 128, e0 = blockIdx.x * 128;
    size_t bTok = (size_t)b * SEQ + (size_t)g * TOKG;

    int tid = threadIdx.x, lane = tid & 31, wid = tid >> 5;
    int lr = lane & 7, lg = lane >> 3;
    int warp_m = (wid & 1) * 64, warp_n = (wid >> 1) * 32;
    unsigned smB = su32(gsm);

    unsigned aoff = ((unsigned)(lr + (lg >> 1) * 8) * 136 + warp_m + (lg & 1) * 8) * 2;
    unsigned boff = ((unsigned)(lr + (lg & 1) * 8) * 136 + warp_n + (lg >> 1) * 8) * 2;

    float acc[4][4][4];
#pragma unroll
    for (int i = 0; i < 4; i++)
#pragma unroll
        for (int j = 0; j < 4; j++)
#pragma unroll
            for (int q = 0; q < 4; q++) acc[i][j][q] = 0.f;

    gs_copy(smB, tid, bTok, 0, d0, e0);
    cp_commit();

    for (int it = 0; it < 5; it++) {
        int cur = it & 1;
        if (it < 4) {
            gs_copy(smB + (1 - cur) * 17408, tid, bTok, (it + 1) * 16, d0, e0);
            cp_commit();
            cp_wait<1>();
        } else cp_wait<0>();
        __syncthreads();

        unsigned sb = smB + cur * 17408;
        uint32_t ah[4][4], al[4][4], bh[2][4], bl[2][4];
#pragma unroll
        for (int mt = 0; mt < 4; mt++) {
            unsigned o = (unsigned)(mt * 16) * 2;
            ldm4t(ah[mt], sb + aoff + o); ldm4t(al[mt], sb + 4352 + aoff + o);
        }
#pragma unroll
        for (int np = 0; np < 2; np++) {
            unsigned o = (unsigned)(np * 16) * 2;
            ldm4t(bh[np], sb + 8704 + boff + o); ldm4t(bl[np], sb + 13056 + boff + o);
        }
#pragma unroll
        for (int mt = 0; mt < 4; mt++)
#pragma unroll
            for (int nt = 0; nt < 4; nt++) {
                const uint32_t* bhp = &bh[nt >> 1][(nt & 1) * 2];
                const uint32_t* blp = &bl[nt >> 1][(nt & 1) * 2];
                mma16816(acc[mt][nt], ah[mt], bhp);
                mma16816(acc[mt][nt], ah[mt], blp);
                mma16816(acc[mt][nt], al[mt], bhp);
            }
        __syncthreads();
    }

    int g4 = lane >> 2, t4 = (lane & 3) * 2;
    float* S = g_S + (size_t)bz * DIM * DIM;
#pragma unroll
    for (int mt = 0; mt < 4; mt++)
#pragma unroll
        for (int nt = 0; nt < 4; nt++) {
            int r = d0 + warp_m + mt * 16 + g4;
            int c = e0 + warp_n + nt * 8 + t4;
            *(float2*)&S[(size_t)r * 256 + c] = make_float2(acc[mt][nt][0], acc[mt][nt][1]);
            *(float2*)&S[(size_t)(r + 8) * 256 + c] = make_float2(acc[mt][nt][2], acc[mt][nt][3]);
        }
}

// ---------------------------------------------------------------------------
// K3: exclusive group prefix; outputs split P. 2 elements/thread. grid 1024.
// ---------------------------------------------------------------------------
__global__ __launch_bounds__(256) void prefix_kernel()
{
    int idx = blockIdx.x * 256 + threadIdx.x;   // BATCH*32768 = 262144
    int b = idx >> 15, de2 = idx & 32767;
    int de = de2 * 2;
    size_t sbase = (size_t)b * NG * 65536 + de;
    size_t pbase = (size_t)b * NG * 32768 + de2;
    const float g6 = gpow(6.f), g6C = gpow(96.f);
    float p0 = 0.f, p1 = 0.f;
    g_Ph[pbase] = 0; g_Pl[pbase] = 0;
    for (int g = 1; g < NG; g++) {
        float2 s = *(const float2*)&g_S[sbase + (size_t)(g - 1) * 65536];
        p0 = g6 * s.x + g6C * p0;
        p1 = g6 * s.y + g6C * p1;
        uint32_t h, l;
        split2(p0, p1, h, l);
        g_Ph[pbase + (size_t)g * 32768] = h;
        g_Pl[pbase + (size_t)g * 32768] = l;
    }
}

// ---------------------------------------------------------------------------
// K5: per-group local term (2 MMAs), cp.async feeds. grid (50, 8), dyn smem.
// layout: sS fp32[80][84] @0 (26880)
//  phase1: QK stages @26880 + st*25600 (Qh@0,Ql@6400,Kh@12800,Kl@19200)
//  phase2: sMh @26880 (14080), sMl @40960; sVh @55040 (21760), sVl @76800
// total 98560
// ---------------------------------------------------------------------------
#define L2_SMEM 98560

__device__ __forceinline__ void l2_qkcopy(unsigned sb, int tid, size_t tokBase, int k0)
{
#pragma unroll
    for (int j = 0; j < 5; j++) {
        int c = tid + j * 256;
        int seg = c / 320, cc = c - seg * 320;
        int r = cc >> 2, ch = cc & 3;
        const char* base = seg == 0 ? (const char*)g_Qh : seg == 1 ? (const char*)g_Ql
                         : seg == 2 ? (const char*)g_Kh : (const char*)g_Kl;
        cpa16(sb + seg * 6400u + r * 80u + ch * 16u,
              base + ((tokBase + r) * 256 + k0) * 2 + ch * 16);
    }
}
__device__ __forceinline__ void l2_vcopy(unsigned smB, int tid, size_t tokBase, int e0)
{
#pragma unroll
    for (int j = 0; j < 10; j++) {
        int c = tid + j * 256;
        int seg = c / 1280, cc = c - seg * 1280;
        int r = cc >> 4, ch = cc & 15;
        const char* base = seg ? (const char*)g_Vl : (const char*)g_Vh;
        cpa16(smB + 55040u + seg * 21760u + r * 272u + ch * 16u,
              base + ((tokBase + r) * 256 + e0) * 2 + ch * 16);
    }
}

__global__ __launch_bounds__(256) void local2_kernel(float* __restrict__ out)
{
    extern __shared__ char sm[];
    float* sS = (float*)sm;                       // [80][84]
    uint32_t* sMh = (uint32_t*)(sm + 26880);      // [80][44]
    uint32_t* sMl = (uint32_t*)(sm + 40960);

    int g = blockIdx.x, b = blockIdx.y;
    int tid = threadIdx.x, lane = tid & 31, wid = tid >> 5;
    int lr = lane & 7, lg = lane >> 3;
    int g4 = lane >> 2, t4 = (lane & 3) * 2;
    unsigned smB = su32(sm);

    const size_t tokBase = (size_t)b * SEQ + (size_t)g * TOKG;

    unsigned rowsel = lr + (lg & 1) * 8;
    unsigned colsel = (lg >> 1) * 8;

    // ---------------- Phase 1: S = Q @ K^T ---------------------------------
    float acc1[4][2][4];
#pragma unroll
    for (int i = 0; i < 4; i++)
#pragma unroll
        for (int j = 0; j < 2; j++)
#pragma unroll
            for (int q = 0; q < 4; q++) acc1[i][j][q] = 0.f;

    l2_qkcopy(smB + 26880, tid, tokBase, 0);
    cp_commit();

    for (int it = 0; it < 8; it++) {
        int cur = it & 1;
        if (it < 7) {
            l2_qkcopy(smB + 26880 + (1 - cur) * 25600, tid, tokBase, (it + 1) * 32);
            cp_commit();
            cp_wait<1>();
        } else cp_wait<0>();
        __syncthreads();

        unsigned sb = smB + 26880 + cur * 25600;
        unsigned qH = sb + rowsel * 80 + colsel * 2, qL = qH + 6400;
        unsigned kH = qH + 12800, kL = qH + 19200;
#pragma unroll
        for (int ks = 0; ks < 32; ks += 16) {
            int li = 0;
            for (int tile = wid; tile < 25; tile += 8, li++) {
                int mt = tile / 5, nt = tile - mt * 5;
                unsigned ao = (unsigned)(mt * 16) * 80 + ks * 2;
                unsigned bo = (unsigned)(nt * 16) * 80 + ks * 2;
                uint32_t ah[4], al[4], rh[4], rl[4];
                ldm4(ah, qH + ao); ldm4(al, qL + ao);
                ldm4(rh, kH + bo); ldm4(rl, kL + bo);
                uint32_t bh0[2] = {rh[0], rh[2]}, bh1[2] = {rh[1], rh[3]};
                uint32_t bl0[2] = {rl[0], rl[2]}, bl1[2] = {rl[1], rl[3]};
                mma16816(acc1[li][0], ah, bh0);
                mma16816(acc1[li][0], ah, bl0);
                mma16816(acc1[li][0], al, bh0);
                mma16816(acc1[li][1], ah, bh1);
                mma16816(acc1[li][1], ah, bl1);
                mma16816(acc1[li][1], al, bh1);
            }
        }
        __syncthreads();
    }

    {
        int li = 0;
        for (int tile = wid; tile < 25; tile += 8, li++) {
            int mt = tile / 5, nt = tile - mt * 5;
#pragma unroll
            for (int sub = 0; sub < 2; sub++) {
                int c = nt * 16 + sub * 8 + t4;
                int r = mt * 16 + g4;
                sS[r * 84 + c]     = acc1[li][sub][0];
                sS[r * 84 + c + 1] = acc1[li][sub][1];
                sS[(r + 8) * 84 + c]     = acc1[li][sub][2];
                sS[(r + 8) * 84 + c + 1] = acc1[li][sub][3];
            }
        }
    }
    __syncthreads();

    // prefetch V slab e0=0 while building M
    l2_vcopy(smB, tid, tokBase, 0);
    cp_commit();

    // ---------------- Phase 2a: build M ------------------------------------
    for (int pz = tid; pz < 3200; pz += 256) {
        int t = pz / 40, sp = pz - t * 40;
        int i = t / 5, o = t - i * 5;
        float mv[2];
#pragma unroll
        for (int u = 0; u < 2; u++) {
            int s = sp * 2 + u;
            int j = s / 5, p = s - j * 5;
            float v = 0.f;
            if (j == i && p <= o) v += gpow((float)(p - o)) * sS[t * 84 + s];
            if (i < 15 && j <= i) v += gpow((float)(6 * (i + 1 - j))) * sS[(t + 5) * 84 + s];
            mv[u] = v;
        }
        uint32_t h, l;
        split2(mv[0], mv[1], h, l);
        sMh[t * 44 + sp] = h;
        sMl[t * 44 + sp] = l;
    }

    // ---------------- Phase 2b: out = M @ V --------------------------------
    unsigned mH = smB + 26880 + rowsel * 176 + colsel * 2, mL = mH + 14080;
    unsigned vH = smB + 55040 + rowsel * 272 + wid * 32 + colsel * 2, vL = vH + 21760;

#pragma unroll
    for (int pass = 0; pass < 2; pass++) {
        int e0 = pass * 128;
        cp_wait<0>();
        __syncthreads();

        float acc2[5][2][4];
#pragma unroll
        for (int i = 0; i < 5; i++)
#pragma unroll
            for (int j = 0; j < 2; j++)
#pragma unroll
                for (int q = 0; q < 4; q++) acc2[i][j][q] = 0.f;

#pragma unroll
        for (int ks = 0; ks < 80; ks += 16) {
            uint32_t bh[4], bl[4];
            unsigned vo = (unsigned)ks * 272;
            ldm4t(bh, vH + vo); ldm4t(bl, vL + vo);
#pragma unroll
            for (int mt = 0; mt < 5; mt++) {
                unsigned ao = (unsigned)(mt * 16) * 176 + ks * 2;
                uint32_t ah[4], al[4];
                ldm4(ah, mH + ao); ldm4(al, mL + ao);
                mma16816(acc2[mt][0], ah, &bh[0]);
                mma16816(acc2[mt][0], ah, &bl[0]);
                mma16816(acc2[mt][0], al, &bh[0]);
                mma16816(acc2[mt][1], ah, &bh[2]);
                mma16816(acc2[mt][1], ah, &bl[2]);
                mma16816(acc2[mt][1], al, &bh[2]);
            }
        }
        __syncthreads();
        if (pass == 0) {
            l2_vcopy(smB, tid, tokBase, 128);
            cp_commit();
        }

#pragma unroll
        for (int mt = 0; mt < 5; mt++)
#pragma unroll
            for (int nt = 0; nt < 2; nt++) {
                int r = mt * 16 + g4;
                int c = e0 + wid * 16 + nt * 8 + t4;
                float* O0 = out + (tokBase + r) * 256 + c;
                float* O1 = out + (tokBase + r + 8) * 256 + c;
                *(float2*)O0 = make_float2(acc2[mt][nt][0], acc2[mt][nt][1]);
                *(float2*)O1 = make_float2(acc2[mt][nt][2], acc2[mt][nt][3]);
            }
    }
}

// ---------------------------------------------------------------------------
// K4: global cross: out += scale * Q_group @ P_g. cp.async pipelined.
// stage: Qh@0(6400),Ql@6400,Ph@12800(8704),Pl@21504; stride 30208. grid (2,400)
// ---------------------------------------------------------------------------
#define CGX_SMEM 60416

__device__ __forceinline__ void cg_copy(unsigned sb, int tid, size_t qTok, size_t pBase, int k0, int e0)
{
#pragma unroll
    for (int j = 0; j < 7; j++) {
        int c = tid + j * 256;
        if (c >= 1664) break;
        if (c < 640) {
            int seg = c / 320, cc = c - seg * 320;
            int r = cc >> 2, ch = cc & 3;
            const char* base = seg ? (const char*)g_Ql : (const char*)g_Qh;
            cpa16(sb + seg * 6400u + r * 80u + ch * 16u,
                  base + ((qTok + r) * 256 + k0) * 2 + ch * 16);
        } else {
            int cc = c - 640;
            int seg = cc >> 9, c2 = cc & 511;
            int r = c2 >> 4, ch = c2 & 15;
            const char* base = seg ? (const char*)g_Pl : (const char*)g_Ph;
            cpa16(sb + 12800u + seg * 8704u + r * 272u + ch * 16u,
                  base + (pBase + (size_t)(k0 + r) * 256 + e0) * 2 + ch * 16);
        }
    }
}

__global__ __launch_bounds__(256) void crossglobal_mma(float* __restrict__ out)
{
    extern __shared__ char sm[];
    int bz = blockIdx.y;
    int b = bz / NG, g = bz % NG;
    int e0 = blockIdx.x * 128;
    size_t qTok = (size_t)b * SEQ + (size_t)g * TOKG;
    size_t pBase = (size_t)bz * 65536;

    int tid = threadIdx.x, lane = tid & 31, wid = tid >> 5;
    int lr = lane & 7, lg = lane >> 3;
    int warp_n = wid * 16;
    unsigned smB = su32(sm);

    unsigned rowsel = lr + (lg & 1) * 8, colsel = (lg >> 1) * 8;
    unsigned aoff = rowsel * 80 + colsel * 2;
    unsigned boff = rowsel * 272 + (warp_n + colsel) * 2;

    float acc[5][2][4];
#pragma unroll
    for (int i = 0; i < 5; i++)
#pragma unroll
        for (int j = 0; j < 2; j++)
#pragma unroll
            for (int q = 0; q < 4; q++) acc[i][j][q] = 0.f;

    cg_copy(smB, tid, qTok, pBase, 0, e0);
    cp_commit();

    for (int it = 0; it < 8; it++) {
        int cur = it & 1;
        if (it < 7) {
            cg_copy(smB + (1 - cur) * 30208, tid, qTok, pBase, (it + 1) * 32, e0);
            cp_commit();
            cp_wait<1>();
        } else cp_wait<0>();
        __syncthreads();

        unsigned sb = smB + cur * 30208;
        unsigned aH = sb + aoff, aL = aH + 6400;
        unsigned bH = sb + 12800 + boff, bL = bH + 8704;
#pragma unroll
        for (int ks = 0; ks < 32; ks += 16) {
            uint32_t ah[5][4], al[5][4], bh[4], bl[4];
#pragma unroll
            for (int mt = 0; mt < 5; mt++) {
                unsigned o = (unsigned)(mt * 16) * 80 + ks * 2;
                ldm4(ah[mt], aH + o); ldm4(al[mt], aL + o);
            }
            {
                unsigned o = (unsigned)ks * 272;
                ldm4t(bh, bH + o); ldm4t(bl, bL + o);
            }
#pragma unroll
            for (int mt = 0; mt < 5; mt++)
#pragma unroll
                for (int nt = 0; nt < 2; nt++) {
                    const uint32_t* bhp = &bh[nt * 2];
                    const uint32_t* blp = &bl[nt * 2];
                    mma16816(acc[mt][nt], ah[mt], bhp);
                    mma16816(acc[mt][nt], ah[mt], blp);
                    mma16816(acc[mt][nt], al[mt], bhp);
                }
        }
        __syncthreads();
    }

    int g4 = lane >> 2, t4 = (lane & 3) * 2;
#pragma unroll
    for (int mt = 0; mt < 5; mt++)
#pragma unroll
        for (int nt = 0; nt < 2; nt++) {
            int c = e0 + warp_n + nt * 8 + t4;
            int r1 = mt * 16 + g4;
            int tok1 = g * TOKG + r1 - 5;
            if (tok1 >= 0) {
                float s = gpow((float)(6 * (r1 / 5)));
                float2* p = (float2*)&out[((size_t)b * SEQ + tok1) * 256 + c];
                float2 o = *p;
                o.x += s * acc[mt][nt][0]; o.y += s * acc[mt][nt][1];
                *p = o;
            }
            int r2 = r1 + 8;
            int tok2 = g * TOKG + r2 - 5;
            if (tok2 >= 0) {
                float s = gpow((float)(6 * (r2 / 5)));
                float2* p = (float2*)&out[((size_t)b * SEQ + tok2) * 256 + c];
                float2 o = *p;
                o.x += s * acc[mt][nt][2]; o.y += s * acc[mt][nt][3];
                *p = o;
            }
        }
}

// ---------------------------------------------------------------------------
extern "C" void kernel_launch(void* const* d_in, const int* in_sizes, int n_in,
                              void* d_out, int out_size)
{
    const float* xq = (const float*)d_in[0];
    const float* xk = (const float*)d_in[1];
    const float* xv = (const float*)d_in[2];
    const float* Wq = (const float*)d_in[3];
    const float* Wk = (const float*)d_in[4];
    const float* Wv = (const float*)d_in[5];
    float* out = (float*)d_out;

    static int attrs_set = 0;
    if (!attrs_set) {
        cudaFuncSetAttribute(proj_mma, cudaFuncAttributeMaxDynamicSharedMemorySize, 2 * PJ_STAGE);
        cudaFuncSetAttribute(local2_kernel, cudaFuncAttributeMaxDynamicSharedMemorySize, L2_SMEM);
        cudaFuncSetAttribute(crossglobal_mma, cudaFuncAttributeMaxDynamicSharedMemorySize, CGX_SMEM);
        attrs_set = 1;
    }

    dim3 blk(256);
    presplit_kernel<<<dim3(8064, 1, 3), blk>>>(xq, xk, xv, Wq, Wk, Wv);
    proj_mma<<<dim3(2, 250, 3), blk, 2 * PJ_STAGE>>>();
    groupstate_mma<<<dim3(2, 2, BATCH * NG), blk>>>();
    prefix_kernel<<<dim3(1024), blk>>>();
    local2_kernel<<<dim3(NG, BATCH), blk, L2_SMEM>>>(out);
    crossglobal_mma<<<dim3(2, BATCH * NG), blk, CGX_SMEM>>>(out);
}

// round 10
// speedup vs baseline: 2.3709x; 1.0106x over previous
#include <cuda_runtime.h>
#include <cuda_bf16.h>
#include <stdint.h>
#include <math.h>

#define BATCH   8
#define SEQ     4000
#define DIM     256
#define BCH     5
#define NCHUNK  800
#define CG      16
#define NG      50
#define TOKG    (CG*BCH)

#define NEL     (BATCH*SEQ*DIM)      // 8,192,000
#define NEL2    (NEL/2)              // 4,096,000 u32

#define GLOG2 (-0.0196090426f)
__device__ __forceinline__ float gpow(float k) { return exp2f(k * GLOG2); }

// ------------------------- global scratch (no alloc) ------------------------
__device__ uint32_t g_Wsh[3 * 32768], g_Wsl[3 * 32768]; // split weights
__device__ uint32_t g_Qh[NEL2], g_Ql[NEL2];
__device__ uint32_t g_Kh[NEL2], g_Kl[NEL2];
__device__ uint32_t g_Vh[NEL2], g_Vl[NEL2];
__device__ uint32_t g_Kwh[NEL2], g_Kwl[NEL2];           // pre-weighted K
__device__ float    g_S[(size_t)BATCH * NG * DIM * DIM];
__device__ uint32_t g_Ph[(size_t)BATCH * NG * 32768], g_Pl[(size_t)BATCH * NG * 32768];

// ------------------------------ helpers -------------------------------------
__device__ __forceinline__ unsigned su32(const void* p) {
    return (unsigned)__cvta_generic_to_shared(p);
}
__device__ __forceinline__ void cpa16(unsigned s, const void* g) {
    asm volatile("cp.async.cg.shared.global [%0], [%1], 16;" :: "r"(s), "l"(g));
}
__device__ __forceinline__ void cp_commit() { asm volatile("cp.async.commit_group;"); }
template<int N> __device__ __forceinline__ void cp_wait() {
    asm volatile("cp.async.wait_group %0;" :: "n"(N));
}
__device__ __forceinline__ void ldm4(uint32_t* r, unsigned addr) {
    asm volatile("ldmatrix.sync.aligned.m8n8.x4.shared.b16 {%0,%1,%2,%3}, [%4];"
        : "=r"(r[0]), "=r"(r[1]), "=r"(r[2]), "=r"(r[3]) : "r"(addr));
}
__device__ __forceinline__ void ldm4t(uint32_t* r, unsigned addr) {
    asm volatile("ldmatrix.sync.aligned.m8n8.x4.trans.shared.b16 {%0,%1,%2,%3}, [%4];"
        : "=r"(r[0]), "=r"(r[1]), "=r"(r[2]), "=r"(r[3]) : "r"(addr));
}
__device__ __forceinline__ void mma16816(float* c, const uint32_t* a, const uint32_t* b) {
    asm volatile(
        "mma.sync.aligned.m16n8k16.row.col.f32.bf16.bf16.f32 "
        "{%0,%1,%2,%3},{%4,%5,%6,%7},{%8,%9},{%0,%1,%2,%3};"
        : "+f"(c[0]), "+f"(c[1]), "+f"(c[2]), "+f"(c[3])
        : "r"(a[0]), "r"(a[1]), "r"(a[2]), "r"(a[3]), "r"(b[0]), "r"(b[1]));
}
__device__ __forceinline__ void split2(float x, float y, uint32_t& h, uint32_t& l) {
    __nv_bfloat162 hb = __floats2bfloat162_rn(x, y);
    float rx = x - __bfloat162float(hb.x);
    float ry = y - __bfloat162float(hb.y);
    __nv_bfloat162 lb = __floats2bfloat162_rn(rx, ry);
    h = *reinterpret_cast<uint32_t*>(&hb);
    l = *reinterpret_cast<uint32_t*>(&lb);
}

// ---------------------------------------------------------------------------
// K0: presplit WEIGHTS only. grid (64,1,3)
// ---------------------------------------------------------------------------
__global__ __launch_bounds__(256) void presplitW_kernel(
    const float* __restrict__ Wq, const float* __restrict__ Wk, const float* __restrict__ Wv)
{
    int which = blockIdx.z;
    const float* s = which == 0 ? Wq : (which == 1 ? Wk : Wv);
    int idx = blockIdx.x * 256 + threadIdx.x;         // 16384 float4 per matrix
    float4 v = ((const float4*)s)[idx];
    uint32_t h0, l0, h1, l1;
    split2(v.x, v.y, h0, l0); split2(v.z, v.w, h1, l1);
    ((uint2*)(g_Wsh + which * 32768))[idx] = make_uint2(h0, h1);
    ((uint2*)(g_Wsl + which * 32768))[idx] = make_uint2(l0, l1);
}

// ---------------------------------------------------------------------------
// K1: QKV projections. 512 threads, 128x256 tile, fp32 A loaded directly and
// split in-kernel (reg-staged); W pre-split via cp.async. grid (250,1,3)
// stage layout (bytes): Ah[128][40h]@0 (10240), Al@10240, Bh[32][264h]@20480
// (16896), Bl@37376. stride 54272, two stages.
// ---------------------------------------------------------------------------
#define PJ_STAGE 54272

__device__ __forceinline__ void pj_wcopy(unsigned sb, int tid, int k0,
                                         const char* Bgh, const char* Bgl)
{
#pragma unroll
    for (int j = 0; j < 4; j++) {
        int c = tid + j * 512;
        int seg = c >> 10, cc = c & 1023;
        int r = cc >> 5, ch = cc & 31;
        const char* gp = (seg ? Bgl : Bgh) + ((size_t)(k0 + r) * 256) * 2 + ch * 16;
        cpa16(sb + 20480u + seg * 16896u + r * 528u + ch * 16u, gp);
    }
}

__global__ __launch_bounds__(512) void proj_mma(
    const float* __restrict__ xq, const float* __restrict__ xk, const float* __restrict__ xv)
{
    extern __shared__ char sm[];
    int which = blockIdx.z;
    const float4* A4 = (const float4*)(which == 0 ? xq : (which == 1 ? xk : xv));
    const char* Bgh = (const char*)(g_Wsh + which * 32768);
    const char* Bgl = (const char*)(g_Wsl + which * 32768);
    uint32_t* Ch = which == 0 ? g_Qh : (which == 1 ? g_Kh : g_Vh);
    uint32_t* Cl = which == 0 ? g_Ql : (which == 1 ? g_Kl : g_Vl);

    int tid = threadIdx.x, lane = tid & 31, wid = tid >> 5;
    int lr = lane & 7, lg = lane >> 3;
    int warp_m = (wid & 1) * 64, warp_n = (wid >> 1) * 32;
    int row0 = blockIdx.x * 128;
    unsigned smB = su32(sm);
    unsigned rowsel = lr + (lg & 1) * 8, colsel = (lg >> 1) * 8;
    unsigned aoff = (unsigned)(warp_m + rowsel) * 80 + colsel * 2;
    unsigned boff = (unsigned)rowsel * 528 + (warp_n + colsel) * 2;

    int r0 = tid >> 3, c0 = tid & 7;         // A chunk: rows r0 and r0+64
    const float4* Ap0 = A4 + (size_t)(row0 + r0) * 64 + c0;
    const float4* Ap1 = A4 + (size_t)(row0 + r0 + 64) * 64 + c0;

    float acc[4][4][4];
#pragma unroll
    for (int i = 0; i < 4; i++)
#pragma unroll
        for (int j = 0; j < 4; j++)
#pragma unroll
            for (int q = 0; q < 4; q++) acc[i][j][q] = 0.f;

    // prologue: A stage 0 into regs, W stage 0 via cp.async
    float4 v0 = Ap0[0], v1 = Ap1[0];
    pj_wcopy(smB, tid, 0, Bgh, Bgl);
    cp_commit();

    for (int it = 0; it < 8; it++) {
        int cur = it & 1;
        float4 n0, n1;
        if (it < 7) {
            n0 = Ap0[(it + 1) * 8];
            n1 = Ap1[(it + 1) * 8];
            pj_wcopy(smB + (1 - cur) * PJ_STAGE, tid, (it + 1) * 32, Bgh, Bgl);
            cp_commit();
        }
        // split current A stage into smem
        {
            char* sbp = sm + cur * PJ_STAGE;
            uint2* pAh = (uint2*)sbp;
            uint2* pAl = (uint2*)(sbp + 10240);
            uint32_t h0, l0, h1, l1;
            split2(v0.x, v0.y, h0, l0); split2(v0.z, v0.w, h1, l1);
            pAh[r0 * 10 + c0] = make_uint2(h0, h1);
            pAl[r0 * 10 + c0] = make_uint2(l0, l1);
            split2(v1.x, v1.y, h0, l0); split2(v1.z, v1.w, h1, l1);
            pAh[(r0 + 64) * 10 + c0] = make_uint2(h0, h1);
            pAl[(r0 + 64) * 10 + c0] = make_uint2(l0, l1);
        }
        if (it < 7) cp_wait<1>(); else cp_wait<0>();
        __syncthreads();

        unsigned sb = smB + cur * PJ_STAGE;
        unsigned aH = sb + aoff, aL = aH + 10240;
        unsigned bH = sb + 20480 + boff, bL = bH + 16896;
#pragma unroll
        for (int ks = 0; ks < 32; ks += 16) {
            uint32_t ah[4][4], al[4][4], bh[2][4], bl[2][4];
#pragma unroll
            for (int mt = 0; mt < 4; mt++) {
                unsigned o = (unsigned)(mt * 16) * 80 + ks * 2;
                ldm4(ah[mt], aH + o); ldm4(al[mt], aL + o);
            }
#pragma unroll
            for (int np = 0; np < 2; np++) {
                unsigned o = (unsigned)ks * 528 + np * 32;
                ldm4t(bh[np], bH + o); ldm4t(bl[np], bL + o);
            }
#pragma unroll
            for (int mt = 0; mt < 4; mt++)
#pragma unroll
                for (int nt = 0; nt < 4; nt++) {
                    const uint32_t* bhp = &bh[nt >> 1][(nt & 1) * 2];
                    const uint32_t* blp = &bl[nt >> 1][(nt & 1) * 2];
                    mma16816(acc[mt][nt], ah[mt], bhp);
                    mma16816(acc[mt][nt], ah[mt], blp);
                    mma16816(acc[mt][nt], al[mt], bhp);
                }
        }
        __syncthreads();
        v0 = n0; v1 = n1;
    }

    int g4 = lane >> 2, t4 = (lane & 3) * 2;
    bool isK = (which == 1);
#pragma unroll
    for (int mt = 0; mt < 4; mt++)
#pragma unroll
        for (int nt = 0; nt < 4; nt++) {
            int r = row0 + warp_m + mt * 16 + g4;
            int c = warp_n + nt * 8 + t4;
#pragma unroll
            for (int h2 = 0; h2 < 2; h2++) {
                int rr = r + h2 * 8;
                float a0 = acc[mt][nt][h2 * 2], a1 = acc[mt][nt][h2 * 2 + 1];
                uint32_t hh, ll;
                split2(a0, a1, hh, ll);
                size_t o = ((size_t)rr * 256 + c) >> 1;
                Ch[o] = hh; Cl[o] = ll;
                if (isK) {
                    int tok = rr % SEQ;
                    float w = gpow(6.f * (float)(15 - ((tok / 5) & 15)));
                    split2(w * a0, w * a1, hh, ll);
                    g_Kwh[o] = hh; g_Kwl[o] = ll;
                }
            }
        }
}

// ---------------------------------------------------------------------------
// K2: group states S_g = Kw^T V, pure-copy cp.async pipelined. grid (2,2,400)
// ---------------------------------------------------------------------------
__device__ __forceinline__ void gs_copy(unsigned sb, int tid, size_t bTok, int t0, int d0, int e0)
{
#pragma unroll
    for (int j = 0; j < 4; j++) {
        int c = tid + j * 256;
        int seg = c >> 8, cc = c & 255;
        int r = cc >> 4, ch = cc & 15;
        const char* base = seg == 0 ? (const char*)g_Kwh : seg == 1 ? (const char*)g_Kwl
                         : seg == 2 ? (const char*)g_Vh : (const char*)g_Vl;
        size_t gidx = ((bTok + t0 + r) * 256 + ((seg < 2) ? d0 : e0)) * 2 + ch * 16;
        cpa16(sb + seg * 4352u + r * 272u + ch * 16u, base + gidx);
    }
}

__global__ __launch_bounds__(256) void groupstate_mma()
{
    __shared__ __align__(16) char gsm[2 * 17408];
    int bz = blockIdx.z;
    int b = bz / NG, g = bz % NG;
    int d0 = blockIdx.y * 128, e0 = blockIdx.x * 128;
    size_t bTok = (size_t)b * SEQ + (size_t)g * TOKG;

    int tid = threadIdx.x, lane = tid & 31, wid = tid >> 5;
    int lr = lane & 7, lg = lane >> 3;
    int warp_m = (wid & 1) * 64, warp_n = (wid >> 1) * 32;
    unsigned smB = su32(gsm);

    unsigned aoff = ((unsigned)(lr + (lg >> 1) * 8) * 136 + warp_m + (lg & 1) * 8) * 2;
    unsigned boff = ((unsigned)(lr + (lg & 1) * 8) * 136 + warp_n + (lg >> 1) * 8) * 2;

    float acc[4][4][4];
#pragma unroll
    for (int i = 0; i < 4; i++)
#pragma unroll
        for (int j = 0; j < 4; j++)
#pragma unroll
            for (int q = 0; q < 4; q++) acc[i][j][q] = 0.f;

    gs_copy(smB, tid, bTok, 0, d0, e0);
    cp_commit();

    for (int it = 0; it < 5; it++) {
        int cur = it & 1;
        if (it < 4) {
            gs_copy(smB + (1 - cur) * 17408, tid, bTok, (it + 1) * 16, d0, e0);
            cp_commit();
            cp_wait<1>();
        } else cp_wait<0>();
        __syncthreads();

        unsigned sb = smB + cur * 17408;
        uint32_t ah[4][4], al[4][4], bh[2][4], bl[2][4];
#pragma unroll
        for (int mt = 0; mt < 4; mt++) {
            unsigned o = (unsigned)(mt * 16) * 2;
            ldm4t(ah[mt], sb + aoff + o); ldm4t(al[mt], sb + 4352 + aoff + o);
        }
#pragma unroll
        for (int np = 0; np < 2; np++) {
            unsigned o = (unsigned)(np * 16) * 2;
            ldm4t(bh[np], sb + 8704 + boff + o); ldm4t(bl[np], sb + 13056 + boff + o);
        }
#pragma unroll
        for (int mt = 0; mt < 4; mt++)
#pragma unroll
            for (int nt = 0; nt < 4; nt++) {
                const uint32_t* bhp = &bh[nt >> 1][(nt & 1) * 2];
                const uint32_t* blp = &bl[nt >> 1][(nt & 1) * 2];
                mma16816(acc[mt][nt], ah[mt], bhp);
                mma16816(acc[mt][nt], ah[mt], blp);
                mma16816(acc[mt][nt], al[mt], bhp);
            }
        __syncthreads();
    }

    int g4 = lane >> 2, t4 = (lane & 3) * 2;
    float* S = g_S + (size_t)bz * DIM * DIM;
#pragma unroll
    for (int mt = 0; mt < 4; mt++)
#pragma unroll
        for (int nt = 0; nt < 4; nt++) {
            int r = d0 + warp_m + mt * 16 + g4;
            int c = e0 + warp_n + nt * 8 + t4;
            *(float2*)&S[(size_t)r * 256 + c] = make_float2(acc[mt][nt][0], acc[mt][nt][1]);
            *(float2*)&S[(size_t)(r + 8) * 256 + c] = make_float2(acc[mt][nt][2], acc[mt][nt][3]);
        }
}

// ---------------------------------------------------------------------------
// K3: exclusive group prefix; float4/thread, 2-deep prefetch. grid 512.
// ---------------------------------------------------------------------------
__global__ __launch_bounds__(256) void prefix_kernel()
{
    int idx = blockIdx.x * 256 + threadIdx.x;   // 131072 total
    int b = idx >> 14, de4 = idx & 16383;
    size_t sbase = (size_t)b * NG * 65536 + (size_t)de4 * 4;
    size_t pbase = (size_t)b * NG * 32768 + (size_t)de4 * 2;
    const float g6 = gpow(6.f), g6C = gpow(96.f);

    *(uint2*)&g_Ph[pbase] = make_uint2(0u, 0u);
    *(uint2*)&g_Pl[pbase] = make_uint2(0u, 0u);

    float4 p = make_float4(0.f, 0.f, 0.f, 0.f);
    float4 sA = *(const float4*)&g_S[sbase];               // S[0]
    float4 sB = *(const float4*)&g_S[sbase + 65536];       // S[1]
    for (int g = 1; g < NG; g++) {
        float4 sC = sB;
        if (g <= NG - 3) sC = *(const float4*)&g_S[sbase + (size_t)(g + 1) * 65536];
        p.x = g6 * sA.x + g6C * p.x;
        p.y = g6 * sA.y + g6C * p.y;
        p.z = g6 * sA.z + g6C * p.z;
        p.w = g6 * sA.w + g6C * p.w;
        uint32_t h0, l0, h1, l1;
        split2(p.x, p.y, h0, l0); split2(p.z, p.w, h1, l1);
        *(uint2*)&g_Ph[pbase + (size_t)g * 32768] = make_uint2(h0, h1);
        *(uint2*)&g_Pl[pbase + (size_t)g * 32768] = make_uint2(l0, l1);
        sA = sB; sB = sC;
    }
}

// ---------------------------------------------------------------------------
// K5: per-group local term (2 MMAs), cp.async feeds. grid (50, 8), dyn smem.
// ---------------------------------------------------------------------------
#define L2_SMEM 98560

__device__ __forceinline__ void l2_qkcopy(unsigned sb, int tid, size_t tokBase, int k0)
{
#pragma unroll
    for (int j = 0; j < 5; j++) {
        int c = tid + j * 256;
        int seg = c / 320, cc = c - seg * 320;
        int r = cc >> 2, ch = cc & 3;
        const char* base = seg == 0 ? (const char*)g_Qh : seg == 1 ? (const char*)g_Ql
                         : seg == 2 ? (const char*)g_Kh : (const char*)g_Kl;
        cpa16(sb + seg * 6400u + r * 80u + ch * 16u,
              base + ((tokBase + r) * 256 + k0) * 2 + ch * 16);
    }
}
__device__ __forceinline__ void l2_vcopy(unsigned smB, int tid, size_t tokBase, int e0)
{
#pragma unroll
    for (int j = 0; j < 10; j++) {
        int c = tid + j * 256;
        int seg = c / 1280, cc = c - seg * 1280;
        int r = cc >> 4, ch = cc & 15;
        const char* base = seg ? (const char*)g_Vl : (const char*)g_Vh;
        cpa16(smB + 55040u + seg * 21760u + r * 272u + ch * 16u,
              base + ((tokBase + r) * 256 + e0) * 2 + ch * 16);
    }
}

__global__ __launch_bounds__(256) void local2_kernel(float* __restrict__ out)
{
    extern __shared__ char sm[];
    float* sS = (float*)sm;                       // [80][84]
    uint32_t* sMh = (uint32_t*)(sm + 26880);      // [80][44]
    uint32_t* sMl = (uint32_t*)(sm + 40960);

    int g = blockIdx.x, b = blockIdx.y;
    int tid = threadIdx.x, lane = tid & 31, wid = tid >> 5;
    int lr = lane & 7, lg = lane >> 3;
    int g4 = lane >> 2, t4 = (lane & 3) * 2;
    unsigned smB = su32(sm);

    const size_t tokBase = (size_t)b * SEQ + (size_t)g * TOKG;

    unsigned rowsel = lr + (lg & 1) * 8;
    unsigned colsel = (lg >> 1) * 8;

    float acc1[4][2][4];
#pragma unroll
    for (int i = 0; i < 4; i++)
#pragma unroll
        for (int j = 0; j < 2; j++)
#pragma unroll
            for (int q = 0; q < 4; q++) acc1[i][j][q] = 0.f;

    l2_qkcopy(smB + 26880, tid, tokBase, 0);
    cp_commit();

    for (int it = 0; it < 8; it++) {
        int cur = it & 1;
        if (it < 7) {
            l2_qkcopy(smB + 26880 + (1 - cur) * 25600, tid, tokBase, (it + 1) * 32);
            cp_commit();
            cp_wait<1>();
        } else cp_wait<0>();
        __syncthreads();

        unsigned sb = smB + 26880 + cur * 25600;
        unsigned qH = sb + rowsel * 80 + colsel * 2, qL = qH + 6400;
        unsigned kH = qH + 12800, kL = qH + 19200;
#pragma unroll
        for (int ks = 0; ks < 32; ks += 16) {
            int li = 0;
            for (int tile = wid; tile < 25; tile += 8, li++) {
                int mt = tile / 5, nt = tile - mt * 5;
                unsigned ao = (unsigned)(mt * 16) * 80 + ks * 2;
                unsigned bo = (unsigned)(nt * 16) * 80 + ks * 2;
                uint32_t ah[4], al[4], rh[4], rl[4];
                ldm4(ah, qH + ao); ldm4(al, qL + ao);
                ldm4(rh, kH + bo); ldm4(rl, kL + bo);
                uint32_t bh0[2] = {rh[0], rh[2]}, bh1[2] = {rh[1], rh[3]};
                uint32_t bl0[2] = {rl[0], rl[2]}, bl1[2] = {rl[1], rl[3]};
                mma16816(acc1[li][0], ah, bh0);
                mma16816(acc1[li][0], ah, bl0);
                mma16816(acc1[li][0], al, bh0);
                mma16816(acc1[li][1], ah, bh1);
                mma16816(acc1[li][1], ah, bl1);
                mma16816(acc1[li][1], al, bh1);
            }
        }
        __syncthreads();
    }

    {
        int li = 0;
        for (int tile = wid; tile < 25; tile += 8, li++) {
            int mt = tile / 5, nt = tile - mt * 5;
#pragma unroll
            for (int sub = 0; sub < 2; sub++) {
                int c = nt * 16 + sub * 8 + t4;
                int r = mt * 16 + g4;
                sS[r * 84 + c]     = acc1[li][sub][0];
                sS[r * 84 + c + 1] = acc1[li][sub][1];
                sS[(r + 8) * 84 + c]     = acc1[li][sub][2];
                sS[(r + 8) * 84 + c + 1] = acc1[li][sub][3];
            }
        }
    }
    __syncthreads();

    l2_vcopy(smB, tid, tokBase, 0);
    cp_commit();

    for (int pz = tid; pz < 3200; pz += 256) {
        int t = pz / 40, sp = pz - t * 40;
        int i = t / 5, o = t - i * 5;
        float mv[2];
#pragma unroll
        for (int u = 0; u < 2; u++) {
            int s = sp * 2 + u;
            int j = s / 5, p = s - j * 5;
            float v = 0.f;
            if (j == i && p <= o) v += gpow((float)(p - o)) * sS[t * 84 + s];
            if (i < 15 && j <= i) v += gpow((float)(6 * (i + 1 - j))) * sS[(t + 5) * 84 + s];
            mv[u] = v;
        }
        uint32_t h, l;
        split2(mv[0], mv[1], h, l);
        sMh[t * 44 + sp] = h;
        sMl[t * 44 + sp] = l;
    }

    unsigned mH = smB + 26880 + rowsel * 176 + colsel * 2, mL = mH + 14080;
    unsigned vH = smB + 55040 + rowsel * 272 + wid * 32 + colsel * 2, vL = vH + 21760;

#pragma unroll
    for (int pass = 0; pass < 2; pass++) {
        int e0 = pass * 128;
        cp_wait<0>();
        __syncthreads();

        float acc2[5][2][4];
#pragma unroll
        for (int i = 0; i < 5; i++)
#pragma unroll
            for (int j = 0; j < 2; j++)
#pragma unroll
                for (int q = 0; q < 4; q++) acc2[i][j][q] = 0.f;

#pragma unroll
        for (int ks = 0; ks < 80; ks += 16) {
            uint32_t bh[4], bl[4];
            unsigned vo = (unsigned)ks * 272;
            ldm4t(bh, vH + vo); ldm4t(bl, vL + vo);
#pragma unroll
            for (int mt = 0; mt < 5; mt++) {
                unsigned ao = (unsigned)(mt * 16) * 176 + ks * 2;
                uint32_t ah[4], al[4];
                ldm4(ah, mH + ao); ldm4(al, mL + ao);
                mma16816(acc2[mt][0], ah, &bh[0]);
                mma16816(acc2[mt][0], ah, &bl[0]);
                mma16816(acc2[mt][0], al, &bh[0]);
                mma16816(acc2[mt][1], ah, &bh[2]);
                mma16816(acc2[mt][1], ah, &bl[2]);
                mma16816(acc2[mt][1], al, &bh[2]);
            }
        }
        __syncthreads();
        if (pass == 0) {
            l2_vcopy(smB, tid, tokBase, 128);
            cp_commit();
        }

#pragma unroll
        for (int mt = 0; mt < 5; mt++)
#pragma unroll
            for (int nt = 0; nt < 2; nt++) {
                int r = mt * 16 + g4;
                int c = e0 + wid * 16 + nt * 8 + t4;
                float* O0 = out + (tokBase + r) * 256 + c;
                float* O1 = out + (tokBase + r + 8) * 256 + c;
                *(float2*)O0 = make_float2(acc2[mt][nt][0], acc2[mt][nt][1]);
                *(float2*)O1 = make_float2(acc2[mt][nt][2], acc2[mt][nt][3]);
            }
    }
}

// ---------------------------------------------------------------------------
// K4: global cross: out += scale * Q_group @ P_g. cp.async pipelined. grid (2,400)
// ---------------------------------------------------------------------------
#define CGX_SMEM 60416

__device__ __forceinline__ void cg_copy(unsigned sb, int tid, size_t qTok, size_t pBase, int k0, int e0)
{
#pragma unroll
    for (int j = 0; j < 7; j++) {
        int c = tid + j * 256;
        if (c >= 1664) break;
        if (c < 640) {
            int seg = c / 320, cc = c - seg * 320;
            int r = cc >> 2, ch = cc & 3;
            const char* base = seg ? (const char*)g_Ql : (const char*)g_Qh;
            cpa16(sb + seg * 6400u + r * 80u + ch * 16u,
                  base + ((qTok + r) * 256 + k0) * 2 + ch * 16);
        } else {
            int cc = c - 640;
            int seg = cc >> 9, c2 = cc & 511;
            int r = c2 >> 4, ch = c2 & 15;
            const char* base = seg ? (const char*)g_Pl : (const char*)g_Ph;
            cpa16(sb + 12800u + seg * 8704u + r * 272u + ch * 16u,
                  base + (pBase + (size_t)(k0 + r) * 256 + e0) * 2 + ch * 16);
        }
    }
}

__global__ __launch_bounds__(256) void crossglobal_mma(float* __restrict__ out)
{
    extern __shared__ char sm[];
    int bz = blockIdx.y;
    int b = bz / NG, g = bz % NG;
    int e0 = blockIdx.x * 128;
    size_t qTok = (size_t)b * SEQ + (size_t)g * TOKG;
    size_t pBase = (size_t)bz * 65536;

    int tid = threadIdx.x, lane = tid & 31, wid = tid >> 5;
    int lr = lane & 7, lg = lane >> 3;
    int warp_n = wid * 16;
    unsigned smB = su32(sm);

    unsigned rowsel = lr + (lg & 1) * 8, colsel = (lg >> 1) * 8;
    unsigned aoff = rowsel * 80 + colsel * 2;
    unsigned boff = rowsel * 272 + (warp_n + colsel) * 2;

    float acc[5][2][4];
#pragma unroll
    for (int i = 0; i < 5; i++)
#pragma unroll
        for (int j = 0; j < 2; j++)
#pragma unroll
            for (int q = 0; q < 4; q++) acc[i][j][q] = 0.f;

    cg_copy(smB, tid, qTok, pBase, 0, e0);
    cp_commit();

    for (int it = 0; it < 8; it++) {
        int cur = it & 1;
        if (it < 7) {
            cg_copy(smB + (1 - cur) * 30208, tid, qTok, pBase, (it + 1) * 32, e0);
            cp_commit();
            cp_wait<1>();
        } else cp_wait<0>();
        __syncthreads();

        unsigned sb = smB + cur * 30208;
        unsigned aH = sb + aoff, aL = aH + 6400;
        unsigned bH = sb + 12800 + boff, bL = bH + 8704;
#pragma unroll
        for (int ks = 0; ks < 32; ks += 16) {
            uint32_t ah[5][4], al[5][4], bh[4], bl[4];
#pragma unroll
            for (int mt = 0; mt < 5; mt++) {
                unsigned o = (unsigned)(mt * 16) * 80 + ks * 2;
                ldm4(ah[mt], aH + o); ldm4(al[mt], aL + o);
            }
            {
                unsigned o = (unsigned)ks * 272;
                ldm4t(bh, bH + o); ldm4t(bl, bL + o);
            }
#pragma unroll
            for (int mt = 0; mt < 5; mt++)
#pragma unroll
                for (int nt = 0; nt < 2; nt++) {
                    const uint32_t* bhp = &bh[nt * 2];
                    const uint32_t* blp = &bl[nt * 2];
                    mma16816(acc[mt][nt], ah[mt], bhp);
                    mma16816(acc[mt][nt], ah[mt], blp);
                    mma16816(acc[mt][nt], al[mt], bhp);
                }
        }
        __syncthreads();
    }

    int g4 = lane >> 2, t4 = (lane & 3) * 2;
#pragma unroll
    for (int mt = 0; mt < 5; mt++)
#pragma unroll
        for (int nt = 0; nt < 2; nt++) {
            int c = e0 + warp_n + nt * 8 + t4;
            int r1 = mt * 16 + g4;
            int tok1 = g * TOKG + r1 - 5;
            if (tok1 >= 0) {
                float s = gpow((float)(6 * (r1 / 5)));
                float2* p = (float2*)&out[((size_t)b * SEQ + tok1) * 256 + c];
                float2 o = *p;
                o.x += s * acc[mt][nt][0]; o.y += s * acc[mt][nt][1];
                *p = o;
            }
            int r2 = r1 + 8;
            int tok2 = g * TOKG + r2 - 5;
            if (tok2 >= 0) {
                float s = gpow((float)(6 * (r2 / 5)));
                float2* p = (float2*)&out[((size_t)b * SEQ + tok2) * 256 + c];
                float2 o = *p;
                o.x += s * acc[mt][nt][2]; o.y += s * acc[mt][nt][3];
                *p = o;
            }
        }
}

// ---------------------------------------------------------------------------
extern "C" void kernel_launch(void* const* d_in, const int* in_sizes, int n_in,
                              void* d_out, int out_size)
{
    const float* xq = (const float*)d_in[0];
    const float* xk = (const float*)d_in[1];
    const float* xv = (const float*)d_in[2];
    const float* Wq = (const float*)d_in[3];
    const float* Wk = (const float*)d_in[4];
    const float* Wv = (const float*)d_in[5];
    float* out = (float*)d_out;

    static int attrs_set = 0;
    if (!attrs_set) {
        cudaFuncSetAttribute(proj_mma, cudaFuncAttributeMaxDynamicSharedMemorySize, 2 * PJ_STAGE);
        cudaFuncSetAttribute(local2_kernel, cudaFuncAttributeMaxDynamicSharedMemorySize, L2_SMEM);
        cudaFuncSetAttribute(crossglobal_mma, cudaFuncAttributeMaxDynamicSharedMemorySize, CGX_SMEM);
        attrs_set = 1;
    }

    presplitW_kernel<<<dim3(64, 1, 3), 256>>>(Wq, Wk, Wv);
    proj_mma<<<dim3(250, 1, 3), 512, 2 * PJ_STAGE>>>(xq, xk, xv);
    groupstate_mma<<<dim3(2, 2, BATCH * NG), 256>>>();
    prefix_kernel<<<dim3(512), 256>>>();
    local2_kernel<<<dim3(NG, BATCH), 256, L2_SMEM>>>(out);
    crossglobal_mma<<<dim3(2, BATCH * NG), 256, CGX_SMEM>>>(out);
}

// round 11
// speedup vs baseline: 2.6064x; 1.0993x over previous
#include <cuda_runtime.h>
#include <cuda_bf16.h>
#include <stdint.h>
#include <math.h>

#define BATCH   8
#define SEQ     4000
#define DIM     256
#define BCH     5
#define NCHUNK  800
#define CG      16
#define NG      50
#define TOKG    (CG*BCH)

#define NEL     (BATCH*SEQ*DIM)      // 8,192,000
#define NEL2    (NEL/2)              // 4,096,000 u32

#define GLOG2 (-0.0196090426f)
__device__ __forceinline__ float gpow(float k) { return exp2f(k * GLOG2); }

// ------------------------- global scratch (no alloc) ------------------------
__device__ uint32_t g_Wsh[3 * 32768], g_Wsl[3 * 32768]; // split weights
__device__ uint32_t g_Qh[NEL2], g_Ql[NEL2];
__device__ uint32_t g_Vh[NEL2], g_Vl[NEL2];
__device__ uint32_t g_Kwh[NEL2], g_Kwl[NEL2];           // pre-weighted K (the ONLY K kept)
__device__ float    g_S[(size_t)BATCH * NG * DIM * DIM];
__device__ uint32_t g_Ph[(size_t)BATCH * NG * 32768], g_Pl[(size_t)BATCH * NG * 32768];

// ------------------------------ helpers -------------------------------------
__device__ __forceinline__ unsigned su32(const void* p) {
    return (unsigned)__cvta_generic_to_shared(p);
}
__device__ __forceinline__ void cpa16(unsigned s, const void* g) {
    asm volatile("cp.async.cg.shared.global [%0], [%1], 16;" :: "r"(s), "l"(g));
}
__device__ __forceinline__ void cp_commit() { asm volatile("cp.async.commit_group;"); }
template<int N> __device__ __forceinline__ void cp_wait() {
    asm volatile("cp.async.wait_group %0;" :: "n"(N));
}
__device__ __forceinline__ void ldm4(uint32_t* r, unsigned addr) {
    asm volatile("ldmatrix.sync.aligned.m8n8.x4.shared.b16 {%0,%1,%2,%3}, [%4];"
        : "=r"(r[0]), "=r"(r[1]), "=r"(r[2]), "=r"(r[3]) : "r"(addr));
}
__device__ __forceinline__ void ldm4t(uint32_t* r, unsigned addr) {
    asm volatile("ldmatrix.sync.aligned.m8n8.x4.trans.shared.b16 {%0,%1,%2,%3}, [%4];"
        : "=r"(r[0]), "=r"(r[1]), "=r"(r[2]), "=r"(r[3]) : "r"(addr));
}
__device__ __forceinline__ void mma16816(float* c, const uint32_t* a, const uint32_t* b) {
    asm volatile(
        "mma.sync.aligned.m16n8k16.row.col.f32.bf16.bf16.f32 "
        "{%0,%1,%2,%3},{%4,%5,%6,%7},{%8,%9},{%0,%1,%2,%3};"
        : "+f"(c[0]), "+f"(c[1]), "+f"(c[2]), "+f"(c[3])
        : "r"(a[0]), "r"(a[1]), "r"(a[2]), "r"(a[3]), "r"(b[0]), "r"(b[1]));
}
__device__ __forceinline__ void split2(float x, float y, uint32_t& h, uint32_t& l) {
    __nv_bfloat162 hb = __floats2bfloat162_rn(x, y);
    float rx = x - __bfloat162float(hb.x);
    float ry = y - __bfloat162float(hb.y);
    __nv_bfloat162 lb = __floats2bfloat162_rn(rx, ry);
    h = *reinterpret_cast<uint32_t*>(&hb);
    l = *reinterpret_cast<uint32_t*>(&lb);
}

// ---------------------------------------------------------------------------
// K0: presplit WEIGHTS only. grid (64,1,3)
// ---------------------------------------------------------------------------
__global__ __launch_bounds__(256) void presplitW_kernel(
    const float* __restrict__ Wq, const float* __restrict__ Wk, const float* __restrict__ Wv)
{
    int which = blockIdx.z;
    const float* s = which == 0 ? Wq : (which == 1 ? Wk : Wv);
    int idx = blockIdx.x * 256 + threadIdx.x;
    float4 v = ((const float4*)s)[idx];
    uint32_t h0, l0, h1, l1;
    split2(v.x, v.y, h0, l0); split2(v.z, v.w, h1, l1);
    ((uint2*)(g_Wsh + which * 32768))[idx] = make_uint2(h0, h1);
    ((uint2*)(g_Wsl + which * 32768))[idx] = make_uint2(l0, l1);
}

// ---------------------------------------------------------------------------
// K1: QKV projections. 512 threads, 128x256 tile. grid (250,1,3)
// K path stores ONLY the pre-weighted Kw (plain K eliminated).
// ---------------------------------------------------------------------------
#define PJ_STAGE 54272

__device__ __forceinline__ void pj_wcopy(unsigned sb, int tid, int k0,
                                         const char* Bgh, const char* Bgl)
{
#pragma unroll
    for (int j = 0; j < 4; j++) {
        int c = tid + j * 512;
        int seg = c >> 10, cc = c & 1023;
        int r = cc >> 5, ch = cc & 31;
        const char* gp = (seg ? Bgl : Bgh) + ((size_t)(k0 + r) * 256) * 2 + ch * 16;
        cpa16(sb + 20480u + seg * 16896u + r * 528u + ch * 16u, gp);
    }
}

__global__ __launch_bounds__(512) void proj_mma(
    const float* __restrict__ xq, const float* __restrict__ xk, const float* __restrict__ xv)
{
    extern __shared__ char sm[];
    int which = blockIdx.z;
    const float4* A4 = (const float4*)(which == 0 ? xq : (which == 1 ? xk : xv));
    const char* Bgh = (const char*)(g_Wsh + which * 32768);
    const char* Bgl = (const char*)(g_Wsl + which * 32768);
    uint32_t* Ch = which == 0 ? g_Qh : g_Vh;   // unused when which==1
    uint32_t* Cl = which == 0 ? g_Ql : g_Vl;

    int tid = threadIdx.x, lane = tid & 31, wid = tid >> 5;
    int lr = lane & 7, lg = lane >> 3;
    int warp_m = (wid & 1) * 64, warp_n = (wid >> 1) * 32;
    int row0 = blockIdx.x * 128;
    unsigned smB = su32(sm);
    unsigned rowsel = lr + (lg & 1) * 8, colsel = (lg >> 1) * 8;
    unsigned aoff = (unsigned)(warp_m + rowsel) * 80 + colsel * 2;
    unsigned boff = (unsigned)rowsel * 528 + (warp_n + colsel) * 2;

    int r0 = tid >> 3, c0 = tid & 7;
    const float4* Ap0 = A4 + (size_t)(row0 + r0) * 64 + c0;
    const float4* Ap1 = A4 + (size_t)(row0 + r0 + 64) * 64 + c0;

    float acc[4][4][4];
#pragma unroll
    for (int i = 0; i < 4; i++)
#pragma unroll
        for (int j = 0; j < 4; j++)
#pragma unroll
            for (int q = 0; q < 4; q++) acc[i][j][q] = 0.f;

    float4 v0 = Ap0[0], v1 = Ap1[0];
    pj_wcopy(smB, tid, 0, Bgh, Bgl);
    cp_commit();

    for (int it = 0; it < 8; it++) {
        int cur = it & 1;
        float4 n0, n1;
        if (it < 7) {
            n0 = Ap0[(it + 1) * 8];
            n1 = Ap1[(it + 1) * 8];
            pj_wcopy(smB + (1 - cur) * PJ_STAGE, tid, (it + 1) * 32, Bgh, Bgl);
            cp_commit();
        }
        {
            char* sbp = sm + cur * PJ_STAGE;
            uint2* pAh = (uint2*)sbp;
            uint2* pAl = (uint2*)(sbp + 10240);
            uint32_t h0, l0, h1, l1;
            split2(v0.x, v0.y, h0, l0); split2(v0.z, v0.w, h1, l1);
            pAh[r0 * 10 + c0] = make_uint2(h0, h1);
            pAl[r0 * 10 + c0] = make_uint2(l0, l1);
            split2(v1.x, v1.y, h0, l0); split2(v1.z, v1.w, h1, l1);
            pAh[(r0 + 64) * 10 + c0] = make_uint2(h0, h1);
            pAl[(r0 + 64) * 10 + c0] = make_uint2(l0, l1);
        }
        if (it < 7) cp_wait<1>(); else cp_wait<0>();
        __syncthreads();

        unsigned sb = smB + cur * PJ_STAGE;
        unsigned aH = sb + aoff, aL = aH + 10240;
        unsigned bH = sb + 20480 + boff, bL = bH + 16896;
#pragma unroll
        for (int ks = 0; ks < 32; ks += 16) {
            uint32_t ah[4][4], al[4][4], bh[2][4], bl[2][4];
#pragma unroll
            for (int mt = 0; mt < 4; mt++) {
                unsigned o = (unsigned)(mt * 16) * 80 + ks * 2;
                ldm4(ah[mt], aH + o); ldm4(al[mt], aL + o);
            }
#pragma unroll
            for (int np = 0; np < 2; np++) {
                unsigned o = (unsigned)ks * 528 + np * 32;
                ldm4t(bh[np], bH + o); ldm4t(bl[np], bL + o);
            }
#pragma unroll
            for (int mt = 0; mt < 4; mt++)
#pragma unroll
                for (int nt = 0; nt < 4; nt++) {
                    const uint32_t* bhp = &bh[nt >> 1][(nt & 1) * 2];
                    const uint32_t* blp = &bl[nt >> 1][(nt & 1) * 2];
                    mma16816(acc[mt][nt], ah[mt], bhp);
                    mma16816(acc[mt][nt], ah[mt], blp);
                    mma16816(acc[mt][nt], al[mt], bhp);
                }
        }
        __syncthreads();
        v0 = n0; v1 = n1;
    }

    int g4 = lane >> 2, t4 = (lane & 3) * 2;
    bool isK = (which == 1);
#pragma unroll
    for (int mt = 0; mt < 4; mt++)
#pragma unroll
        for (int nt = 0; nt < 4; nt++) {
            int r = row0 + warp_m + mt * 16 + g4;
            int c = warp_n + nt * 8 + t4;
#pragma unroll
            for (int h2 = 0; h2 < 2; h2++) {
                int rr = r + h2 * 8;
                float a0 = acc[mt][nt][h2 * 2], a1 = acc[mt][nt][h2 * 2 + 1];
                uint32_t hh, ll;
                size_t o = ((size_t)rr * 256 + c) >> 1;
                if (isK) {
                    int tok = rr % SEQ;
                    float w = gpow(6.f * (float)(15 - ((tok / 5) & 15)));
                    split2(w * a0, w * a1, hh, ll);
                    g_Kwh[o] = hh; g_Kwl[o] = ll;
                } else {
                    split2(a0, a1, hh, ll);
                    Ch[o] = hh; Cl[o] = ll;
                }
            }
        }
}

// ---------------------------------------------------------------------------
// K2: group states S_g = Kw^T V, pure-copy cp.async pipelined. grid (2,2,400)
// ---------------------------------------------------------------------------
__device__ __forceinline__ void gs_copy(unsigned sb, int tid, size_t bTok, int t0, int d0, int e0)
{
#pragma unroll
    for (int j = 0; j < 4; j++) {
        int c = tid + j * 256;
        int seg = c >> 8, cc = c & 255;
        int r = cc >> 4, ch = cc & 15;
        const char* base = seg == 0 ? (const char*)g_Kwh : seg == 1 ? (const char*)g_Kwl
                         : seg == 2 ? (const char*)g_Vh : (const char*)g_Vl;
        size_t gidx = ((bTok + t0 + r) * 256 + ((seg < 2) ? d0 : e0)) * 2 + ch * 16;
        cpa16(sb + seg * 4352u + r * 272u + ch * 16u, base + gidx);
    }
}

__global__ __launch_bounds__(256) void groupstate_mma()
{
    __shared__ __align__(16) char gsm[2 * 17408];
    int bz = blockIdx.z;
    int b = bz / NG, g = bz % NG;
    int d0 = blockIdx.y * 128, e0 = blockIdx.x * 128;
    size_t bTok = (size_t)b * SEQ + (size_t)g * TOKG;

    int tid = threadIdx.x, lane = tid & 31, wid = tid >> 5;
    int lr = lane & 7, lg = lane >> 3;
    int warp_m = (wid & 1) * 64, warp_n = (wid >> 1) * 32;
    unsigned smB = su32(gsm);

    unsigned aoff = ((unsigned)(lr + (lg >> 1) * 8) * 136 + warp_m + (lg & 1) * 8) * 2;
    unsigned boff = ((unsigned)(lr + (lg & 1) * 8) * 136 + warp_n + (lg >> 1) * 8) * 2;

    float acc[4][4][4];
#pragma unroll
    for (int i = 0; i < 4; i++)
#pragma unroll
        for (int j = 0; j < 4; j++)
#pragma unroll
            for (int q = 0; q < 4; q++) acc[i][j][q] = 0.f;

    gs_copy(smB, tid, bTok, 0, d0, e0);
    cp_commit();

    for (int it = 0; it < 5; it++) {
        int cur = it & 1;
        if (it < 4) {
            gs_copy(smB + (1 - cur) * 17408, tid, bTok, (it + 1) * 16, d0, e0);
            cp_commit();
            cp_wait<1>();
        } else cp_wait<0>();
        __syncthreads();

        unsigned sb = smB + cur * 17408;
        uint32_t ah[4][4], al[4][4], bh[2][4], bl[2][4];
#pragma unroll
        for (int mt = 0; mt < 4; mt++) {
            unsigned o = (unsigned)(mt * 16) * 2;
            ldm4t(ah[mt], sb + aoff + o); ldm4t(al[mt], sb + 4352 + aoff + o);
        }
#pragma unroll
        for (int np = 0; np < 2; np++) {
            unsigned o = (unsigned)(np * 16) * 2;
            ldm4t(bh[np], sb + 8704 + boff + o); ldm4t(bl[np], sb + 13056 + boff + o);
        }
#pragma unroll
        for (int mt = 0; mt < 4; mt++)
#pragma unroll
            for (int nt = 0; nt < 4; nt++) {
                const uint32_t* bhp = &bh[nt >> 1][(nt & 1) * 2];
                const uint32_t* blp = &bl[nt >> 1][(nt & 1) * 2];
                mma16816(acc[mt][nt], ah[mt], bhp);
                mma16816(acc[mt][nt], ah[mt], blp);
                mma16816(acc[mt][nt], al[mt], bhp);
            }
        __syncthreads();
    }

    int g4 = lane >> 2, t4 = (lane & 3) * 2;
    float* S = g_S + (size_t)bz * DIM * DIM;
#pragma unroll
    for (int mt = 0; mt < 4; mt++)
#pragma unroll
        for (int nt = 0; nt < 4; nt++) {
            int r = d0 + warp_m + mt * 16 + g4;
            int c = e0 + warp_n + nt * 8 + t4;
            *(float2*)&S[(size_t)r * 256 + c] = make_float2(acc[mt][nt][0], acc[mt][nt][1]);
            *(float2*)&S[(size_t)(r + 8) * 256 + c] = make_float2(acc[mt][nt][2], acc[mt][nt][3]);
        }
}

// ---------------------------------------------------------------------------
// K3: exclusive group prefix. 2 floats/thread, 262144 threads, 3-deep ring.
// grid 1024.
// ---------------------------------------------------------------------------
__global__ __launch_bounds__(256) void prefix_kernel()
{
    int idx = blockIdx.x * 256 + threadIdx.x;   // [0, 262144)
    int b = idx >> 15, de2 = idx & 32767;
    size_t sbase = (size_t)b * NG * 65536 + (size_t)de2 * 2;
    size_t pbase = (size_t)b * NG * 32768 + de2;
    const float g6 = gpow(6.f), g6C = gpow(96.f);

    g_Ph[pbase] = 0u; g_Pl[pbase] = 0u;

    float2 p = make_float2(0.f, 0.f);
    float2 s0 = *(const float2*)&g_S[sbase];
    float2 s1 = *(const float2*)&g_S[sbase + 65536];
    float2 s2 = *(const float2*)&g_S[sbase + 2 * 65536];
    for (int g = 1; g < NG; g++) {
        float2 nxt = s2;
        if (g + 2 < NG) nxt = *(const float2*)&g_S[sbase + (size_t)(g + 2) * 65536];
        p.x = g6 * s0.x + g6C * p.x;
        p.y = g6 * s0.y + g6C * p.y;
        uint32_t h, l;
        split2(p.x, p.y, h, l);
        g_Ph[pbase + (size_t)g * 32768] = h;
        g_Pl[pbase + (size_t)g * 32768] = l;
        s0 = s1; s1 = s2; s2 = nxt;
    }
}

// ---------------------------------------------------------------------------
// K5: per-group local term (2 MMAs). Uses Kw instead of K; weights fold 1/w_j.
// grid (50, 8), dyn smem.
// ---------------------------------------------------------------------------
#define L2_SMEM 98560

__device__ __forceinline__ void l2_qkcopy(unsigned sb, int tid, size_t tokBase, int k0)
{
#pragma unroll
    for (int j = 0; j < 5; j++) {
        int c = tid + j * 256;
        int seg = c / 320, cc = c - seg * 320;
        int r = cc >> 2, ch = cc & 3;
        const char* base = seg == 0 ? (const char*)g_Qh : seg == 1 ? (const char*)g_Ql
                         : seg == 2 ? (const char*)g_Kwh : (const char*)g_Kwl;
        cpa16(sb + seg * 6400u + r * 80u + ch * 16u,
              base + ((tokBase + r) * 256 + k0) * 2 + ch * 16);
    }
}
__device__ __forceinline__ void l2_vcopy(unsigned smB, int tid, size_t tokBase, int e0)
{
#pragma unroll
    for (int j = 0; j < 10; j++) {
        int c = tid + j * 256;
        int seg = c / 1280, cc = c - seg * 1280;
        int r = cc >> 4, ch = cc & 15;
        const char* base = seg ? (const char*)g_Vl : (const char*)g_Vh;
        cpa16(smB + 55040u + seg * 21760u + r * 272u + ch * 16u,
              base + ((tokBase + r) * 256 + e0) * 2 + ch * 16);
    }
}

__global__ __launch_bounds__(256) void local2_kernel(float* __restrict__ out)
{
    extern __shared__ char sm[];
    float* sS = (float*)sm;                       // [80][84]
    uint32_t* sMh = (uint32_t*)(sm + 26880);      // [80][44]
    uint32_t* sMl = (uint32_t*)(sm + 40960);

    int g = blockIdx.x, b = blockIdx.y;
    int tid = threadIdx.x, lane = tid & 31, wid = tid >> 5;
    int lr = lane & 7, lg = lane >> 3;
    int g4 = lane >> 2, t4 = (lane & 3) * 2;
    unsigned smB = su32(sm);

    const size_t tokBase = (size_t)b * SEQ + (size_t)g * TOKG;

    unsigned rowsel = lr + (lg & 1) * 8;
    unsigned colsel = (lg >> 1) * 8;

    float acc1[4][2][4];
#pragma unroll
    for (int i = 0; i < 4; i++)
#pragma unroll
        for (int j = 0; j < 2; j++)
#pragma unroll
            for (int q = 0; q < 4; q++) acc1[i][j][q] = 0.f;

    l2_qkcopy(smB + 26880, tid, tokBase, 0);
    cp_commit();

    for (int it = 0; it < 8; it++) {
        int cur = it & 1;
        if (it < 7) {
            l2_qkcopy(smB + 26880 + (1 - cur) * 25600, tid, tokBase, (it + 1) * 32);
            cp_commit();
            cp_wait<1>();
        } else cp_wait<0>();
        __syncthreads();

        unsigned sb = smB + 26880 + cur * 25600;
        unsigned qH = sb + rowsel * 80 + colsel * 2, qL = qH + 6400;
        unsigned kH = qH + 12800, kL = qH + 19200;
#pragma unroll
        for (int ks = 0; ks < 32; ks += 16) {
            int li = 0;
            for (int tile = wid; tile < 25; tile += 8, li++) {
                int mt = tile / 5, nt = tile - mt * 5;
                unsigned ao = (unsigned)(mt * 16) * 80 + ks * 2;
                unsigned bo = (unsigned)(nt * 16) * 80 + ks * 2;
                uint32_t ah[4], al[4], rh[4], rl[4];
                ldm4(ah, qH + ao); ldm4(al, qL + ao);
                ldm4(rh, kH + bo); ldm4(rl, kL + bo);
                uint32_t bh0[2] = {rh[0], rh[2]}, bh1[2] = {rh[1], rh[3]};
                uint32_t bl0[2] = {rl[0], rl[2]}, bl1[2] = {rl[1], rl[3]};
                mma16816(acc1[li][0], ah, bh0);
                mma16816(acc1[li][0], ah, bl0);
                mma16816(acc1[li][0], al, bh0);
                mma16816(acc1[li][1], ah, bh1);
                mma16816(acc1[li][1], ah, bl1);
                mma16816(acc1[li][1], al, bh1);
            }
        }
        __syncthreads();
    }

    {
        int li = 0;
        for (int tile = wid; tile < 25; tile += 8, li++) {
            int mt = tile / 5, nt = tile - mt * 5;
#pragma unroll
            for (int sub = 0; sub < 2; sub++) {
                int c = nt * 16 + sub * 8 + t4;
                int r = mt * 16 + g4;
                sS[r * 84 + c]     = acc1[li][sub][0];
                sS[r * 84 + c + 1] = acc1[li][sub][1];
                sS[(r + 8) * 84 + c]     = acc1[li][sub][2];
                sS[(r + 8) * 84 + c + 1] = acc1[li][sub][3];
            }
        }
    }
    __syncthreads();

    l2_vcopy(smB, tid, tokBase, 0);
    cp_commit();

    // build M; sS holds Q·Kw^T, so weights fold the 1/w_j = gamma^{-6(15-j)}
    for (int pz = tid; pz < 3200; pz += 256) {
        int t = pz / 40, sp = pz - t * 40;
        int i = t / 5, o = t - i * 5;
        float mv[2];
#pragma unroll
        for (int u = 0; u < 2; u++) {
            int s = sp * 2 + u;
            int j = s / 5, p = s - j * 5;
            float v = 0.f;
            if (j == i && p <= o) v += gpow((float)(p - o - 6 * (15 - i))) * sS[t * 84 + s];
            if (i < 15 && j <= i) v += gpow((float)(6 * (i - 14))) * sS[(t + 5) * 84 + s];
            mv[u] = v;
        }
        uint32_t h, l;
        split2(mv[0], mv[1], h, l);
        sMh[t * 44 + sp] = h;
        sMl[t * 44 + sp] = l;
    }

    unsigned mH = smB + 26880 + rowsel * 176 + colsel * 2, mL = mH + 14080;
    unsigned vH = smB + 55040 + rowsel * 272 + wid * 32 + colsel * 2, vL = vH + 21760;

#pragma unroll
    for (int pass = 0; pass < 2; pass++) {
        int e0 = pass * 128;
        cp_wait<0>();
        __syncthreads();

        float acc2[5][2][4];
#pragma unroll
        for (int i = 0; i < 5; i++)
#pragma unroll
            for (int j = 0; j < 2; j++)
#pragma unroll
                for (int q = 0; q < 4; q++) acc2[i][j][q] = 0.f;

#pragma unroll
        for (int ks = 0; ks < 80; ks += 16) {
            uint32_t bh[4], bl[4];
            unsigned vo = (unsigned)ks * 272;
            ldm4t(bh, vH + vo); ldm4t(bl, vL + vo);
#pragma unroll
            for (int mt = 0; mt < 5; mt++) {
                unsigned ao = (unsigned)(mt * 16) * 176 + ks * 2;
                uint32_t ah[4], al[4];
                ldm4(ah, mH + ao); ldm4(al, mL + ao);
                mma16816(acc2[mt][0], ah, &bh[0]);
                mma16816(acc2[mt][0], ah, &bl[0]);
                mma16816(acc2[mt][0], al, &bh[0]);
                mma16816(acc2[mt][1], ah, &bh[2]);
                mma16816(acc2[mt][1], ah, &bl[2]);
                mma16816(acc2[mt][1], al, &bh[2]);
            }
        }
        __syncthreads();
        if (pass == 0) {
            l2_vcopy(smB, tid, tokBase, 128);
            cp_commit();
        }

#pragma unroll
        for (int mt = 0; mt < 5; mt++)
#pragma unroll
            for (int nt = 0; nt < 2; nt++) {
                int r = mt * 16 + g4;
                int c = e0 + wid * 16 + nt * 8 + t4;
                float* O0 = out + (tokBase + r) * 256 + c;
                float* O1 = out + (tokBase + r + 8) * 256 + c;
                *(float2*)O0 = make_float2(acc2[mt][nt][0], acc2[mt][nt][1]);
                *(float2*)O1 = make_float2(acc2[mt][nt][2], acc2[mt][nt][3]);
            }
    }
}

// ---------------------------------------------------------------------------
// K4: global cross: out += scale * Q_group @ P_g via REDG atomics. grid (2,400)
// ---------------------------------------------------------------------------
#define CGX_SMEM 60416

__device__ __forceinline__ void cg_copy(unsigned sb, int tid, size_t qTok, size_t pBase, int k0, int e0)
{
#pragma unroll
    for (int j = 0; j < 7; j++) {
        int c = tid + j * 256;
        if (c >= 1664) break;
        if (c < 640) {
            int seg = c / 320, cc = c - seg * 320;
            int r = cc >> 2, ch = cc & 3;
            const char* base = seg ? (const char*)g_Ql : (const char*)g_Qh;
            cpa16(sb + seg * 6400u + r * 80u + ch * 16u,
                  base + ((qTok + r) * 256 + k0) * 2 + ch * 16);
        } else {
            int cc = c - 640;
            int seg = cc >> 9, c2 = cc & 511;
            int r = c2 >> 4, ch = c2 & 15;
            const char* base = seg ? (const char*)g_Pl : (const char*)g_Ph;
            cpa16(sb + 12800u + seg * 8704u + r * 272u + ch * 16u,
                  base + (pBase + (size_t)(k0 + r) * 256 + e0) * 2 + ch * 16);
        }
    }
}

__global__ __launch_bounds__(256) void crossglobal_mma(float* __restrict__ out)
{
    extern __shared__ char sm[];
    int bz = blockIdx.y;
    int b = bz / NG, g = bz % NG;
    int e0 = blockIdx.x * 128;
    size_t qTok = (size_t)b * SEQ + (size_t)g * TOKG;
    size_t pBase = (size_t)bz * 65536;

    int tid = threadIdx.x, lane = tid & 31, wid = tid >> 5;
    int lr = lane & 7, lg = lane >> 3;
    int warp_n = wid * 16;
    unsigned smB = su32(sm);

    unsigned rowsel = lr + (lg & 1) * 8, colsel = (lg >> 1) * 8;
    unsigned aoff = rowsel * 80 + colsel * 2;
    unsigned boff = rowsel * 272 + (warp_n + colsel) * 2;

    float acc[5][2][4];
#pragma unroll
    for (int i = 0; i < 5; i++)
#pragma unroll
        for (int j = 0; j < 2; j++)
#pragma unroll
            for (int q = 0; q < 4; q++) acc[i][j][q] = 0.f;

    cg_copy(smB, tid, qTok, pBase, 0, e0);
    cp_commit();

    for (int it = 0; it < 8; it++) {
        int cur = it & 1;
        if (it < 7) {
            cg_copy(smB + (1 - cur) * 30208, tid, qTok, pBase, (it + 1) * 32, e0);
            cp_commit();
            cp_wait<1>();
        } else cp_wait<0>();
        __syncthreads();

        unsigned sb = smB + cur * 30208;
        unsigned aH = sb + aoff, aL = aH + 6400;
        unsigned bH = sb + 12800 + boff, bL = bH + 8704;
#pragma unroll
        for (int ks = 0; ks < 32; ks += 16) {
            uint32_t ah[5][4], al[5][4], bh[4], bl[4];
#pragma unroll
            for (int mt = 0; mt < 5; mt++) {
                unsigned o = (unsigned)(mt * 16) * 80 + ks * 2;
                ldm4(ah[mt], aH + o); ldm4(al[mt], aL + o);
            }
            {
                unsigned o = (unsigned)ks * 272;
                ldm4t(bh, bH + o); ldm4t(bl, bL + o);
            }
#pragma unroll
            for (int mt = 0; mt < 5; mt++)
#pragma unroll
                for (int nt = 0; nt < 2; nt++) {
                    const uint32_t* bhp = &bh[nt * 2];
                    const uint32_t* blp = &bl[nt * 2];
                    mma16816(acc[mt][nt], ah[mt], bhp);
                    mma16816(acc[mt][nt], ah[mt], blp);
                    mma16816(acc[mt][nt], al[mt], bhp);
                }
        }
        __syncthreads();
    }

    int g4 = lane >> 2, t4 = (lane & 3) * 2;
#pragma unroll
    for (int mt = 0; mt < 5; mt++)
#pragma unroll
        for (int nt = 0; nt < 2; nt++) {
            int c = e0 + warp_n + nt * 8 + t4;
            int r1 = mt * 16 + g4;
            int tok1 = g * TOKG + r1 - 5;
            if (tok1 >= 0) {
                float s = gpow((float)(6 * (r1 / 5)));
                float* p = &out[((size_t)b * SEQ + tok1) * 256 + c];
                atomicAdd(p,     s * acc[mt][nt][0]);
                atomicAdd(p + 1, s * acc[mt][nt][1]);
            }
            int r2 = r1 + 8;
            int tok2 = g * TOKG + r2 - 5;
            if (tok2 >= 0) {
                float s = gpow((float)(6 * (r2 / 5)));
                float* p = &out[((size_t)b * SEQ + tok2) * 256 + c];
                atomicAdd(p,     s * acc[mt][nt][2]);
                atomicAdd(p + 1, s * acc[mt][nt][3]);
            }
        }
}

// ---------------------------------------------------------------------------
extern "C" void kernel_launch(void* const* d_in, const int* in_sizes, int n_in,
                              void* d_out, int out_size)
{
    const float* xq = (const float*)d_in[0];
    const float* xk = (const float*)d_in[1];
    const float* xv = (const float*)d_in[2];
    const float* Wq = (const float*)d_in[3];
    const float* Wk = (const float*)d_in[4];
    const float* Wv = (const float*)d_in[5];
    float* out = (float*)d_out;

    static int attrs_set = 0;
    if (!attrs_set) {
        cudaFuncSetAttribute(proj_mma, cudaFuncAttributeMaxDynamicSharedMemorySize, 2 * PJ_STAGE);
        cudaFuncSetAttribute(local2_kernel, cudaFuncAttributeMaxDynamicSharedMemorySize, L2_SMEM);
        cudaFuncSetAttribute(crossglobal_mma, cudaFuncAttributeMaxDynamicSharedMemorySize, CGX_SMEM);
        attrs_set = 1;
    }

    presplitW_kernel<<<dim3(64, 1, 3), 256>>>(Wq, Wk, Wv);
    proj_mma<<<dim3(250, 1, 3), 512, 2 * PJ_STAGE>>>(xq, xk, xv);
    groupstate_mma<<<dim3(2, 2, BATCH * NG), 256>>>();
    prefix_kernel<<<dim3(1024), 256>>>();
    local2_kernel<<<dim3(NG, BATCH), 256, L2_SMEM>>>(out);
    crossglobal_mma<<<dim3(2, BATCH * NG), 256, CGX_SMEM>>>(out);
}

// round 12
// speedup vs baseline: 2.6758x; 1.0266x over previous
#include <cuda_runtime.h>
#include <cuda_bf16.h>
#include <stdint.h>
#include <math.h>

#define BATCH   8
#define SEQ     4000
#define DIM     256
#define BCH     5
#define NCHUNK  800
#define CG      16
#define NG      50
#define TOKG    (CG*BCH)

#define NEL     (BATCH*SEQ*DIM)      // 8,192,000
#define NEL2    (NEL/2)              // 4,096,000 u32

#define GLOG2 (-0.0196090426f)
__device__ __forceinline__ float gpow(float k) { return exp2f(k * GLOG2); }

// ------------------------- global scratch (no alloc) ------------------------
__device__ uint32_t g_Wsh[3 * 32768], g_Wsl[3 * 32768]; // split weights
__device__ uint32_t g_Qh[NEL2], g_Ql[NEL2];
__device__ uint32_t g_Vh[NEL2], g_Vl[NEL2];
__device__ uint32_t g_Kwh[NEL2], g_Kwl[NEL2];           // pre-weighted K
__device__ float    g_S[(size_t)BATCH * NG * DIM * DIM];
__device__ uint32_t g_Ph[(size_t)BATCH * NG * 32768], g_Pl[(size_t)BATCH * NG * 32768];

// ------------------------------ helpers -------------------------------------
__device__ __forceinline__ unsigned su32(const void* p) {
    return (unsigned)__cvta_generic_to_shared(p);
}
__device__ __forceinline__ void cpa16(unsigned s, const void* g) {
    asm volatile("cp.async.cg.shared.global [%0], [%1], 16;" :: "r"(s), "l"(g));
}
__device__ __forceinline__ void cp_commit() { asm volatile("cp.async.commit_group;"); }
template<int N> __device__ __forceinline__ void cp_wait() {
    asm volatile("cp.async.wait_group %0;" :: "n"(N));
}
__device__ __forceinline__ void ldm4(uint32_t* r, unsigned addr) {
    asm volatile("ldmatrix.sync.aligned.m8n8.x4.shared.b16 {%0,%1,%2,%3}, [%4];"
        : "=r"(r[0]), "=r"(r[1]), "=r"(r[2]), "=r"(r[3]) : "r"(addr));
}
__device__ __forceinline__ void ldm4t(uint32_t* r, unsigned addr) {
    asm volatile("ldmatrix.sync.aligned.m8n8.x4.trans.shared.b16 {%0,%1,%2,%3}, [%4];"
        : "=r"(r[0]), "=r"(r[1]), "=r"(r[2]), "=r"(r[3]) : "r"(addr));
}
__device__ __forceinline__ void mma16816(float* c, const uint32_t* a, const uint32_t* b) {
    asm volatile(
        "mma.sync.aligned.m16n8k16.row.col.f32.bf16.bf16.f32 "
        "{%0,%1,%2,%3},{%4,%5,%6,%7},{%8,%9},{%0,%1,%2,%3};"
        : "+f"(c[0]), "+f"(c[1]), "+f"(c[2]), "+f"(c[3])
        : "r"(a[0]), "r"(a[1]), "r"(a[2]), "r"(a[3]), "r"(b[0]), "r"(b[1]));
}
__device__ __forceinline__ void split2(float x, float y, uint32_t& h, uint32_t& l) {
    __nv_bfloat162 hb = __floats2bfloat162_rn(x, y);
    float rx = x - __bfloat162float(hb.x);
    float ry = y - __bfloat162float(hb.y);
    __nv_bfloat162 lb = __floats2bfloat162_rn(rx, ry);
    h = *reinterpret_cast<uint32_t*>(&hb);
    l = *reinterpret_cast<uint32_t*>(&lb);
}

// ---------------------------------------------------------------------------
// K0: presplit WEIGHTS only. grid (64,1,3)
// ---------------------------------------------------------------------------
__global__ __launch_bounds__(256) void presplitW_kernel(
    const float* __restrict__ Wq, const float* __restrict__ Wk, const float* __restrict__ Wv)
{
    int which = blockIdx.z;
    const float* s = which == 0 ? Wq : (which == 1 ? Wk : Wv);
    int idx = blockIdx.x * 256 + threadIdx.x;
    float4 v = ((const float4*)s)[idx];
    uint32_t h0, l0, h1, l1;
    split2(v.x, v.y, h0, l0); split2(v.z, v.w, h1, l1);
    ((uint2*)(g_Wsh + which * 32768))[idx] = make_uint2(h0, h1);
    ((uint2*)(g_Wsl + which * 32768))[idx] = make_uint2(l0, l1);
}

// ---------------------------------------------------------------------------
// K1: QKV projections. which = blockIdx.z + which0 (Q alone / K,V pair).
// 512 threads, 128x256 tile. grid (250,1,nz)
// ---------------------------------------------------------------------------
#define PJ_STAGE 54272

__device__ __forceinline__ void pj_wcopy(unsigned sb, int tid, int k0,
                                         const char* Bgh, const char* Bgl)
{
#pragma unroll
    for (int j = 0; j < 4; j++) {
        int c = tid + j * 512;
        int seg = c >> 10, cc = c & 1023;
        int r = cc >> 5, ch = cc & 31;
        const char* gp = (seg ? Bgl : Bgh) + ((size_t)(k0 + r) * 256) * 2 + ch * 16;
        cpa16(sb + 20480u + seg * 16896u + r * 528u + ch * 16u, gp);
    }
}

__global__ __launch_bounds__(512) void proj_mma(
    const float* __restrict__ xq, const float* __restrict__ xk, const float* __restrict__ xv,
    int which0)
{
    extern __shared__ char sm[];
    int which = blockIdx.z + which0;
    const float4* A4 = (const float4*)(which == 0 ? xq : (which == 1 ? xk : xv));
    const char* Bgh = (const char*)(g_Wsh + which * 32768);
    const char* Bgl = (const char*)(g_Wsl + which * 32768);
    uint32_t* Ch = which == 0 ? g_Qh : g_Vh;   // unused when which==1
    uint32_t* Cl = which == 0 ? g_Ql : g_Vl;

    int tid = threadIdx.x, lane = tid & 31, wid = tid >> 5;
    int lr = lane & 7, lg = lane >> 3;
    int warp_m = (wid & 1) * 64, warp_n = (wid >> 1) * 32;
    int row0 = blockIdx.x * 128;
    unsigned smB = su32(sm);
    unsigned rowsel = lr + (lg & 1) * 8, colsel = (lg >> 1) * 8;
    unsigned aoff = (unsigned)(warp_m + rowsel) * 80 + colsel * 2;
    unsigned boff = (unsigned)rowsel * 528 + (warp_n + colsel) * 2;

    int r0 = tid >> 3, c0 = tid & 7;
    const float4* Ap0 = A4 + (size_t)(row0 + r0) * 64 + c0;
    const float4* Ap1 = A4 + (size_t)(row0 + r0 + 64) * 64 + c0;

    float acc[4][4][4];
#pragma unroll
    for (int i = 0; i < 4; i++)
#pragma unroll
        for (int j = 0; j < 4; j++)
#pragma unroll
            for (int q = 0; q < 4; q++) acc[i][j][q] = 0.f;

    float4 v0 = Ap0[0], v1 = Ap1[0];
    pj_wcopy(smB, tid, 0, Bgh, Bgl);
    cp_commit();

    for (int it = 0; it < 8; it++) {
        int cur = it & 1;
        float4 n0, n1;
        if (it < 7) {
            n0 = Ap0[(it + 1) * 8];
            n1 = Ap1[(it + 1) * 8];
            pj_wcopy(smB + (1 - cur) * PJ_STAGE, tid, (it + 1) * 32, Bgh, Bgl);
            cp_commit();
        }
        {
            char* sbp = sm + cur * PJ_STAGE;
            uint2* pAh = (uint2*)sbp;
            uint2* pAl = (uint2*)(sbp + 10240);
            uint32_t h0, l0, h1, l1;
            split2(v0.x, v0.y, h0, l0); split2(v0.z, v0.w, h1, l1);
            pAh[r0 * 10 + c0] = make_uint2(h0, h1);
            pAl[r0 * 10 + c0] = make_uint2(l0, l1);
            split2(v1.x, v1.y, h0, l0); split2(v1.z, v1.w, h1, l1);
            pAh[(r0 + 64) * 10 + c0] = make_uint2(h0, h1);
            pAl[(r0 + 64) * 10 + c0] = make_uint2(l0, l1);
        }
        if (it < 7) cp_wait<1>(); else cp_wait<0>();
        __syncthreads();

        unsigned sb = smB + cur * PJ_STAGE;
        unsigned aH = sb + aoff, aL = aH + 10240;
        unsigned bH = sb + 20480 + boff, bL = bH + 16896;
#pragma unroll
        for (int ks = 0; ks < 32; ks += 16) {
            uint32_t ah[4][4], al[4][4], bh[2][4], bl[2][4];
#pragma unroll
            for (int mt = 0; mt < 4; mt++) {
                unsigned o = (unsigned)(mt * 16) * 80 + ks * 2;
                ldm4(ah[mt], aH + o); ldm4(al[mt], aL + o);
            }
#pragma unroll
            for (int np = 0; np < 2; np++) {
                unsigned o = (unsigned)ks * 528 + np * 32;
                ldm4t(bh[np], bH + o); ldm4t(bl[np], bL + o);
            }
#pragma unroll
            for (int mt = 0; mt < 4; mt++)
#pragma unroll
                for (int nt = 0; nt < 4; nt++) {
                    const uint32_t* bhp = &bh[nt >> 1][(nt & 1) * 2];
                    const uint32_t* blp = &bl[nt >> 1][(nt & 1) * 2];
                    mma16816(acc[mt][nt], ah[mt], bhp);
                    mma16816(acc[mt][nt], ah[mt], blp);
                    mma16816(acc[mt][nt], al[mt], bhp);
                }
        }
        __syncthreads();
        v0 = n0; v1 = n1;
    }

    int g4 = lane >> 2, t4 = (lane & 3) * 2;
    bool isK = (which == 1);
#pragma unroll
    for (int mt = 0; mt < 4; mt++)
#pragma unroll
        for (int nt = 0; nt < 4; nt++) {
            int r = row0 + warp_m + mt * 16 + g4;
            int c = warp_n + nt * 8 + t4;
#pragma unroll
            for (int h2 = 0; h2 < 2; h2++) {
                int rr = r + h2 * 8;
                float a0 = acc[mt][nt][h2 * 2], a1 = acc[mt][nt][h2 * 2 + 1];
                uint32_t hh, ll;
                size_t o = ((size_t)rr * 256 + c) >> 1;
                if (isK) {
                    int tok = rr % SEQ;
                    float w = gpow(6.f * (float)(15 - ((tok / 5) & 15)));
                    split2(w * a0, w * a1, hh, ll);
                    g_Kwh[o] = hh; g_Kwl[o] = ll;
                } else {
                    split2(a0, a1, hh, ll);
                    Ch[o] = hh; Cl[o] = ll;
                }
            }
        }
}

// ---------------------------------------------------------------------------
// K2: group states S_g = Kw^T V, pure-copy cp.async pipelined. grid (2,2,400)
// ---------------------------------------------------------------------------
__device__ __forceinline__ void gs_copy(unsigned sb, int tid, size_t bTok, int t0, int d0, int e0)
{
#pragma unroll
    for (int j = 0; j < 4; j++) {
        int c = tid + j * 256;
        int seg = c >> 8, cc = c & 255;
        int r = cc >> 4, ch = cc & 15;
        const char* base = seg == 0 ? (const char*)g_Kwh : seg == 1 ? (const char*)g_Kwl
                         : seg == 2 ? (const char*)g_Vh : (const char*)g_Vl;
        size_t gidx = ((bTok + t0 + r) * 256 + ((seg < 2) ? d0 : e0)) * 2 + ch * 16;
        cpa16(sb + seg * 4352u + r * 272u + ch * 16u, base + gidx);
    }
}

__global__ __launch_bounds__(256) void groupstate_mma()
{
    __shared__ __align__(16) char gsm[2 * 17408];
    int bz = blockIdx.z;
    int b = bz / NG, g = bz % NG;
    int d0 = blockIdx.y * 128, e0 = blockIdx.x * 128;
    size_t bTok = (size_t)b * SEQ + (size_t)g * TOKG;

    int tid = threadIdx.x, lane = tid & 31, wid = tid >> 5;
    int lr = lane & 7, lg = lane >> 3;
    int warp_m = (wid & 1) * 64, warp_n = (wid >> 1) * 32;
    unsigned smB = su32(gsm);

    unsigned aoff = ((unsigned)(lr + (lg >> 1) * 8) * 136 + warp_m + (lg & 1) * 8) * 2;
    unsigned boff = ((unsigned)(lr + (lg & 1) * 8) * 136 + warp_n + (lg >> 1) * 8) * 2;

    float acc[4][4][4];
#pragma unroll
    for (int i = 0; i < 4; i++)
#pragma unroll
        for (int j = 0; j < 4; j++)
#pragma unroll
            for (int q = 0; q < 4; q++) acc[i][j][q] = 0.f;

    gs_copy(smB, tid, bTok, 0, d0, e0);
    cp_commit();

    for (int it = 0; it < 5; it++) {
        int cur = it & 1;
        if (it < 4) {
            gs_copy(smB + (1 - cur) * 17408, tid, bTok, (it + 1) * 16, d0, e0);
            cp_commit();
            cp_wait<1>();
        } else cp_wait<0>();
        __syncthreads();

        unsigned sb = smB + cur * 17408;
        uint32_t ah[4][4], al[4][4], bh[2][4], bl[2][4];
#pragma unroll
        for (int mt = 0; mt < 4; mt++) {
            unsigned o = (unsigned)(mt * 16) * 2;
            ldm4t(ah[mt], sb + aoff + o); ldm4t(al[mt], sb + 4352 + aoff + o);
        }
#pragma unroll
        for (int np = 0; np < 2; np++) {
            unsigned o = (unsigned)(np * 16) * 2;
            ldm4t(bh[np], sb + 8704 + boff + o); ldm4t(bl[np], sb + 13056 + boff + o);
        }
#pragma unroll
        for (int mt = 0; mt < 4; mt++)
#pragma unroll
            for (int nt = 0; nt < 4; nt++) {
                const uint32_t* bhp = &bh[nt >> 1][(nt & 1) * 2];
                const uint32_t* blp = &bl[nt >> 1][(nt & 1) * 2];
                mma16816(acc[mt][nt], ah[mt], bhp);
                mma16816(acc[mt][nt], ah[mt], blp);
                mma16816(acc[mt][nt], al[mt], bhp);
            }
        __syncthreads();
    }

    int g4 = lane >> 2, t4 = (lane & 3) * 2;
    float* S = g_S + (size_t)bz * DIM * DIM;
#pragma unroll
    for (int mt = 0; mt < 4; mt++)
#pragma unroll
        for (int nt = 0; nt < 4; nt++) {
            int r = d0 + warp_m + mt * 16 + g4;
            int c = e0 + warp_n + nt * 8 + t4;
            *(float2*)&S[(size_t)r * 256 + c] = make_float2(acc[mt][nt][0], acc[mt][nt][1]);
            *(float2*)&S[(size_t)(r + 8) * 256 + c] = make_float2(acc[mt][nt][2], acc[mt][nt][3]);
        }
}

// ---------------------------------------------------------------------------
// K3: exclusive group prefix. 2 floats/thread, 262144 threads, 3-deep ring.
// ---------------------------------------------------------------------------
__global__ __launch_bounds__(256) void prefix_kernel()
{
    int idx = blockIdx.x * 256 + threadIdx.x;   // [0, 262144)
    int b = idx >> 15, de2 = idx & 32767;
    size_t sbase = (size_t)b * NG * 65536 + (size_t)de2 * 2;
    size_t pbase = (size_t)b * NG * 32768 + de2;
    const float g6 = gpow(6.f), g6C = gpow(96.f);

    g_Ph[pbase] = 0u; g_Pl[pbase] = 0u;

    float2 p = make_float2(0.f, 0.f);
    float2 s0 = *(const float2*)&g_S[sbase];
    float2 s1 = *(const float2*)&g_S[sbase + 65536];
    float2 s2 = *(const float2*)&g_S[sbase + 2 * 65536];
    for (int g = 1; g < NG; g++) {
        float2 nxt = s2;
        if (g + 2 < NG) nxt = *(const float2*)&g_S[sbase + (size_t)(g + 2) * 65536];
        p.x = g6 * s0.x + g6C * p.x;
        p.y = g6 * s0.y + g6C * p.y;
        uint32_t h, l;
        split2(p.x, p.y, h, l);
        g_Ph[pbase + (size_t)g * 32768] = h;
        g_Pl[pbase + (size_t)g * 32768] = l;
        s0 = s1; s1 = s2; s2 = nxt;
    }
}

// ---------------------------------------------------------------------------
// K5: per-group local term (2 MMAs). grid (50, 8), dyn smem.
// ---------------------------------------------------------------------------
#define L2_SMEM 98560

__device__ __forceinline__ void l2_qkcopy(unsigned sb, int tid, size_t tokBase, int k0)
{
#pragma unroll
    for (int j = 0; j < 5; j++) {
        int c = tid + j * 256;
        int seg = c / 320, cc = c - seg * 320;
        int r = cc >> 2, ch = cc & 3;
        const char* base = seg == 0 ? (const char*)g_Qh : seg == 1 ? (const char*)g_Ql
                         : seg == 2 ? (const char*)g_Kwh : (const char*)g_Kwl;
        cpa16(sb + seg * 6400u + r * 80u + ch * 16u,
              base + ((tokBase + r) * 256 + k0) * 2 + ch * 16);
    }
}
__device__ __forceinline__ void l2_vcopy(unsigned smB, int tid, size_t tokBase, int e0)
{
#pragma unroll
    for (int j = 0; j < 10; j++) {
        int c = tid + j * 256;
        int seg = c / 1280, cc = c - seg * 1280;
        int r = cc >> 4, ch = cc & 15;
        const char* base = seg ? (const char*)g_Vl : (const char*)g_Vh;
        cpa16(smB + 55040u + seg * 21760u + r * 272u + ch * 16u,
              base + ((tokBase + r) * 256 + e0) * 2 + ch * 16);
    }
}

__global__ __launch_bounds__(256) void local2_kernel(float* __restrict__ out)
{
    extern __shared__ char sm[];
    float* sS = (float*)sm;                       // [80][84]
    uint32_t* sMh = (uint32_t*)(sm + 26880);      // [80][44]
    uint32_t* sMl = (uint32_t*)(sm + 40960);

    int g = blockIdx.x, b = blockIdx.y;
    int tid = threadIdx.x, lane = tid & 31, wid = tid >> 5;
    int lr = lane & 7, lg = lane >> 3;
    int g4 = lane >> 2, t4 = (lane & 3) * 2;
    unsigned smB = su32(sm);

    const size_t tokBase = (size_t)b * SEQ + (size_t)g * TOKG;

    unsigned rowsel = lr + (lg & 1) * 8;
    unsigned colsel = (lg >> 1) * 8;

    float acc1[4][2][4];
#pragma unroll
    for (int i = 0; i < 4; i++)
#pragma unroll
        for (int j = 0; j < 2; j++)
#pragma unroll
            for (int q = 0; q < 4; q++) acc1[i][j][q] = 0.f;

    l2_qkcopy(smB + 26880, tid, tokBase, 0);
    cp_commit();

    for (int it = 0; it < 8; it++) {
        int cur = it & 1;
        if (it < 7) {
            l2_qkcopy(smB + 26880 + (1 - cur) * 25600, tid, tokBase, (it + 1) * 32);
            cp_commit();
            cp_wait<1>();
        } else cp_wait<0>();
        __syncthreads();

        unsigned sb = smB + 26880 + cur * 25600;
        unsigned qH = sb + rowsel * 80 + colsel * 2, qL = qH + 6400;
        unsigned kH = qH + 12800, kL = qH + 19200;
#pragma unroll
        for (int ks = 0; ks < 32; ks += 16) {
            int li = 0;
            for (int tile = wid; tile < 25; tile += 8, li++) {
                int mt = tile / 5, nt = tile - mt * 5;
                unsigned ao = (unsigned)(mt * 16) * 80 + ks * 2;
                unsigned bo = (unsigned)(nt * 16) * 80 + ks * 2;
                uint32_t ah[4], al[4], rh[4], rl[4];
                ldm4(ah, qH + ao); ldm4(al, qL + ao);
                ldm4(rh, kH + bo); ldm4(rl, kL + bo);
                uint32_t bh0[2] = {rh[0], rh[2]}, bh1[2] = {rh[1], rh[3]};
                uint32_t bl0[2] = {rl[0], rl[2]}, bl1[2] = {rl[1], rl[3]};
                mma16816(acc1[li][0], ah, bh0);
                mma16816(acc1[li][0], ah, bl0);
                mma16816(acc1[li][0], al, bh0);
                mma16816(acc1[li][1], ah, bh1);
                mma16816(acc1[li][1], ah, bl1);
                mma16816(acc1[li][1], al, bh1);
            }
        }
        __syncthreads();
    }

    {
        int li = 0;
        for (int tile = wid; tile < 25; tile += 8, li++) {
            int mt = tile / 5, nt = tile - mt * 5;
#pragma unroll
            for (int sub = 0; sub < 2; sub++) {
                int c = nt * 16 + sub * 8 + t4;
                int r = mt * 16 + g4;
                sS[r * 84 + c]     = acc1[li][sub][0];
                sS[r * 84 + c + 1] = acc1[li][sub][1];
                sS[(r + 8) * 84 + c]     = acc1[li][sub][2];
                sS[(r + 8) * 84 + c + 1] = acc1[li][sub][3];
            }
        }
    }
    __syncthreads();

    l2_vcopy(smB, tid, tokBase, 0);
    cp_commit();

    // build M; sS holds Q·Kw^T, weights fold 1/w_j
    for (int pz = tid; pz < 3200; pz += 256) {
        int t = pz / 40, sp = pz - t * 40;
        int i = t / 5, o = t - i * 5;
        float mv[2];
#pragma unroll
        for (int u = 0; u < 2; u++) {
            int s = sp * 2 + u;
            int j = s / 5, p = s - j * 5;
            float v = 0.f;
            if (j == i && p <= o) v += gpow((float)(p - o - 6 * (15 - i))) * sS[t * 84 + s];
            if (i < 15 && j <= i) v += gpow((float)(6 * (i - 14))) * sS[(t + 5) * 84 + s];
            mv[u] = v;
        }
        uint32_t h, l;
        split2(mv[0], mv[1], h, l);
        sMh[t * 44 + sp] = h;
        sMl[t * 44 + sp] = l;
    }

    unsigned mH = smB + 26880 + rowsel * 176 + colsel * 2, mL = mH + 14080;
    unsigned vH = smB + 55040 + rowsel * 272 + wid * 32 + colsel * 2, vL = vH + 21760;

#pragma unroll
    for (int pass = 0; pass < 2; pass++) {
        int e0 = pass * 128;
        cp_wait<0>();
        __syncthreads();

        float acc2[5][2][4];
#pragma unroll
        for (int i = 0; i < 5; i++)
#pragma unroll
            for (int j = 0; j < 2; j++)
#pragma unroll
                for (int q = 0; q < 4; q++) acc2[i][j][q] = 0.f;

#pragma unroll
        for (int ks = 0; ks < 80; ks += 16) {
            uint32_t bh[4], bl[4];
            unsigned vo = (unsigned)ks * 272;
            ldm4t(bh, vH + vo); ldm4t(bl, vL + vo);
#pragma unroll
            for (int mt = 0; mt < 5; mt++) {
                unsigned ao = (unsigned)(mt * 16) * 176 + ks * 2;
                uint32_t ah[4], al[4];
                ldm4(ah, mH + ao); ldm4(al, mL + ao);
                mma16816(acc2[mt][0], ah, &bh[0]);
                mma16816(acc2[mt][0], ah, &bl[0]);
                mma16816(acc2[mt][0], al, &bh[0]);
                mma16816(acc2[mt][1], ah, &bh[2]);
                mma16816(acc2[mt][1], ah, &bl[2]);
                mma16816(acc2[mt][1], al, &bh[2]);
            }
        }
        __syncthreads();
        if (pass == 0) {
            l2_vcopy(smB, tid, tokBase, 128);
            cp_commit();
        }

#pragma unroll
        for (int mt = 0; mt < 5; mt++)
#pragma unroll
            for (int nt = 0; nt < 2; nt++) {
                int r = mt * 16 + g4;
                int c = e0 + wid * 16 + nt * 8 + t4;
                float* O0 = out + (tokBase + r) * 256 + c;
                float* O1 = out + (tokBase + r + 8) * 256 + c;
                *(float2*)O0 = make_float2(acc2[mt][nt][0], acc2[mt][nt][1]);
                *(float2*)O1 = make_float2(acc2[mt][nt][2], acc2[mt][nt][3]);
            }
    }
}

// ---------------------------------------------------------------------------
// K4: global cross: out += scale * Q_group @ P_g via REDG atomics. grid (2,400)
// ---------------------------------------------------------------------------
#define CGX_SMEM 60416

__device__ __forceinline__ void cg_copy(unsigned sb, int tid, size_t qTok, size_t pBase, int k0, int e0)
{
#pragma unroll
    for (int j = 0; j < 7; j++) {
        int c = tid + j * 256;
        if (c >= 1664) break;
        if (c < 640) {
            int seg = c / 320, cc = c - seg * 320;
            int r = cc >> 2, ch = cc & 3;
            const char* base = seg ? (const char*)g_Ql : (const char*)g_Qh;
            cpa16(sb + seg * 6400u + r * 80u + ch * 16u,
                  base + ((qTok + r) * 256 + k0) * 2 + ch * 16);
        } else {
            int cc = c - 640;
            int seg = cc >> 9, c2 = cc & 511;
            int r = c2 >> 4, ch = c2 & 15;
            const char* base = seg ? (const char*)g_Pl : (const char*)g_Ph;
            cpa16(sb + 12800u + seg * 8704u + r * 272u + ch * 16u,
                  base + (pBase + (size_t)(k0 + r) * 256 + e0) * 2 + ch * 16);
        }
    }
}

__global__ __launch_bounds__(256) void crossglobal_mma(float* __restrict__ out)
{
    extern __shared__ char sm[];
    int bz = blockIdx.y;
    int b = bz / NG, g = bz % NG;
    int e0 = blockIdx.x * 128;
    size_t qTok = (size_t)b * SEQ + (size_t)g * TOKG;
    size_t pBase = (size_t)bz * 65536;

    int tid = threadIdx.x, lane = tid & 31, wid = tid >> 5;
    int lr = lane & 7, lg = lane >> 3;
    int warp_n = wid * 16;
    unsigned smB = su32(sm);

    unsigned rowsel = lr + (lg & 1) * 8, colsel = (lg >> 1) * 8;
    unsigned aoff = rowsel * 80 + colsel * 2;
    unsigned boff = rowsel * 272 + (warp_n + colsel) * 2;

    float acc[5][2][4];
#pragma unroll
    for (int i = 0; i < 5; i++)
#pragma unroll
        for (int j = 0; j < 2; j++)
#pragma unroll
            for (int q = 0; q < 4; q++) acc[i][j][q] = 0.f;

    cg_copy(smB, tid, qTok, pBase, 0, e0);
    cp_commit();

    for (int it = 0; it < 8; it++) {
        int cur = it & 1;
        if (it < 7) {
            cg_copy(smB + (1 - cur) * 30208, tid, qTok, pBase, (it + 1) * 32, e0);
            cp_commit();
            cp_wait<1>();
        } else cp_wait<0>();
        __syncthreads();

        unsigned sb = smB + cur * 30208;
        unsigned aH = sb + aoff, aL = aH + 6400;
        unsigned bH = sb + 12800 + boff, bL = bH + 8704;
#pragma unroll
        for (int ks = 0; ks < 32; ks += 16) {
            uint32_t ah[5][4], al[5][4], bh[4], bl[4];
#pragma unroll
            for (int mt = 0; mt < 5; mt++) {
                unsigned o = (unsigned)(mt * 16) * 80 + ks * 2;
                ldm4(ah[mt], aH + o); ldm4(al[mt], aL + o);
            }
            {
                unsigned o = (unsigned)ks * 272;
                ldm4t(bh, bH + o); ldm4t(bl, bL + o);
            }
#pragma unroll
            for (int mt = 0; mt < 5; mt++)
#pragma unroll
                for (int nt = 0; nt < 2; nt++) {
                    const uint32_t* bhp = &bh[nt * 2];
                    const uint32_t* blp = &bl[nt * 2];
                    mma16816(acc[mt][nt], ah[mt], bhp);
                    mma16816(acc[mt][nt], ah[mt], blp);
                    mma16816(acc[mt][nt], al[mt], bhp);
                }
        }
        __syncthreads();
    }

    int g4 = lane >> 2, t4 = (lane & 3) * 2;
#pragma unroll
    for (int mt = 0; mt < 5; mt++)
#pragma unroll
        for (int nt = 0; nt < 2; nt++) {
            int c = e0 + warp_n + nt * 8 + t4;
            int r1 = mt * 16 + g4;
            int tok1 = g * TOKG + r1 - 5;
            if (tok1 >= 0) {
                float s = gpow((float)(6 * (r1 / 5)));
                float* p = &out[((size_t)b * SEQ + tok1) * 256 + c];
                atomicAdd(p,     s * acc[mt][nt][0]);
                atomicAdd(p + 1, s * acc[mt][nt][1]);
            }
            int r2 = r1 + 8;
            int tok2 = g * TOKG + r2 - 5;
            if (tok2 >= 0) {
                float s = gpow((float)(6 * (r2 / 5)));
                float* p = &out[((size_t)b * SEQ + tok2) * 256 + c];
                atomicAdd(p,     s * acc[mt][nt][2]);
                atomicAdd(p + 1, s * acc[mt][nt][3]);
            }
        }
}

// ---------------------------------------------------------------------------
// Launch: fork/join two-stream DAG (capture-safe).
//   s0: presplitW -> projKV -> groupstate -> prefix -> [wait evL2] crossglobal
//   s1: [wait evPre] projQ -> [wait evKV] local2 -> evL2
// ---------------------------------------------------------------------------
extern "C" void kernel_launch(void* const* d_in, const int* in_sizes, int n_in,
                              void* d_out, int out_size)
{
    const float* xq = (const float*)d_in[0];
    const float* xk = (const float*)d_in[1];
    const float* xv = (const float*)d_in[2];
    const float* Wq = (const float*)d_in[3];
    const float* Wk = (const float*)d_in[4];
    const float* Wv = (const float*)d_in[5];
    float* out = (float*)d_out;

    static cudaStream_t s1;
    static cudaEvent_t evPre, evKV, evL2;
    static int inited = 0;
    if (!inited) {
        cudaFuncSetAttribute(proj_mma, cudaFuncAttributeMaxDynamicSharedMemorySize, 2 * PJ_STAGE);
        cudaFuncSetAttribute(local2_kernel, cudaFuncAttributeMaxDynamicSharedMemorySize, L2_SMEM);
        cudaFuncSetAttribute(crossglobal_mma, cudaFuncAttributeMaxDynamicSharedMemorySize, CGX_SMEM);
        cudaStreamCreateWithFlags(&s1, cudaStreamNonBlocking);
        cudaEventCreateWithFlags(&evPre, cudaEventDisableTiming);
        cudaEventCreateWithFlags(&evKV, cudaEventDisableTiming);
        cudaEventCreateWithFlags(&evL2, cudaEventDisableTiming);
        inited = 1;
    }

    // s0 (default stream)
    presplitW_kernel<<<dim3(64, 1, 3), 256>>>(Wq, Wk, Wv);
    cudaEventRecord(evPre, 0);

    // s1: Q projection can run concurrently with K/V projection
    cudaStreamWaitEvent(s1, evPre, 0);
    proj_mma<<<dim3(250, 1, 1), 512, 2 * PJ_STAGE, s1>>>(xq, xk, xv, 0);

    // s0: K,V projections -> memory-bound chain
    proj_mma<<<dim3(250, 1, 2), 512, 2 * PJ_STAGE>>>(xq, xk, xv, 1);
    cudaEventRecord(evKV, 0);
    groupstate_mma<<<dim3(2, 2, BATCH * NG), 256>>>();
    prefix_kernel<<<dim3(1024), 256>>>();

    // s1: local term (needs Q from s1 + Kw/V from s0)
    cudaStreamWaitEvent(s1, evKV, 0);
    local2_kernel<<<dim3(NG, BATCH), 256, L2_SMEM, s1>>>(out);
    cudaEventRecord(evL2, s1);

    // s0: cross term accumulates into out after local2 wrote it
    cudaStreamWaitEvent(0, evL2, 0);
    crossglobal_mma<<<dim3(2, BATCH * NG), 256, CGX_SMEM>>>(out);
}

// round 13
// speedup vs baseline: 2.7600x; 1.0315x over previous
#include <cuda_runtime.h>
#include <cuda_bf16.h>
#include <stdint.h>
#include <math.h>

#define BATCH   8
#define SEQ     4000
#define DIM     256
#define BCH     5
#define NCHUNK  800
#define CG      16
#define NG      50
#define TOKG    (CG*BCH)

#define NEL     (BATCH*SEQ*DIM)      // 8,192,000
#define NEL2    (NEL/2)              // 4,096,000 u32

#define GLOG2 (-0.0196090426f)
__device__ __forceinline__ float gpow(float k) { return exp2f(k * GLOG2); }

// ------------------------- global scratch (no alloc) ------------------------
__device__ uint32_t g_Wsh[3 * 32768], g_Wsl[3 * 32768]; // split weights
__device__ uint32_t g_Qh[NEL2], g_Ql[NEL2];
__device__ uint32_t g_Vh[NEL2], g_Vl[NEL2];
__device__ uint32_t g_Kwh[NEL2], g_Kwl[NEL2];           // pre-weighted K
__device__ float    g_S[(size_t)BATCH * NG * DIM * DIM];
__device__ uint32_t g_Ph[(size_t)BATCH * NG * 32768], g_Pl[(size_t)BATCH * NG * 32768];

// ------------------------------ helpers -------------------------------------
__device__ __forceinline__ unsigned su32(const void* p) {
    return (unsigned)__cvta_generic_to_shared(p);
}
__device__ __forceinline__ void cpa16(unsigned s, const void* g) {
    asm volatile("cp.async.cg.shared.global [%0], [%1], 16;" :: "r"(s), "l"(g));
}
__device__ __forceinline__ void cp_commit() { asm volatile("cp.async.commit_group;"); }
template<int N> __device__ __forceinline__ void cp_wait() {
    asm volatile("cp.async.wait_group %0;" :: "n"(N));
}
__device__ __forceinline__ void ldm4(uint32_t* r, unsigned addr) {
    asm volatile("ldmatrix.sync.aligned.m8n8.x4.shared.b16 {%0,%1,%2,%3}, [%4];"
        : "=r"(r[0]), "=r"(r[1]), "=r"(r[2]), "=r"(r[3]) : "r"(addr));
}
__device__ __forceinline__ void ldm4t(uint32_t* r, unsigned addr) {
    asm volatile("ldmatrix.sync.aligned.m8n8.x4.trans.shared.b16 {%0,%1,%2,%3}, [%4];"
        : "=r"(r[0]), "=r"(r[1]), "=r"(r[2]), "=r"(r[3]) : "r"(addr));
}
__device__ __forceinline__ void mma16816(float* c, const uint32_t* a, const uint32_t* b) {
    asm volatile(
        "mma.sync.aligned.m16n8k16.row.col.f32.bf16.bf16.f32 "
        "{%0,%1,%2,%3},{%4,%5,%6,%7},{%8,%9},{%0,%1,%2,%3};"
        : "+f"(c[0]), "+f"(c[1]), "+f"(c[2]), "+f"(c[3])
        : "r"(a[0]), "r"(a[1]), "r"(a[2]), "r"(a[3]), "r"(b[0]), "r"(b[1]));
}
__device__ __forceinline__ void split2(float x, float y, uint32_t& h, uint32_t& l) {
    __nv_bfloat162 hb = __floats2bfloat162_rn(x, y);
    float rx = x - __bfloat162float(hb.x);
    float ry = y - __bfloat162float(hb.y);
    __nv_bfloat162 lb = __floats2bfloat162_rn(rx, ry);
    h = *reinterpret_cast<uint32_t*>(&hb);
    l = *reinterpret_cast<uint32_t*>(&lb);
}

// ---------------------------------------------------------------------------
// K0: presplit WEIGHTS only. grid (64,1,3)
// ---------------------------------------------------------------------------
__global__ __launch_bounds__(256) void presplitW_kernel(
    const float* __restrict__ Wq, const float* __restrict__ Wk, const float* __restrict__ Wv)
{
    int which = blockIdx.z;
    const float* s = which == 0 ? Wq : (which == 1 ? Wk : Wv);
    int idx = blockIdx.x * 256 + threadIdx.x;
    float4 v = ((const float4*)s)[idx];
    uint32_t h0, l0, h1, l1;
    split2(v.x, v.y, h0, l0); split2(v.z, v.w, h1, l1);
    ((uint2*)(g_Wsh + which * 32768))[idx] = make_uint2(h0, h1);
    ((uint2*)(g_Wsl + which * 32768))[idx] = make_uint2(l0, l1);
}

// ---------------------------------------------------------------------------
// K1: QKV projections. 512 threads, 128x256 tile. grid (250,1,3)
// ---------------------------------------------------------------------------
#define PJ_STAGE 54272

__device__ __forceinline__ void pj_wcopy(unsigned sb, int tid, int k0,
                                         const char* Bgh, const char* Bgl)
{
#pragma unroll
    for (int j = 0; j < 4; j++) {
        int c = tid + j * 512;
        int seg = c >> 10, cc = c & 1023;
        int r = cc >> 5, ch = cc & 31;
        const char* gp = (seg ? Bgl : Bgh) + ((size_t)(k0 + r) * 256) * 2 + ch * 16;
        cpa16(sb + 20480u + seg * 16896u + r * 528u + ch * 16u, gp);
    }
}

__global__ __launch_bounds__(512) void proj_mma(
    const float* __restrict__ xq, const float* __restrict__ xk, const float* __restrict__ xv)
{
    extern __shared__ char sm[];
    int which = blockIdx.z;
    const float4* A4 = (const float4*)(which == 0 ? xq : (which == 1 ? xk : xv));
    const char* Bgh = (const char*)(g_Wsh + which * 32768);
    const char* Bgl = (const char*)(g_Wsl + which * 32768);
    uint32_t* Ch = which == 0 ? g_Qh : g_Vh;   // unused when which==1
    uint32_t* Cl = which == 0 ? g_Ql : g_Vl;

    int tid = threadIdx.x, lane = tid & 31, wid = tid >> 5;
    int lr = lane & 7, lg = lane >> 3;
    int warp_m = (wid & 1) * 64, warp_n = (wid >> 1) * 32;
    int row0 = blockIdx.x * 128;
    unsigned smB = su32(sm);
    unsigned rowsel = lr + (lg & 1) * 8, colsel = (lg >> 1) * 8;
    unsigned aoff = (unsigned)(warp_m + rowsel) * 80 + colsel * 2;
    unsigned boff = (unsigned)rowsel * 528 + (warp_n + colsel) * 2;

    int r0 = tid >> 3, c0 = tid & 7;
    const float4* Ap0 = A4 + (size_t)(row0 + r0) * 64 + c0;
    const float4* Ap1 = A4 + (size_t)(row0 + r0 + 64) * 64 + c0;

    float acc[4][4][4];
#pragma unroll
    for (int i = 0; i < 4; i++)
#pragma unroll
        for (int j = 0; j < 4; j++)
#pragma unroll
            for (int q = 0; q < 4; q++) acc[i][j][q] = 0.f;

    float4 v0 = Ap0[0], v1 = Ap1[0];
    pj_wcopy(smB, tid, 0, Bgh, Bgl);
    cp_commit();

    for (int it = 0; it < 8; it++) {
        int cur = it & 1;
        float4 n0, n1;
        if (it < 7) {
            n0 = Ap0[(it + 1) * 8];
            n1 = Ap1[(it + 1) * 8];
            pj_wcopy(smB + (1 - cur) * PJ_STAGE, tid, (it + 1) * 32, Bgh, Bgl);
            cp_commit();
        }
        {
            char* sbp = sm + cur * PJ_STAGE;
            uint2* pAh = (uint2*)sbp;
            uint2* pAl = (uint2*)(sbp + 10240);
            uint32_t h0, l0, h1, l1;
            split2(v0.x, v0.y, h0, l0); split2(v0.z, v0.w, h1, l1);
            pAh[r0 * 10 + c0] = make_uint2(h0, h1);
            pAl[r0 * 10 + c0] = make_uint2(l0, l1);
            split2(v1.x, v1.y, h0, l0); split2(v1.z, v1.w, h1, l1);
            pAh[(r0 + 64) * 10 + c0] = make_uint2(h0, h1);
            pAl[(r0 + 64) * 10 + c0] = make_uint2(l0, l1);
        }
        if (it < 7) cp_wait<1>(); else cp_wait<0>();
        __syncthreads();

        unsigned sb = smB + cur * PJ_STAGE;
        unsigned aH = sb + aoff, aL = aH + 10240;
        unsigned bH = sb + 20480 + boff, bL = bH + 16896;
#pragma unroll
        for (int ks = 0; ks < 32; ks += 16) {
            uint32_t ah[4][4], al[4][4], bh[2][4], bl[2][4];
#pragma unroll
            for (int mt = 0; mt < 4; mt++) {
                unsigned o = (unsigned)(mt * 16) * 80 + ks * 2;
                ldm4(ah[mt], aH + o); ldm4(al[mt], aL + o);
            }
#pragma unroll
            for (int np = 0; np < 2; np++) {
                unsigned o = (unsigned)ks * 528 + np * 32;
                ldm4t(bh[np], bH + o); ldm4t(bl[np], bL + o);
            }
#pragma unroll
            for (int mt = 0; mt < 4; mt++)
#pragma unroll
                for (int nt = 0; nt < 4; nt++) {
                    const uint32_t* bhp = &bh[nt >> 1][(nt & 1) * 2];
                    const uint32_t* blp = &bl[nt >> 1][(nt & 1) * 2];
                    mma16816(acc[mt][nt], ah[mt], bhp);
                    mma16816(acc[mt][nt], ah[mt], blp);
                    mma16816(acc[mt][nt], al[mt], bhp);
                }
        }
        __syncthreads();
        v0 = n0; v1 = n1;
    }

    int g4 = lane >> 2, t4 = (lane & 3) * 2;
    bool isK = (which == 1);
#pragma unroll
    for (int mt = 0; mt < 4; mt++)
#pragma unroll
        for (int nt = 0; nt < 4; nt++) {
            int r = row0 + warp_m + mt * 16 + g4;
            int c = warp_n + nt * 8 + t4;
#pragma unroll
            for (int h2 = 0; h2 < 2; h2++) {
                int rr = r + h2 * 8;
                float a0 = acc[mt][nt][h2 * 2], a1 = acc[mt][nt][h2 * 2 + 1];
                uint32_t hh, ll;
                size_t o = ((size_t)rr * 256 + c) >> 1;
                if (isK) {
                    int tok = rr % SEQ;
                    float w = gpow(6.f * (float)(15 - ((tok / 5) & 15)));
                    split2(w * a0, w * a1, hh, ll);
                    g_Kwh[o] = hh; g_Kwl[o] = ll;
                } else {
                    split2(a0, a1, hh, ll);
                    Ch[o] = hh; Cl[o] = ll;
                }
            }
        }
}

// ---------------------------------------------------------------------------
// K2: group states S_g = Kw^T V. FULL-GROUP prefetch: all 5 stages issued
// up-front (5 commit groups, single-use buffers), drained wait<4>..<0>.
// grid (2,2,400), dynamic smem 87040.
// ---------------------------------------------------------------------------
#define GS_STAGE 17408
#define GS_SMEM  (5 * GS_STAGE)

__device__ __forceinline__ void gs_copy(unsigned sb, int tid, size_t bTok, int t0, int d0, int e0)
{
#pragma unroll
    for (int j = 0; j < 4; j++) {
        int c = tid + j * 256;
        int seg = c >> 8, cc = c & 255;
        int r = cc >> 4, ch = cc & 15;
        const char* base = seg == 0 ? (const char*)g_Kwh : seg == 1 ? (const char*)g_Kwl
                         : seg == 2 ? (const char*)g_Vh : (const char*)g_Vl;
        size_t gidx = ((bTok + t0 + r) * 256 + ((seg < 2) ? d0 : e0)) * 2 + ch * 16;
        cpa16(sb + seg * 4352u + r * 272u + ch * 16u, base + gidx);
    }
}

__global__ __launch_bounds__(256) void groupstate_mma()
{
    extern __shared__ char gsm[];
    int bz = blockIdx.z;
    int b = bz / NG, g = bz % NG;
    int d0 = blockIdx.y * 128, e0 = blockIdx.x * 128;
    size_t bTok = (size_t)b * SEQ + (size_t)g * TOKG;

    int tid = threadIdx.x, lane = tid & 31, wid = tid >> 5;
    int lr = lane & 7, lg = lane >> 3;
    int warp_m = (wid & 1) * 64, warp_n = (wid >> 1) * 32;
    unsigned smB = su32(gsm);

    unsigned aoff = ((unsigned)(lr + (lg >> 1) * 8) * 136 + warp_m + (lg & 1) * 8) * 2;
    unsigned boff = ((unsigned)(lr + (lg & 1) * 8) * 136 + warp_n + (lg >> 1) * 8) * 2;

    float acc[4][4][4];
#pragma unroll
    for (int i = 0; i < 4; i++)
#pragma unroll
        for (int j = 0; j < 4; j++)
#pragma unroll
            for (int q = 0; q < 4; q++) acc[i][j][q] = 0.f;

    // issue all 5 stages up-front
#pragma unroll
    for (int st = 0; st < 5; st++) {
        gs_copy(smB + st * GS_STAGE, tid, bTok, st * 16, d0, e0);
        cp_commit();
    }

#pragma unroll
    for (int it = 0; it < 5; it++) {
        if (it == 0) cp_wait<4>();
        else if (it == 1) cp_wait<3>();
        else if (it == 2) cp_wait<2>();
        else if (it == 3) cp_wait<1>();
        else cp_wait<0>();
        __syncthreads();

        unsigned sb = smB + it * GS_STAGE;
        uint32_t ah[4][4], al[4][4], bh[2][4], bl[2][4];
#pragma unroll
        for (int mt = 0; mt < 4; mt++) {
            unsigned o = (unsigned)(mt * 16) * 2;
            ldm4t(ah[mt], sb + aoff + o); ldm4t(al[mt], sb + 4352 + aoff + o);
        }
#pragma unroll
        for (int np = 0; np < 2; np++) {
            unsigned o = (unsigned)(np * 16) * 2;
            ldm4t(bh[np], sb + 8704 + boff + o); ldm4t(bl[np], sb + 13056 + boff + o);
        }
#pragma unroll
        for (int mt = 0; mt < 4; mt++)
#pragma unroll
            for (int nt = 0; nt < 4; nt++) {
                const uint32_t* bhp = &bh[nt >> 1][(nt & 1) * 2];
                const uint32_t* blp = &bl[nt >> 1][(nt & 1) * 2];
                mma16816(acc[mt][nt], ah[mt], bhp);
                mma16816(acc[mt][nt], ah[mt], blp);
                mma16816(acc[mt][nt], al[mt], bhp);
            }
        // no trailing sync: buffers are single-use
    }

    int g4 = lane >> 2, t4 = (lane & 3) * 2;
    float* S = g_S + (size_t)bz * DIM * DIM;
#pragma unroll
    for (int mt = 0; mt < 4; mt++)
#pragma unroll
        for (int nt = 0; nt < 4; nt++) {
            int r = d0 + warp_m + mt * 16 + g4;
            int c = e0 + warp_n + nt * 8 + t4;
            *(float2*)&S[(size_t)r * 256 + c] = make_float2(acc[mt][nt][0], acc[mt][nt][1]);
            *(float2*)&S[(size_t)(r + 8) * 256 + c] = make_float2(acc[mt][nt][2], acc[mt][nt][3]);
        }
}

// ---------------------------------------------------------------------------
// K3: exclusive group prefix. 2 floats/thread, 262144 threads, 3-deep ring.
// ---------------------------------------------------------------------------
__global__ __launch_bounds__(256) void prefix_kernel()
{
    int idx = blockIdx.x * 256 + threadIdx.x;   // [0, 262144)
    int b = idx >> 15, de2 = idx & 32767;
    size_t sbase = (size_t)b * NG * 65536 + (size_t)de2 * 2;
    size_t pbase = (size_t)b * NG * 32768 + de2;
    const float g6 = gpow(6.f), g6C = gpow(96.f);

    g_Ph[pbase] = 0u; g_Pl[pbase] = 0u;

    float2 p = make_float2(0.f, 0.f);
    float2 s0 = *(const float2*)&g_S[sbase];
    float2 s1 = *(const float2*)&g_S[sbase + 65536];
    float2 s2 = *(const float2*)&g_S[sbase + 2 * 65536];
    for (int g = 1; g < NG; g++) {
        float2 nxt = s2;
        if (g + 2 < NG) nxt = *(const float2*)&g_S[sbase + (size_t)(g + 2) * 65536];
        p.x = g6 * s0.x + g6C * p.x;
        p.y = g6 * s0.y + g6C * p.y;
        uint32_t h, l;
        split2(p.x, p.y, h, l);
        g_Ph[pbase + (size_t)g * 32768] = h;
        g_Pl[pbase + (size_t)g * 32768] = l;
        s0 = s1; s1 = s2; s2 = nxt;
    }
}

// ---------------------------------------------------------------------------
// K5: per-group local term (2 MMAs). grid (50, 8), dyn smem.
// ---------------------------------------------------------------------------
#define L2_SMEM 98560

__device__ __forceinline__ void l2_qkcopy(unsigned sb, int tid, size_t tokBase, int k0)
{
#pragma unroll
    for (int j = 0; j < 5; j++) {
        int c = tid + j * 256;
        int seg = c / 320, cc = c - seg * 320;
        int r = cc >> 2, ch = cc & 3;
        const char* base = seg == 0 ? (const char*)g_Qh : seg == 1 ? (const char*)g_Ql
                         : seg == 2 ? (const char*)g_Kwh : (const char*)g_Kwl;
        cpa16(sb + seg * 6400u + r * 80u + ch * 16u,
              base + ((tokBase + r) * 256 + k0) * 2 + ch * 16);
    }
}
__device__ __forceinline__ void l2_vcopy(unsigned smB, int tid, size_t tokBase, int e0)
{
#pragma unroll
    for (int j = 0; j < 10; j++) {
        int c = tid + j * 256;
        int seg = c / 1280, cc = c - seg * 1280;
        int r = cc >> 4, ch = cc & 15;
        const char* base = seg ? (const char*)g_Vl : (const char*)g_Vh;
        cpa16(smB + 55040u + seg * 21760u + r * 272u + ch * 16u,
              base + ((tokBase + r) * 256 + e0) * 2 + ch * 16);
    }
}

__global__ __launch_bounds__(256) void local2_kernel(float* __restrict__ out)
{
    extern __shared__ char sm[];
    float* sS = (float*)sm;                       // [80][84]
    uint32_t* sMh = (uint32_t*)(sm + 26880);      // [80][44]
    uint32_t* sMl = (uint32_t*)(sm + 40960);

    int g = blockIdx.x, b = blockIdx.y;
    int tid = threadIdx.x, lane = tid & 31, wid = tid >> 5;
    int lr = lane & 7, lg = lane >> 3;
    int g4 = lane >> 2, t4 = (lane & 3) * 2;
    unsigned smB = su32(sm);

    const size_t tokBase = (size_t)b * SEQ + (size_t)g * TOKG;

    unsigned rowsel = lr + (lg & 1) * 8;
    unsigned colsel = (lg >> 1) * 8;

    float acc1[4][2][4];
#pragma unroll
    for (int i = 0; i < 4; i++)
#pragma unroll
        for (int j = 0; j < 2; j++)
#pragma unroll
            for (int q = 0; q < 4; q++) acc1[i][j][q] = 0.f;

    l2_qkcopy(smB + 26880, tid, tokBase, 0);
    cp_commit();

    for (int it = 0; it < 8; it++) {
        int cur = it & 1;
        if (it < 7) {
            l2_qkcopy(smB + 26880 + (1 - cur) * 25600, tid, tokBase, (it + 1) * 32);
            cp_commit();
            cp_wait<1>();
        } else cp_wait<0>();
        __syncthreads();

        unsigned sb = smB + 26880 + cur * 25600;
        unsigned qH = sb + rowsel * 80 + colsel * 2, qL = qH + 6400;
        unsigned kH = qH + 12800, kL = qH + 19200;
#pragma unroll
        for (int ks = 0; ks < 32; ks += 16) {
            int li = 0;
            for (int tile = wid; tile < 25; tile += 8, li++) {
                int mt = tile / 5, nt = tile - mt * 5;
                unsigned ao = (unsigned)(mt * 16) * 80 + ks * 2;
                unsigned bo = (unsigned)(nt * 16) * 80 + ks * 2;
                uint32_t ah[4], al[4], rh[4], rl[4];
                ldm4(ah, qH + ao); ldm4(al, qL + ao);
                ldm4(rh, kH + bo); ldm4(rl, kL + bo);
                uint32_t bh0[2] = {rh[0], rh[2]}, bh1[2] = {rh[1], rh[3]};
                uint32_t bl0[2] = {rl[0], rl[2]}, bl1[2] = {rl[1], rl[3]};
                mma16816(acc1[li][0], ah, bh0);
                mma16816(acc1[li][0], ah, bl0);
                mma16816(acc1[li][0], al, bh0);
                mma16816(acc1[li][1], ah, bh1);
                mma16816(acc1[li][1], ah, bl1);
                mma16816(acc1[li][1], al, bh1);
            }
        }
        __syncthreads();
    }

    {
        int li = 0;
        for (int tile = wid; tile < 25; tile += 8, li++) {
            int mt = tile / 5, nt = tile - mt * 5;
#pragma unroll
            for (int sub = 0; sub < 2; sub++) {
                int c = nt * 16 + sub * 8 + t4;
                int r = mt * 16 + g4;
                sS[r * 84 + c]     = acc1[li][sub][0];
                sS[r * 84 + c + 1] = acc1[li][sub][1];
                sS[(r + 8) * 84 + c]     = acc1[li][sub][2];
                sS[(r + 8) * 84 + c + 1] = acc1[li][sub][3];
            }
        }
    }
    __syncthreads();

    l2_vcopy(smB, tid, tokBase, 0);
    cp_commit();

    // build M; sS holds Q·Kw^T, weights fold 1/w_j
    for (int pz = tid; pz < 3200; pz += 256) {
        int t = pz / 40, sp = pz - t * 40;
        int i = t / 5, o = t - i * 5;
        float mv[2];
#pragma unroll
        for (int u = 0; u < 2; u++) {
            int s = sp * 2 + u;
            int j = s / 5, p = s - j * 5;
            float v = 0.f;
            if (j == i && p <= o) v += gpow((float)(p - o - 6 * (15 - i))) * sS[t * 84 + s];
            if (i < 15 && j <= i) v += gpow((float)(6 * (i - 14))) * sS[(t + 5) * 84 + s];
            mv[u] = v;
        }
        uint32_t h, l;
        split2(mv[0], mv[1], h, l);
        sMh[t * 44 + sp] = h;
        sMl[t * 44 + sp] = l;
    }

    unsigned mH = smB + 26880 + rowsel * 176 + colsel * 2, mL = mH + 14080;
    unsigned vH = smB + 55040 + rowsel * 272 + wid * 32 + colsel * 2, vL = vH + 21760;

#pragma unroll
    for (int pass = 0; pass < 2; pass++) {
        int e0 = pass * 128;
        cp_wait<0>();
        __syncthreads();

        float acc2[5][2][4];
#pragma unroll
        for (int i = 0; i < 5; i++)
#pragma unroll
            for (int j = 0; j < 2; j++)
#pragma unroll
                for (int q = 0; q < 4; q++) acc2[i][j][q] = 0.f;

#pragma unroll
        for (int ks = 0; ks < 80; ks += 16) {
            uint32_t bh[4], bl[4];
            unsigned vo = (unsigned)ks * 272;
            ldm4t(bh, vH + vo); ldm4t(bl, vL + vo);
#pragma unroll
            for (int mt = 0; mt < 5; mt++) {
                unsigned ao = (unsigned)(mt * 16) * 176 + ks * 2;
                uint32_t ah[4], al[4];
                ldm4(ah, mH + ao); ldm4(al, mL + ao);
                mma16816(acc2[mt][0], ah, &bh[0]);
                mma16816(acc2[mt][0], ah, &bl[0]);
                mma16816(acc2[mt][0], al, &bh[0]);
                mma16816(acc2[mt][1], ah, &bh[2]);
                mma16816(acc2[mt][1], ah, &bl[2]);
                mma16816(acc2[mt][1], al, &bh[2]);
            }
        }
        __syncthreads();
        if (pass == 0) {
            l2_vcopy(smB, tid, tokBase, 128);
            cp_commit();
        }

#pragma unroll
        for (int mt = 0; mt < 5; mt++)
#pragma unroll
            for (int nt = 0; nt < 2; nt++) {
                int r = mt * 16 + g4;
                int c = e0 + wid * 16 + nt * 8 + t4;
                float* O0 = out + (tokBase + r) * 256 + c;
                float* O1 = out + (tokBase + r + 8) * 256 + c;
                *(float2*)O0 = make_float2(acc2[mt][nt][0], acc2[mt][nt][1]);
                *(float2*)O1 = make_float2(acc2[mt][nt][2], acc2[mt][nt][3]);
            }
    }
}

// ---------------------------------------------------------------------------
// K4: global cross: out += scale * Q_group @ P_g via REDG atomics. grid (2,400)
// ---------------------------------------------------------------------------
#define CGX_SMEM 60416

__device__ __forceinline__ void cg_copy(unsigned sb, int tid, size_t qTok, size_t pBase, int k0, int e0)
{
#pragma unroll
    for (int j = 0; j < 7; j++) {
        int c = tid + j * 256;
        if (c >= 1664) break;
        if (c < 640) {
            int seg = c / 320, cc = c - seg * 320;
            int r = cc >> 2, ch = cc & 3;
            const char* base = seg ? (const char*)g_Ql : (const char*)g_Qh;
            cpa16(sb + seg * 6400u + r * 80u + ch * 16u,
                  base + ((qTok + r) * 256 + k0) * 2 + ch * 16);
        } else {
            int cc = c - 640;
            int seg = cc >> 9, c2 = cc & 511;
            int r = c2 >> 4, ch = c2 & 15;
            const char* base = seg ? (const char*)g_Pl : (const char*)g_Ph;
            cpa16(sb + 12800u + seg * 8704u + r * 272u + ch * 16u,
                  base + (pBase + (size_t)(k0 + r) * 256 + e0) * 2 + ch * 16);
        }
    }
}

__global__ __launch_bounds__(256) void crossglobal_mma(float* __restrict__ out)
{
    extern __shared__ char sm[];
    int bz = blockIdx.y;
    int b = bz / NG, g = bz % NG;
    int e0 = blockIdx.x * 128;
    size_t qTok = (size_t)b * SEQ + (size_t)g * TOKG;
    size_t pBase = (size_t)bz * 65536;

    int tid = threadIdx.x, lane = tid & 31, wid = tid >> 5;
    int lr = lane & 7, lg = lane >> 3;
    int warp_n = wid * 16;
    unsigned smB = su32(sm);

    unsigned rowsel = lr + (lg & 1) * 8, colsel = (lg >> 1) * 8;
    unsigned aoff = rowsel * 80 + colsel * 2;
    unsigned boff = rowsel * 272 + (warp_n + colsel) * 2;

    float acc[5][2][4];
#pragma unroll
    for (int i = 0; i < 5; i++)
#pragma unroll
        for (int j = 0; j < 2; j++)
#pragma unroll
            for (int q = 0; q < 4; q++) acc[i][j][q] = 0.f;

    cg_copy(smB, tid, qTok, pBase, 0, e0);
    cp_commit();

    for (int it = 0; it < 8; it++) {
        int cur = it & 1;
        if (it < 7) {
            cg_copy(smB + (1 - cur) * 30208, tid, qTok, pBase, (it + 1) * 32, e0);
            cp_commit();
            cp_wait<1>();
        } else cp_wait<0>();
        __syncthreads();

        unsigned sb = smB + cur * 30208;
        unsigned aH = sb + aoff, aL = aH + 6400;
        unsigned bH = sb + 12800 + boff, bL = bH + 8704;
#pragma unroll
        for (int ks = 0; ks < 32; ks += 16) {
            uint32_t ah[5][4], al[5][4], bh[4], bl[4];
#pragma unroll
            for (int mt = 0; mt < 5; mt++) {
                unsigned o = (unsigned)(mt * 16) * 80 + ks * 2;
                ldm4(ah[mt], aH + o); ldm4(al[mt], aL + o);
            }
            {
                unsigned o = (unsigned)ks * 272;
                ldm4t(bh, bH + o); ldm4t(bl, bL + o);
            }
#pragma unroll
            for (int mt = 0; mt < 5; mt++)
#pragma unroll
                for (int nt = 0; nt < 2; nt++) {
                    const uint32_t* bhp = &bh[nt * 2];
                    const uint32_t* blp = &bl[nt * 2];
                    mma16816(acc[mt][nt], ah[mt], bhp);
                    mma16816(acc[mt][nt], ah[mt], blp);
                    mma16816(acc[mt][nt], al[mt], bhp);
                }
        }
        __syncthreads();
    }

    int g4 = lane >> 2, t4 = (lane & 3) * 2;
#pragma unroll
    for (int mt = 0; mt < 5; mt++)
#pragma unroll
        for (int nt = 0; nt < 2; nt++) {
            int c = e0 + warp_n + nt * 8 + t4;
            int r1 = mt * 16 + g4;
            int tok1 = g * TOKG + r1 - 5;
            if (tok1 >= 0) {
                float s = gpow((float)(6 * (r1 / 5)));
                float* p = &out[((size_t)b * SEQ + tok1) * 256 + c];
                atomicAdd(p,     s * acc[mt][nt][0]);
                atomicAdd(p + 1, s * acc[mt][nt][1]);
            }
            int r2 = r1 + 8;
            int tok2 = g * TOKG + r2 - 5;
            if (tok2 >= 0) {
                float s = gpow((float)(6 * (r2 / 5)));
                float* p = &out[((size_t)b * SEQ + tok2) * 256 + c];
                atomicAdd(p,     s * acc[mt][nt][2]);
                atomicAdd(p + 1, s * acc[mt][nt][3]);
            }
        }
}

// ---------------------------------------------------------------------------
// Launch DAG (capture-safe):
//   s0: presplitW -> proj(Q,K,V) -> evProj -> groupstate -> prefix
//   s1: [wait evProj] local2 -> evL2
//   s0: [wait evL2] crossglobal
// local2 (tensor/smem-bound) overlaps groupstate+prefix (mixed/DRAM-bound).
// ---------------------------------------------------------------------------
extern "C" void kernel_launch(void* const* d_in, const int* in_sizes, int n_in,
                              void* d_out, int out_size)
{
    const float* xq = (const float*)d_in[0];
    const float* xk = (const float*)d_in[1];
    const float* xv = (const float*)d_in[2];
    const float* Wq = (const float*)d_in[3];
    const float* Wk = (const float*)d_in[4];
    const float* Wv = (const float*)d_in[5];
    float* out = (float*)d_out;

    static cudaStream_t s1;
    static cudaEvent_t evProj, evL2;
    static int inited = 0;
    if (!inited) {
        cudaFuncSetAttribute(proj_mma, cudaFuncAttributeMaxDynamicSharedMemorySize, 2 * PJ_STAGE);
        cudaFuncSetAttribute(groupstate_mma, cudaFuncAttributeMaxDynamicSharedMemorySize, GS_SMEM);
        cudaFuncSetAttribute(local2_kernel, cudaFuncAttributeMaxDynamicSharedMemorySize, L2_SMEM);
        cudaFuncSetAttribute(crossglobal_mma, cudaFuncAttributeMaxDynamicSharedMemorySize, CGX_SMEM);
        cudaStreamCreateWithFlags(&s1, cudaStreamNonBlocking);
        cudaEventCreateWithFlags(&evProj, cudaEventDisableTiming);
        cudaEventCreateWithFlags(&evL2, cudaEventDisableTiming);
        inited = 1;
    }

    // s0: presplit + unified QKV projection
    presplitW_kernel<<<dim3(64, 1, 3), 256>>>(Wq, Wk, Wv);
    proj_mma<<<dim3(250, 1, 3), 512, 2 * PJ_STAGE>>>(xq, xk, xv);
    cudaEventRecord(evProj, 0);

    // s1: local term overlaps the memory-bound chain below
    cudaStreamWaitEvent(s1, evProj, 0);
    local2_kernel<<<dim3(NG, BATCH), 256, L2_SMEM, s1>>>(out);
    cudaEventRecord(evL2, s1);

    // s0: memory-bound chain
    groupstate_mma<<<dim3(2, 2, BATCH * NG), 256, GS_SMEM>>>();
    prefix_kernel<<<dim3(1024), 256>>>();

    // s0: cross term accumulates into out after local2 wrote it
    cudaStreamWaitEvent(0, evL2, 0);
    crossglobal_mma<<<dim3(2, BATCH * NG), 256, CGX_SMEM>>>(out);
}